// round 1
// baseline (speedup 1.0000x reference)
#include <cuda_runtime.h>
#include <math.h>

// Problem constants
#define Bn   4
#define Sn   1024
#define Hn   20
#define Dn   64
#define DMn  1280
#define DFn  5120
#define NTOK 4096           // Bn*Sn
#define NBH  80             // Bn*Hn
#define EPSLN 1e-5f

// ---------------- scratch (static device globals; no allocation) -------------
__device__ float g_h   [(size_t)NTOK * DMn];           // LN output
__device__ float g_q   [(size_t)NTOK * DMn];
__device__ float g_k   [(size_t)NTOK * DMn];
__device__ float g_v   [(size_t)NTOK * DMn];
__device__ float g_attn[(size_t)NTOK * DMn];
__device__ float g_x1  [(size_t)NTOK * DMn];           // x + attn proj (residual 1)
__device__ float g_f1  [(size_t)NTOK * DFn];           // FC1/GELU output
__device__ float g_logits[(size_t)NBH * Sn * Sn];      // 320 MB attention scores

// ---------------- LayerNorm: one block per row --------------------------------
__global__ void __launch_bounds__(256) ln_kernel(const float* __restrict__ x,
                                                 const float* __restrict__ sc,
                                                 const float* __restrict__ off,
                                                 float* __restrict__ y)
{
    const int row = blockIdx.x;
    const float* xr = x + (size_t)row * DMn;
    float* yr = y + (size_t)row * DMn;
    const int t = threadIdx.x;
    const int lane = t & 31, wid = t >> 5;

    __shared__ float sh[32];
    __shared__ float s_mean, s_rstd;

    float vals[5];
    float s = 0.f;
#pragma unroll
    for (int i = 0; i < 5; i++) { vals[i] = xr[t + i * 256]; s += vals[i]; }
#pragma unroll
    for (int o = 16; o; o >>= 1) s += __shfl_xor_sync(0xffffffffu, s, o);
    if (lane == 0) sh[wid] = s;
    __syncthreads();
    if (wid == 0) {
        float v = (lane < 8) ? sh[lane] : 0.f;
#pragma unroll
        for (int o = 4; o; o >>= 1) v += __shfl_xor_sync(0xffffffffu, v, o);
        if (lane == 0) s_mean = v * (1.0f / DMn);
    }
    __syncthreads();
    const float mean = s_mean;
    __syncthreads();

    float vs = 0.f;
#pragma unroll
    for (int i = 0; i < 5; i++) { float d = vals[i] - mean; vs += d * d; }
#pragma unroll
    for (int o = 16; o; o >>= 1) vs += __shfl_xor_sync(0xffffffffu, vs, o);
    if (lane == 0) sh[wid] = vs;
    __syncthreads();
    if (wid == 0) {
        float v = (lane < 8) ? sh[lane] : 0.f;
#pragma unroll
        for (int o = 4; o; o >>= 1) v += __shfl_xor_sync(0xffffffffu, v, o);
        if (lane == 0) s_rstd = rsqrtf(v * (1.0f / DMn) + EPSLN);
    }
    __syncthreads();
    const float rstd = s_rstd;

#pragma unroll
    for (int i = 0; i < 5; i++) {
        int c = t + i * 256;
        yr[c] = (vals[i] - mean) * rstd * sc[c] + off[c];
    }
}

// ---------------- Generic tiled SGEMM with fused epilogue --------------------
// C[M,N] = A[M,K] @ B[K,N] + bias ; EPI: 0=bias, 1=bias+res, 2=bias+gelu(exact)
// Requires M%128==0, N%128==0, K%8==0. 256 threads, 8x8 per thread.
__device__ __forceinline__ float gelu_exact(float v) {
    return 0.5f * v * (1.0f + erff(v * 0.70710678118654752f));
}

template <int EPI>
__global__ void __launch_bounds__(256) gemm_epi(const float* __restrict__ A,
                                                const float* __restrict__ B,
                                                const float* __restrict__ bias,
                                                const float* __restrict__ res,
                                                float* __restrict__ C,
                                                int M, int N, int K)
{
    __shared__ float As[8][128];
    __shared__ float Bs[8][128];

    const int tid = threadIdx.x;
    const int tr = tid >> 4, tc = tid & 15;
    const int rowBase = blockIdx.y * 128;
    const int colBase = blockIdx.x * 128;

    const int aRow = tid >> 1;
    const int aCol = (tid & 1) * 4;
    const int bRow = tid >> 5;
    const int bCol = (tid & 31) * 4;

    const float* Ag = A + (size_t)(rowBase + aRow) * K + aCol;
    const float* Bg = B + (size_t)bRow * N + colBase + bCol;

    float acc[8][8];
#pragma unroll
    for (int i = 0; i < 8; i++)
#pragma unroll
        for (int j = 0; j < 8; j++) acc[i][j] = 0.f;

    for (int k0 = 0; k0 < K; k0 += 8) {
        float4 a4 = *reinterpret_cast<const float4*>(Ag + k0);
        float4 b4 = *reinterpret_cast<const float4*>(Bg + (size_t)k0 * N);
        As[aCol + 0][aRow] = a4.x;
        As[aCol + 1][aRow] = a4.y;
        As[aCol + 2][aRow] = a4.z;
        As[aCol + 3][aRow] = a4.w;
        *reinterpret_cast<float4*>(&Bs[bRow][bCol]) = b4;
        __syncthreads();
#pragma unroll
        for (int kk = 0; kk < 8; kk++) {
            float4 a0 = *reinterpret_cast<const float4*>(&As[kk][tr * 4]);
            float4 a1 = *reinterpret_cast<const float4*>(&As[kk][tr * 4 + 64]);
            float4 b0 = *reinterpret_cast<const float4*>(&Bs[kk][tc * 4]);
            float4 b1 = *reinterpret_cast<const float4*>(&Bs[kk][tc * 4 + 64]);
            float ra[8] = {a0.x, a0.y, a0.z, a0.w, a1.x, a1.y, a1.z, a1.w};
            float rb[8] = {b0.x, b0.y, b0.z, b0.w, b1.x, b1.y, b1.z, b1.w};
#pragma unroll
            for (int i = 0; i < 8; i++)
#pragma unroll
                for (int j = 0; j < 8; j++)
                    acc[i][j] = fmaf(ra[i], rb[j], acc[i][j]);
        }
        __syncthreads();
    }

#pragma unroll
    for (int i = 0; i < 8; i++) {
        const int row = rowBase + (i >> 2) * 64 + tr * 4 + (i & 3);
#pragma unroll
        for (int jb = 0; jb < 2; jb++) {
            const int col = colBase + jb * 64 + tc * 4;
            const float4 bb = *reinterpret_cast<const float4*>(&bias[col]);
            float4 o;
            o.x = acc[i][jb * 4 + 0] + bb.x;
            o.y = acc[i][jb * 4 + 1] + bb.y;
            o.z = acc[i][jb * 4 + 2] + bb.z;
            o.w = acc[i][jb * 4 + 3] + bb.w;
            if (EPI == 1) {
                const float4 r4 = *reinterpret_cast<const float4*>(&res[(size_t)row * N + col]);
                o.x += r4.x; o.y += r4.y; o.z += r4.z; o.w += r4.w;
            }
            if (EPI == 2) {
                o.x = gelu_exact(o.x); o.y = gelu_exact(o.y);
                o.z = gelu_exact(o.z); o.w = gelu_exact(o.w);
            }
            *reinterpret_cast<float4*>(&C[(size_t)row * N + col]) = o;
        }
    }
}

// ---------------- QK^T: logits[bh,t,T] = q.k / 8 ------------------------------
// grid (S/64, S/64, B*H), block 256; 64x64 output tile, loop over D=64.
__global__ void __launch_bounds__(256) qk_kernel(const float* __restrict__ q,
                                                 const float* __restrict__ k,
                                                 float* __restrict__ logits)
{
    __shared__ float Qs[64][65];
    __shared__ float Ks[64][65];
    const int bh = blockIdx.z;
    const int b = bh / Hn, h = bh % Hn;
    const int t0 = blockIdx.y * 64, T0 = blockIdx.x * 64;

    const float* qbase = q + ((size_t)(b * Sn + t0)) * DMn + h * Dn;
    const float* kbase = k + ((size_t)(b * Sn + T0)) * DMn + h * Dn;

    for (int i = threadIdx.x; i < 64 * 64; i += 256) {
        int r = i >> 6, c = i & 63;
        Qs[r][c] = qbase[(size_t)r * DMn + c];
        Ks[r][c] = kbase[(size_t)r * DMn + c];
    }
    __syncthreads();

    const int tr = threadIdx.x >> 4, tc = threadIdx.x & 15;
    float acc[4][4];
#pragma unroll
    for (int i = 0; i < 4; i++)
#pragma unroll
        for (int j = 0; j < 4; j++) acc[i][j] = 0.f;

#pragma unroll 4
    for (int d = 0; d < 64; d++) {
        float ra[4], rb[4];
#pragma unroll
        for (int i = 0; i < 4; i++) ra[i] = Qs[tr + 16 * i][d];
#pragma unroll
        for (int j = 0; j < 4; j++) rb[j] = Ks[tc + 16 * j][d];
#pragma unroll
        for (int i = 0; i < 4; i++)
#pragma unroll
            for (int j = 0; j < 4; j++)
                acc[i][j] = fmaf(ra[i], rb[j], acc[i][j]);
    }

    float* lbase = logits + ((size_t)bh * Sn) * Sn;
#pragma unroll
    for (int i = 0; i < 4; i++)
#pragma unroll
        for (int j = 0; j < 4; j++)
            lbase[(size_t)(t0 + tr + 16 * i) * Sn + T0 + tc + 16 * j] = acc[i][j] * 0.125f;
}

// ---------------- row softmax over 1024, in place -----------------------------
__global__ void __launch_bounds__(256) softmax_kernel(float* __restrict__ p)
{
    float* r = p + (size_t)blockIdx.x * Sn;
    const int t = threadIdx.x;
    const int lane = t & 31, wid = t >> 5;
    __shared__ float sh[32];
    __shared__ float s_max, s_sum;

    float v[4];
    float m = -1e30f;
#pragma unroll
    for (int i = 0; i < 4; i++) { v[i] = r[t + i * 256]; m = fmaxf(m, v[i]); }
#pragma unroll
    for (int o = 16; o; o >>= 1) m = fmaxf(m, __shfl_xor_sync(0xffffffffu, m, o));
    if (lane == 0) sh[wid] = m;
    __syncthreads();
    if (wid == 0) {
        float x = (lane < 8) ? sh[lane] : -1e30f;
#pragma unroll
        for (int o = 4; o; o >>= 1) x = fmaxf(x, __shfl_xor_sync(0xffffffffu, x, o));
        if (lane == 0) s_max = x;
    }
    __syncthreads();
    const float mx = s_max;
    __syncthreads();

    float s = 0.f;
#pragma unroll
    for (int i = 0; i < 4; i++) { v[i] = expf(v[i] - mx); s += v[i]; }
#pragma unroll
    for (int o = 16; o; o >>= 1) s += __shfl_xor_sync(0xffffffffu, s, o);
    if (lane == 0) sh[wid] = s;
    __syncthreads();
    if (wid == 0) {
        float x = (lane < 8) ? sh[lane] : 0.f;
#pragma unroll
        for (int o = 4; o; o >>= 1) x += __shfl_xor_sync(0xffffffffu, x, o);
        if (lane == 0) s_sum = x;
    }
    __syncthreads();
    const float inv = 1.0f / s_sum;
#pragma unroll
    for (int i = 0; i < 4; i++) r[t + i * 256] = v[i] * inv;
}

// ---------------- P @ V: attn[b,t,h,d] = sum_T w[bh,t,T] v[b,T,h,d] -----------
// grid (S/64, 1, B*H), block 256; output tile 64t x 64d; K loop over T in 16s.
__global__ void __launch_bounds__(256) wv_kernel(const float* __restrict__ w,
                                                 const float* __restrict__ v,
                                                 float* __restrict__ out)
{
    __shared__ float Ws[64][17];
    __shared__ float Vs[16][65];
    const int bh = blockIdx.z;
    const int b = bh / Hn, h = bh % Hn;
    const int t0 = blockIdx.x * 64;
    const int tid = threadIdx.x;
    const int tr = tid >> 4, tc = tid & 15;

    const float* wbase = w + ((size_t)bh * Sn + t0) * Sn;
    const float* vbase = v + (size_t)b * Sn * DMn + h * Dn;

    float acc[4][4];
#pragma unroll
    for (int i = 0; i < 4; i++)
#pragma unroll
        for (int j = 0; j < 4; j++) acc[i][j] = 0.f;

    for (int T0 = 0; T0 < Sn; T0 += 16) {
#pragma unroll
        for (int it = 0; it < 4; it++) {
            int lin = tid + it * 256;            // 0..1023
            int r = lin >> 4, c = lin & 15;      // Ws 64x16
            Ws[r][c] = wbase[(size_t)r * Sn + T0 + c];
        }
#pragma unroll
        for (int it = 0; it < 4; it++) {
            int lin = tid + it * 256;            // Vs 16x64
            int r = lin >> 6, c = lin & 63;
            Vs[r][c] = vbase[(size_t)(T0 + r) * DMn + c];
        }
        __syncthreads();
#pragma unroll
        for (int kk = 0; kk < 16; kk++) {
            float ra[4], rb[4];
#pragma unroll
            for (int i = 0; i < 4; i++) ra[i] = Ws[tr + 16 * i][kk];
#pragma unroll
            for (int j = 0; j < 4; j++) rb[j] = Vs[kk][tc + 16 * j];
#pragma unroll
            for (int i = 0; i < 4; i++)
#pragma unroll
                for (int j = 0; j < 4; j++)
                    acc[i][j] = fmaf(ra[i], rb[j], acc[i][j]);
        }
        __syncthreads();
    }

    float* obase = out + ((size_t)(b * Sn + t0)) * DMn + h * Dn;
#pragma unroll
    for (int i = 0; i < 4; i++)
#pragma unroll
        for (int j = 0; j < 4; j++)
            obase[(size_t)(tr + 16 * i) * DMn + tc + 16 * j] = acc[i][j];
}

// ---------------- launch ------------------------------------------------------
extern "C" void kernel_launch(void* const* d_in, const int* in_sizes, int n_in,
                              void* d_out, int out_size)
{
    const float* x        = (const float*)d_in[0];
    const float* ln1_s    = (const float*)d_in[1];
    const float* ln1_o    = (const float*)d_in[2];
    const float* wq       = (const float*)d_in[3];
    const float* bq       = (const float*)d_in[4];
    const float* wk       = (const float*)d_in[5];
    const float* bk       = (const float*)d_in[6];
    const float* wv       = (const float*)d_in[7];
    const float* bv       = (const float*)d_in[8];
    const float* wo       = (const float*)d_in[9];
    const float* bo       = (const float*)d_in[10];
    const float* ln2_s    = (const float*)d_in[11];
    const float* ln2_o    = (const float*)d_in[12];
    const float* fc1_w    = (const float*)d_in[13];
    const float* fc1_b    = (const float*)d_in[14];
    const float* fc2_w    = (const float*)d_in[15];
    const float* fc2_b    = (const float*)d_in[16];
    float* out            = (float*)d_out;

    float *ph, *pq, *pk, *pv, *pattn, *px1, *pf1, *plog;
    cudaGetSymbolAddress((void**)&ph,    g_h);
    cudaGetSymbolAddress((void**)&pq,    g_q);
    cudaGetSymbolAddress((void**)&pk,    g_k);
    cudaGetSymbolAddress((void**)&pv,    g_v);
    cudaGetSymbolAddress((void**)&pattn, g_attn);
    cudaGetSymbolAddress((void**)&px1,   g_x1);
    cudaGetSymbolAddress((void**)&pf1,   g_f1);
    cudaGetSymbolAddress((void**)&plog,  g_logits);

    // 1) LN1
    ln_kernel<<<NTOK, 256>>>(x, ln1_s, ln1_o, ph);

    // 2) Q, K, V projections
    {
        dim3 grid(DMn / 128, NTOK / 128);
        gemm_epi<0><<<grid, 256>>>(ph, wq, bq, nullptr, pq, NTOK, DMn, DMn);
        gemm_epi<0><<<grid, 256>>>(ph, wk, bk, nullptr, pk, NTOK, DMn, DMn);
        gemm_epi<0><<<grid, 256>>>(ph, wv, bv, nullptr, pv, NTOK, DMn, DMn);
    }

    // 3) attention scores + softmax + PV
    {
        dim3 grid(Sn / 64, Sn / 64, NBH);
        qk_kernel<<<grid, 256>>>(pq, pk, plog);
    }
    softmax_kernel<<<NBH * Sn, 256>>>(plog);
    {
        dim3 grid(Sn / 64, 1, NBH);
        wv_kernel<<<grid, 256>>>(plog, pv, pattn);
    }

    // 4) output projection + residual(x) -> x1
    {
        dim3 grid(DMn / 128, NTOK / 128);
        gemm_epi<1><<<grid, 256>>>(pattn, wo, bo, x, px1, NTOK, DMn, DMn);
    }

    // 5) LN2
    ln_kernel<<<NTOK, 256>>>(px1, ln2_s, ln2_o, ph);

    // 6) FC1 + exact GELU
    {
        dim3 grid(DFn / 128, NTOK / 128);
        gemm_epi<2><<<grid, 256>>>(ph, fc1_w, fc1_b, nullptr, pf1, NTOK, DFn, DMn);
    }

    // 7) FC2 + residual(x1) -> out
    {
        dim3 grid(DMn / 128, NTOK / 128);
        gemm_epi<1><<<grid, 256>>>(pf1, fc2_w, fc2_b, px1, out, NTOK, DMn, DFn);
    }
}

// round 2
// speedup vs baseline: 2.1221x; 2.1221x over previous
#include <cuda_runtime.h>
#include <math.h>
#include <stdint.h>

// Problem constants
#define Bn   4
#define Sn   1024
#define Hn   20
#define Dn   64
#define DMn  1280
#define DFn  5120
#define NTOK 4096           // Bn*Sn
#define NBH  80             // Bn*Hn
#define EPSLN 1e-5f

// ---------------- scratch (static device globals; no allocation) -------------
__device__ float g_h   [(size_t)NTOK * DMn];           // LN output
__device__ float g_q   [(size_t)NTOK * DMn];
__device__ float g_k   [(size_t)NTOK * DMn];
__device__ float g_v   [(size_t)NTOK * DMn];
__device__ float g_attn[(size_t)NTOK * DMn];
__device__ float g_x1  [(size_t)NTOK * DMn];           // x + attn proj (residual 1)
__device__ float g_f1  [(size_t)NTOK * DFn];           // FC1/GELU output
__device__ float g_logits[(size_t)NBH * Sn * Sn];      // 320 MB attention scores

// ---------------- LayerNorm: one block per row --------------------------------
__global__ void __launch_bounds__(256) ln_kernel(const float* __restrict__ x,
                                                 const float* __restrict__ sc,
                                                 const float* __restrict__ off,
                                                 float* __restrict__ y)
{
    const int row = blockIdx.x;
    const float* xr = x + (size_t)row * DMn;
    float* yr = y + (size_t)row * DMn;
    const int t = threadIdx.x;
    const int lane = t & 31, wid = t >> 5;

    __shared__ float sh[32];
    __shared__ float s_mean, s_rstd;

    float vals[5];
    float s = 0.f;
#pragma unroll
    for (int i = 0; i < 5; i++) { vals[i] = xr[t + i * 256]; s += vals[i]; }
#pragma unroll
    for (int o = 16; o; o >>= 1) s += __shfl_xor_sync(0xffffffffu, s, o);
    if (lane == 0) sh[wid] = s;
    __syncthreads();
    if (wid == 0) {
        float v = (lane < 8) ? sh[lane] : 0.f;
#pragma unroll
        for (int o = 4; o; o >>= 1) v += __shfl_xor_sync(0xffffffffu, v, o);
        if (lane == 0) s_mean = v * (1.0f / DMn);
    }
    __syncthreads();
    const float mean = s_mean;
    __syncthreads();

    float vs = 0.f;
#pragma unroll
    for (int i = 0; i < 5; i++) { float d = vals[i] - mean; vs += d * d; }
#pragma unroll
    for (int o = 16; o; o >>= 1) vs += __shfl_xor_sync(0xffffffffu, vs, o);
    if (lane == 0) sh[wid] = vs;
    __syncthreads();
    if (wid == 0) {
        float v = (lane < 8) ? sh[lane] : 0.f;
#pragma unroll
        for (int o = 4; o; o >>= 1) v += __shfl_xor_sync(0xffffffffu, v, o);
        if (lane == 0) s_rstd = rsqrtf(v * (1.0f / DMn) + EPSLN);
    }
    __syncthreads();
    const float rstd = s_rstd;

#pragma unroll
    for (int i = 0; i < 5; i++) {
        int c = t + i * 256;
        yr[c] = (vals[i] - mean) * rstd * sc[c] + off[c];
    }
}

// ---------------- TF32 tensor-core GEMM with fused epilogue ------------------
// C[M,N] = A[M,K] @ B[K,N] + bias ; EPI: 0=bias, 1=bias+res, 2=bias+gelu(exact)
// 256 threads, 128x128 CTA tile, warp tile 64x32, mma.sync m16n8k8 tf32.
// Requires M%128==0, N%128==0, K%16==0.
__device__ __forceinline__ float gelu_exact(float v) {
    return 0.5f * v * (1.0f + erff(v * 0.70710678118654752f));
}

__device__ __forceinline__ uint32_t f2tf(float f) {
    uint32_t u;
    asm("cvt.rna.tf32.f32 %0, %1;" : "=r"(u) : "f"(f));
    return u;
}

#define AS_STRIDE 20   // 16 k + 4 pad  -> conflict-free A fragment LDS
#define BS_STRIDE 132  // 128 n + 4 pad -> 2-way on B fragment LDS

template <int EPI>
__global__ void __launch_bounds__(256, 2) gemm_tf32(const float* __restrict__ A,
                                                    const float* __restrict__ B,
                                                    const float* __restrict__ bias,
                                                    const float* __restrict__ res,
                                                    float* __restrict__ C,
                                                    int M, int N, int K)
{
    __shared__ uint32_t As[2][128 * AS_STRIDE];
    __shared__ uint32_t Bs[2][16 * BS_STRIDE];

    const int tid = threadIdx.x;
    const int rowBase = blockIdx.y * 128;
    const int colBase = blockIdx.x * 128;
    const int lane = tid & 31, warp = tid >> 5;
    const int wm = (warp >> 2) * 64;   // 0 / 64
    const int wn = (warp & 3) * 32;    // 0,32,64,96
    const int g = lane >> 2, t4 = lane & 3;

    float acc[16][4];
#pragma unroll
    for (int i = 0; i < 16; i++)
#pragma unroll
        for (int j = 0; j < 4; j++) acc[i][j] = 0.f;

    float4 pa[2], pb[2];

    // staging index precompute
    const int ar0 = tid >> 2, ac0 = (tid & 3) * 4;            // i=0
    const int ar1 = (tid + 256) >> 2, ac1 = ((tid + 256) & 3) * 4;
    const int br0 = tid >> 5, bc0 = (tid & 31) * 4;
    const int br1 = (tid + 256) >> 5, bc1 = ((tid + 256) & 31) * 4;

    auto loadTiles = [&](int k0) {
        pa[0] = *reinterpret_cast<const float4*>(A + (size_t)(rowBase + ar0) * K + k0 + ac0);
        pa[1] = *reinterpret_cast<const float4*>(A + (size_t)(rowBase + ar1) * K + k0 + ac1);
        pb[0] = *reinterpret_cast<const float4*>(B + (size_t)(k0 + br0) * N + colBase + bc0);
        pb[1] = *reinterpret_cast<const float4*>(B + (size_t)(k0 + br1) * N + colBase + bc1);
    };
    auto storeTiles = [&](int buf) {
        uint32_t* d0 = &As[buf][ar0 * AS_STRIDE + ac0];
        d0[0] = f2tf(pa[0].x); d0[1] = f2tf(pa[0].y); d0[2] = f2tf(pa[0].z); d0[3] = f2tf(pa[0].w);
        uint32_t* d1 = &As[buf][ar1 * AS_STRIDE + ac1];
        d1[0] = f2tf(pa[1].x); d1[1] = f2tf(pa[1].y); d1[2] = f2tf(pa[1].z); d1[3] = f2tf(pa[1].w);
        uint32_t* e0 = &Bs[buf][br0 * BS_STRIDE + bc0];
        e0[0] = f2tf(pb[0].x); e0[1] = f2tf(pb[0].y); e0[2] = f2tf(pb[0].z); e0[3] = f2tf(pb[0].w);
        uint32_t* e1 = &Bs[buf][br1 * BS_STRIDE + bc1];
        e1[0] = f2tf(pb[1].x); e1[1] = f2tf(pb[1].y); e1[2] = f2tf(pb[1].z); e1[3] = f2tf(pb[1].w);
    };
    auto compute = [&](int buf) {
#pragma unroll
        for (int ks = 0; ks < 2; ks++) {
            const int ko = ks * 8;
            uint32_t a[4][4], b[4][2];
#pragma unroll
            for (int mi = 0; mi < 4; mi++) {
                const uint32_t* p = &As[buf][(wm + mi * 16 + g) * AS_STRIDE + ko + t4];
                a[mi][0] = p[0];
                a[mi][1] = p[8 * AS_STRIDE];
                a[mi][2] = p[4];
                a[mi][3] = p[8 * AS_STRIDE + 4];
            }
#pragma unroll
            for (int ni = 0; ni < 4; ni++) {
                const uint32_t* p = &Bs[buf][(ko + t4) * BS_STRIDE + wn + ni * 8 + g];
                b[ni][0] = p[0];
                b[ni][1] = p[4 * BS_STRIDE];
            }
#pragma unroll
            for (int mi = 0; mi < 4; mi++)
#pragma unroll
                for (int ni = 0; ni < 4; ni++) {
                    float* c = acc[mi * 4 + ni];
                    asm volatile(
                        "mma.sync.aligned.m16n8k8.row.col.f32.tf32.tf32.f32 "
                        "{%0,%1,%2,%3}, {%4,%5,%6,%7}, {%8,%9}, {%0,%1,%2,%3};"
                        : "+f"(c[0]), "+f"(c[1]), "+f"(c[2]), "+f"(c[3])
                        : "r"(a[mi][0]), "r"(a[mi][1]), "r"(a[mi][2]), "r"(a[mi][3]),
                          "r"(b[ni][0]), "r"(b[ni][1]));
                }
        }
    };

    loadTiles(0);
    storeTiles(0);
    __syncthreads();

    const int nIt = K >> 4;
    for (int it = 0; it < nIt; ++it) {
        const int buf = it & 1;
        if (it + 1 < nIt) loadTiles((it + 1) << 4);
        compute(buf);
        if (it + 1 < nIt) {
            storeTiles(buf ^ 1);
            __syncthreads();
        }
    }

    // epilogue
#pragma unroll
    for (int mi = 0; mi < 4; mi++) {
#pragma unroll
        for (int ni = 0; ni < 4; ni++) {
            float* c = acc[mi * 4 + ni];
            const int col = colBase + wn + ni * 8 + t4 * 2;
            const float2 bb = *reinterpret_cast<const float2*>(bias + col);
#pragma unroll
            for (int h = 0; h < 2; h++) {
                const int row = rowBase + wm + mi * 16 + g + h * 8;
                float o0 = c[h * 2 + 0] + bb.x;
                float o1 = c[h * 2 + 1] + bb.y;
                if (EPI == 1) {
                    const float2 r2 = *reinterpret_cast<const float2*>(res + (size_t)row * N + col);
                    o0 += r2.x; o1 += r2.y;
                }
                if (EPI == 2) {
                    o0 = gelu_exact(o0);
                    o1 = gelu_exact(o1);
                }
                *reinterpret_cast<float2*>(C + (size_t)row * N + col) = make_float2(o0, o1);
            }
        }
    }
}

// ---------------- QK^T: logits[bh,t,T] = q.k / 8 ------------------------------
__global__ void __launch_bounds__(256) qk_kernel(const float* __restrict__ q,
                                                 const float* __restrict__ k,
                                                 float* __restrict__ logits)
{
    __shared__ float Qs[64][65];
    __shared__ float Ks[64][65];
    const int bh = blockIdx.z;
    const int b = bh / Hn, h = bh % Hn;
    const int t0 = blockIdx.y * 64, T0 = blockIdx.x * 64;

    const float* qbase = q + ((size_t)(b * Sn + t0)) * DMn + h * Dn;
    const float* kbase = k + ((size_t)(b * Sn + T0)) * DMn + h * Dn;

    for (int i = threadIdx.x; i < 64 * 64; i += 256) {
        int r = i >> 6, c = i & 63;
        Qs[r][c] = qbase[(size_t)r * DMn + c];
        Ks[r][c] = kbase[(size_t)r * DMn + c];
    }
    __syncthreads();

    const int tr = threadIdx.x >> 4, tc = threadIdx.x & 15;
    float acc[4][4];
#pragma unroll
    for (int i = 0; i < 4; i++)
#pragma unroll
        for (int j = 0; j < 4; j++) acc[i][j] = 0.f;

#pragma unroll 4
    for (int d = 0; d < 64; d++) {
        float ra[4], rb[4];
#pragma unroll
        for (int i = 0; i < 4; i++) ra[i] = Qs[tr + 16 * i][d];
#pragma unroll
        for (int j = 0; j < 4; j++) rb[j] = Ks[tc + 16 * j][d];
#pragma unroll
        for (int i = 0; i < 4; i++)
#pragma unroll
            for (int j = 0; j < 4; j++)
                acc[i][j] = fmaf(ra[i], rb[j], acc[i][j]);
    }

    float* lbase = logits + ((size_t)bh * Sn) * Sn;
#pragma unroll
    for (int i = 0; i < 4; i++)
#pragma unroll
        for (int j = 0; j < 4; j++)
            lbase[(size_t)(t0 + tr + 16 * i) * Sn + T0 + tc + 16 * j] = acc[i][j] * 0.125f;
}

// ---------------- row softmax over 1024, in place -----------------------------
__global__ void __launch_bounds__(256) softmax_kernel(float* __restrict__ p)
{
    float* r = p + (size_t)blockIdx.x * Sn;
    const int t = threadIdx.x;
    const int lane = t & 31, wid = t >> 5;
    __shared__ float sh[32];
    __shared__ float s_max, s_sum;

    float v[4];
    float m = -1e30f;
#pragma unroll
    for (int i = 0; i < 4; i++) { v[i] = r[t + i * 256]; m = fmaxf(m, v[i]); }
#pragma unroll
    for (int o = 16; o; o >>= 1) m = fmaxf(m, __shfl_xor_sync(0xffffffffu, m, o));
    if (lane == 0) sh[wid] = m;
    __syncthreads();
    if (wid == 0) {
        float x = (lane < 8) ? sh[lane] : -1e30f;
#pragma unroll
        for (int o = 4; o; o >>= 1) x = fmaxf(x, __shfl_xor_sync(0xffffffffu, x, o));
        if (lane == 0) s_max = x;
    }
    __syncthreads();
    const float mx = s_max;
    __syncthreads();

    float s = 0.f;
#pragma unroll
    for (int i = 0; i < 4; i++) { v[i] = expf(v[i] - mx); s += v[i]; }
#pragma unroll
    for (int o = 16; o; o >>= 1) s += __shfl_xor_sync(0xffffffffu, s, o);
    if (lane == 0) sh[wid] = s;
    __syncthreads();
    if (wid == 0) {
        float x = (lane < 8) ? sh[lane] : 0.f;
#pragma unroll
        for (int o = 4; o; o >>= 1) x += __shfl_xor_sync(0xffffffffu, x, o);
        if (lane == 0) s_sum = x;
    }
    __syncthreads();
    const float inv = 1.0f / s_sum;
#pragma unroll
    for (int i = 0; i < 4; i++) r[t + i * 256] = v[i] * inv;
}

// ---------------- P @ V -------------------------------------------------------
__global__ void __launch_bounds__(256) wv_kernel(const float* __restrict__ w,
                                                 const float* __restrict__ v,
                                                 float* __restrict__ out)
{
    __shared__ float Ws[64][17];
    __shared__ float Vs[16][65];
    const int bh = blockIdx.z;
    const int b = bh / Hn, h = bh % Hn;
    const int t0 = blockIdx.x * 64;
    const int tid = threadIdx.x;
    const int tr = tid >> 4, tc = tid & 15;

    const float* wbase = w + ((size_t)bh * Sn + t0) * Sn;
    const float* vbase = v + (size_t)b * Sn * DMn + h * Dn;

    float acc[4][4];
#pragma unroll
    for (int i = 0; i < 4; i++)
#pragma unroll
        for (int j = 0; j < 4; j++) acc[i][j] = 0.f;

    for (int T0 = 0; T0 < Sn; T0 += 16) {
#pragma unroll
        for (int it = 0; it < 4; it++) {
            int lin = tid + it * 256;
            int r = lin >> 4, c = lin & 15;
            Ws[r][c] = wbase[(size_t)r * Sn + T0 + c];
        }
#pragma unroll
        for (int it = 0; it < 4; it++) {
            int lin = tid + it * 256;
            int r = lin >> 6, c = lin & 63;
            Vs[r][c] = vbase[(size_t)(T0 + r) * DMn + c];
        }
        __syncthreads();
#pragma unroll
        for (int kk = 0; kk < 16; kk++) {
            float ra[4], rb[4];
#pragma unroll
            for (int i = 0; i < 4; i++) ra[i] = Ws[tr + 16 * i][kk];
#pragma unroll
            for (int j = 0; j < 4; j++) rb[j] = Vs[kk][tc + 16 * j];
#pragma unroll
            for (int i = 0; i < 4; i++)
#pragma unroll
                for (int j = 0; j < 4; j++)
                    acc[i][j] = fmaf(ra[i], rb[j], acc[i][j]);
        }
        __syncthreads();
    }

    float* obase = out + ((size_t)(b * Sn + t0)) * DMn + h * Dn;
#pragma unroll
    for (int i = 0; i < 4; i++)
#pragma unroll
        for (int j = 0; j < 4; j++)
            obase[(size_t)(tr + 16 * i) * DMn + tc + 16 * j] = acc[i][j];
}

// ---------------- launch ------------------------------------------------------
extern "C" void kernel_launch(void* const* d_in, const int* in_sizes, int n_in,
                              void* d_out, int out_size)
{
    const float* x        = (const float*)d_in[0];
    const float* ln1_s    = (const float*)d_in[1];
    const float* ln1_o    = (const float*)d_in[2];
    const float* wq       = (const float*)d_in[3];
    const float* bq       = (const float*)d_in[4];
    const float* wk       = (const float*)d_in[5];
    const float* bk       = (const float*)d_in[6];
    const float* wv       = (const float*)d_in[7];
    const float* bv       = (const float*)d_in[8];
    const float* wo       = (const float*)d_in[9];
    const float* bo       = (const float*)d_in[10];
    const float* ln2_s    = (const float*)d_in[11];
    const float* ln2_o    = (const float*)d_in[12];
    const float* fc1_w    = (const float*)d_in[13];
    const float* fc1_b    = (const float*)d_in[14];
    const float* fc2_w    = (const float*)d_in[15];
    const float* fc2_b    = (const float*)d_in[16];
    float* out            = (float*)d_out;

    float *ph, *pq, *pk, *pv, *pattn, *px1, *pf1, *plog;
    cudaGetSymbolAddress((void**)&ph,    g_h);
    cudaGetSymbolAddress((void**)&pq,    g_q);
    cudaGetSymbolAddress((void**)&pk,    g_k);
    cudaGetSymbolAddress((void**)&pv,    g_v);
    cudaGetSymbolAddress((void**)&pattn, g_attn);
    cudaGetSymbolAddress((void**)&px1,   g_x1);
    cudaGetSymbolAddress((void**)&pf1,   g_f1);
    cudaGetSymbolAddress((void**)&plog,  g_logits);

    // 1) LN1
    ln_kernel<<<NTOK, 256>>>(x, ln1_s, ln1_o, ph);

    // 2) Q, K, V projections (tf32 tensor cores)
    {
        dim3 grid(DMn / 128, NTOK / 128);
        gemm_tf32<0><<<grid, 256>>>(ph, wq, bq, nullptr, pq, NTOK, DMn, DMn);
        gemm_tf32<0><<<grid, 256>>>(ph, wk, bk, nullptr, pk, NTOK, DMn, DMn);
        gemm_tf32<0><<<grid, 256>>>(ph, wv, bv, nullptr, pv, NTOK, DMn, DMn);
    }

    // 3) attention scores + softmax + PV
    {
        dim3 grid(Sn / 64, Sn / 64, NBH);
        qk_kernel<<<grid, 256>>>(pq, pk, plog);
    }
    softmax_kernel<<<NBH * Sn, 256>>>(plog);
    {
        dim3 grid(Sn / 64, 1, NBH);
        wv_kernel<<<grid, 256>>>(plog, pv, pattn);
    }

    // 4) output projection + residual(x) -> x1
    {
        dim3 grid(DMn / 128, NTOK / 128);
        gemm_tf32<1><<<grid, 256>>>(pattn, wo, bo, x, px1, NTOK, DMn, DMn);
    }

    // 5) LN2
    ln_kernel<<<NTOK, 256>>>(px1, ln2_s, ln2_o, ph);

    // 6) FC1 + exact GELU
    {
        dim3 grid(DFn / 128, NTOK / 128);
        gemm_tf32<2><<<grid, 256>>>(ph, fc1_w, fc1_b, nullptr, pf1, NTOK, DFn, DMn);
    }

    // 7) FC2 + residual(x1) -> out
    {
        dim3 grid(DMn / 128, NTOK / 128);
        gemm_tf32<1><<<grid, 256>>>(pf1, fc2_w, fc2_b, px1, out, NTOK, DMn, DFn);
    }
}

// round 3
// speedup vs baseline: 3.0448x; 1.4348x over previous
#include <cuda_runtime.h>
#include <math.h>
#include <stdint.h>

// Problem constants
#define Bn   4
#define Sn   1024
#define Hn   20
#define Dn   64
#define DMn  1280
#define DFn  5120
#define NTOK 4096           // Bn*Sn
#define NBH  80             // Bn*Hn
#define EPSLN 1e-5f

// ---------------- scratch (static device globals; no allocation) -------------
__device__ float g_h   [(size_t)NTOK * DMn];           // LN output (tf32-rounded)
__device__ float g_q   [(size_t)NTOK * DMn];
__device__ float g_k   [(size_t)NTOK * DMn];
__device__ float g_v   [(size_t)NTOK * DMn];
__device__ float g_attn[(size_t)NTOK * DMn];           // flash output (tf32-rounded)
__device__ float g_x1  [(size_t)NTOK * DMn];           // x + attn proj (residual 1)
__device__ float g_f1  [(size_t)NTOK * DFn];           // FC1/GELU output (tf32-rounded)
__device__ float g_wr  [19660800];                     // tf32-rounded weights

#define WSZ_DM (DMn * DMn)          // 1,638,400
#define WSZ_FC (DMn * DFn)          // 6,553,600

// ---------------- tf32 helpers ------------------------------------------------
__device__ __forceinline__ uint32_t f2tf(float f) {
    uint32_t u;
    asm("cvt.rna.tf32.f32 %0, %1;" : "=r"(u) : "f"(f));
    return u;
}
__device__ __forceinline__ float rtf(float f) { return __uint_as_float(f2tf(f)); }

// ---------------- weight rounding (per replay; deterministic) -----------------
__global__ void __launch_bounds__(256) round4_kernel(const float4* __restrict__ in,
                                                     float4* __restrict__ out, int n4)
{
    int i = blockIdx.x * 256 + threadIdx.x;
    if (i < n4) {
        float4 f = in[i];
        f.x = rtf(f.x); f.y = rtf(f.y); f.z = rtf(f.z); f.w = rtf(f.w);
        out[i] = f;
    }
}

// ---------------- LayerNorm: one block per row (tf32-rounded output) ----------
__global__ void __launch_bounds__(256) ln_kernel(const float* __restrict__ x,
                                                 const float* __restrict__ sc,
                                                 const float* __restrict__ off,
                                                 float* __restrict__ y)
{
    const int row = blockIdx.x;
    const float* xr = x + (size_t)row * DMn;
    float* yr = y + (size_t)row * DMn;
    const int t = threadIdx.x;
    const int lane = t & 31, wid = t >> 5;

    __shared__ float sh[32];
    __shared__ float s_mean, s_rstd;

    float vals[5];
    float s = 0.f;
#pragma unroll
    for (int i = 0; i < 5; i++) { vals[i] = xr[t + i * 256]; s += vals[i]; }
#pragma unroll
    for (int o = 16; o; o >>= 1) s += __shfl_xor_sync(0xffffffffu, s, o);
    if (lane == 0) sh[wid] = s;
    __syncthreads();
    if (wid == 0) {
        float v = (lane < 8) ? sh[lane] : 0.f;
#pragma unroll
        for (int o = 4; o; o >>= 1) v += __shfl_xor_sync(0xffffffffu, v, o);
        if (lane == 0) s_mean = v * (1.0f / DMn);
    }
    __syncthreads();
    const float mean = s_mean;
    __syncthreads();

    float vs = 0.f;
#pragma unroll
    for (int i = 0; i < 5; i++) { float d = vals[i] - mean; vs += d * d; }
#pragma unroll
    for (int o = 16; o; o >>= 1) vs += __shfl_xor_sync(0xffffffffu, vs, o);
    if (lane == 0) sh[wid] = vs;
    __syncthreads();
    if (wid == 0) {
        float v = (lane < 8) ? sh[lane] : 0.f;
#pragma unroll
        for (int o = 4; o; o >>= 1) v += __shfl_xor_sync(0xffffffffu, v, o);
        if (lane == 0) s_rstd = rsqrtf(v * (1.0f / DMn) + EPSLN);
    }
    __syncthreads();
    const float rstd = s_rstd;

#pragma unroll
    for (int i = 0; i < 5; i++) {
        int c = t + i * 256;
        yr[c] = rtf((vals[i] - mean) * rstd * sc[c] + off[c]);
    }
}

// ---------------- TF32 tensor-core GEMM, cp.async pipeline -------------------
// C[M,N] = A[M,K] @ B[K,N] + bias ; EPI: 0=bias, 1=bias+res, 2=bias+gelu(exact)
// A and B MUST be tf32-pre-rounded floats. 256 threads, 128x128 tile.
__device__ __forceinline__ float gelu_exact(float v) {
    return 0.5f * v * (1.0f + erff(v * 0.70710678118654752f));
}

__device__ __forceinline__ void cp16(void* smem_dst, const void* gsrc) {
    uint32_t s = (uint32_t)__cvta_generic_to_shared(smem_dst);
    asm volatile("cp.async.cg.shared.global [%0], [%1], 16;" :: "r"(s), "l"(gsrc));
}

#define AS_STRIDE 20   // 16 k + 4 pad  -> conflict-free A fragment LDS
#define BS_STRIDE 136  // 128 n + 8 pad -> conflict-free B fragment LDS

template <int EPI>
__global__ void __launch_bounds__(256, 2) gemm_tf32(const float* __restrict__ A,
                                                    const float* __restrict__ B,
                                                    const float* __restrict__ bias,
                                                    const float* __restrict__ res,
                                                    float* __restrict__ C,
                                                    int M, int N, int K)
{
    __shared__ float As[2][128 * AS_STRIDE];
    __shared__ float Bs[2][16 * BS_STRIDE];

    const int tid = threadIdx.x;
    const int rowBase = blockIdx.y * 128;
    const int colBase = blockIdx.x * 128;
    const int lane = tid & 31, warp = tid >> 5;
    const int wm = (warp >> 2) * 64;   // 0 / 64
    const int wn = (warp & 3) * 32;    // 0,32,64,96
    const int g = lane >> 2, t4 = lane & 3;

    float acc[16][4];
#pragma unroll
    for (int i = 0; i < 16; i++)
#pragma unroll
        for (int j = 0; j < 4; j++) acc[i][j] = 0.f;

    const int ar0 = tid >> 2, ac0 = (tid & 3) * 4;
    const int ar1 = (tid + 256) >> 2, ac1 = ((tid + 256) & 3) * 4;
    const int br0 = tid >> 5, bc0 = (tid & 31) * 4;
    const int br1 = (tid + 256) >> 5, bc1 = ((tid + 256) & 31) * 4;

    auto issueLoads = [&](int k0, int buf) {
        cp16(&As[buf][ar0 * AS_STRIDE + ac0], A + (size_t)(rowBase + ar0) * K + k0 + ac0);
        cp16(&As[buf][ar1 * AS_STRIDE + ac1], A + (size_t)(rowBase + ar1) * K + k0 + ac1);
        cp16(&Bs[buf][br0 * BS_STRIDE + bc0], B + (size_t)(k0 + br0) * N + colBase + bc0);
        cp16(&Bs[buf][br1 * BS_STRIDE + bc1], B + (size_t)(k0 + br1) * N + colBase + bc1);
        asm volatile("cp.async.commit_group;" ::: "memory");
    };
    auto compute = [&](int buf) {
#pragma unroll
        for (int ks = 0; ks < 2; ks++) {
            const int ko = ks * 8;
            uint32_t a[4][4], b[4][2];
#pragma unroll
            for (int mi = 0; mi < 4; mi++) {
                const float* p = &As[buf][(wm + mi * 16 + g) * AS_STRIDE + ko + t4];
                a[mi][0] = __float_as_uint(p[0]);
                a[mi][1] = __float_as_uint(p[8 * AS_STRIDE]);
                a[mi][2] = __float_as_uint(p[4]);
                a[mi][3] = __float_as_uint(p[8 * AS_STRIDE + 4]);
            }
#pragma unroll
            for (int ni = 0; ni < 4; ni++) {
                const float* p = &Bs[buf][(ko + t4) * BS_STRIDE + wn + ni * 8 + g];
                b[ni][0] = __float_as_uint(p[0]);
                b[ni][1] = __float_as_uint(p[4 * BS_STRIDE]);
            }
#pragma unroll
            for (int mi = 0; mi < 4; mi++)
#pragma unroll
                for (int ni = 0; ni < 4; ni++) {
                    float* c = acc[mi * 4 + ni];
                    asm volatile(
                        "mma.sync.aligned.m16n8k8.row.col.f32.tf32.tf32.f32 "
                        "{%0,%1,%2,%3}, {%4,%5,%6,%7}, {%8,%9}, {%0,%1,%2,%3};"
                        : "+f"(c[0]), "+f"(c[1]), "+f"(c[2]), "+f"(c[3])
                        : "r"(a[mi][0]), "r"(a[mi][1]), "r"(a[mi][2]), "r"(a[mi][3]),
                          "r"(b[ni][0]), "r"(b[ni][1]));
                }
        }
    };

    issueLoads(0, 0);
    const int nIt = K >> 4;
    for (int it = 0; it < nIt; ++it) {
        const int buf = it & 1;
        if (it + 1 < nIt) {
            issueLoads((it + 1) << 4, buf ^ 1);
            asm volatile("cp.async.wait_group 1;" ::: "memory");
        } else {
            asm volatile("cp.async.wait_group 0;" ::: "memory");
        }
        __syncthreads();
        compute(buf);
        __syncthreads();
    }

    // epilogue
#pragma unroll
    for (int mi = 0; mi < 4; mi++) {
#pragma unroll
        for (int ni = 0; ni < 4; ni++) {
            float* c = acc[mi * 4 + ni];
            const int col = colBase + wn + ni * 8 + t4 * 2;
            const float2 bb = *reinterpret_cast<const float2*>(bias + col);
#pragma unroll
            for (int h = 0; h < 2; h++) {
                const int row = rowBase + wm + mi * 16 + g + h * 8;
                float o0 = c[h * 2 + 0] + bb.x;
                float o1 = c[h * 2 + 1] + bb.y;
                if (EPI == 1) {
                    const float2 r2 = *reinterpret_cast<const float2*>(res + (size_t)row * N + col);
                    o0 += r2.x; o1 += r2.y;
                }
                if (EPI == 2) {
                    o0 = rtf(gelu_exact(o0));   // feeds FC2 A operand
                    o1 = rtf(gelu_exact(o1));
                }
                *reinterpret_cast<float2*>(C + (size_t)row * N + col) = make_float2(o0, o1);
            }
        }
    }
}

// ---------------- fused flash attention (tf32 mma, online softmax) -----------
// grid (S/64, B*H), 256 threads (8 warps as 4m x 2n, warp tile 16x32).
// SMEM: Qs/Ks/Vs/Ss 64x68 floats each + m/l/alpha rows. ~70KB dynamic.
#define FST 68
__global__ void __launch_bounds__(256) flash_attn(const float* __restrict__ q,
                                                  const float* __restrict__ k,
                                                  const float* __restrict__ v,
                                                  float* __restrict__ out)
{
    extern __shared__ float sm[];
    float* Qs = sm;
    float* Ks = sm + 64 * FST;
    float* Vs = sm + 2 * 64 * FST;
    float* Ss = sm + 3 * 64 * FST;
    float* mrow = sm + 4 * 64 * FST;
    float* lrow = mrow + 64;
    float* arow = lrow + 64;

    const int tid = threadIdx.x;
    const int lane = tid & 31, warp = tid >> 5;
    const int g = lane >> 2, t4 = lane & 3;
    const int wm = (warp >> 1) * 16, wn = (warp & 1) * 32;
    const int bh = blockIdx.y;
    const int b = bh / Hn, h = bh % Hn;
    const int t0 = blockIdx.x * 64;

    const int lr = tid >> 2, lc = (tid & 3) * 16;

    // load Q tile (tf32-rounded)
    const float* qb = q + (size_t)(b * Sn + t0) * DMn + h * Dn;
#pragma unroll
    for (int i = 0; i < 4; i++) {
        float4 f = *reinterpret_cast<const float4*>(qb + (size_t)lr * DMn + lc + i * 4);
        float* d = &Qs[lr * FST + lc + i * 4];
        d[0] = rtf(f.x); d[1] = rtf(f.y); d[2] = rtf(f.z); d[3] = rtf(f.w);
    }
    if (tid < 64) { mrow[tid] = -3e38f; lrow[tid] = 0.f; }

    float o[4][4];
#pragma unroll
    for (int ni = 0; ni < 4; ni++)
#pragma unroll
        for (int j = 0; j < 4; j++) o[ni][j] = 0.f;

    __syncthreads();

    for (int j0 = 0; j0 < Sn; j0 += 64) {
        // load K, V tiles (tf32-rounded)
        const float* kb = k + (size_t)(b * Sn + j0) * DMn + h * Dn;
        const float* vb = v + (size_t)(b * Sn + j0) * DMn + h * Dn;
#pragma unroll
        for (int i = 0; i < 4; i++) {
            float4 f = *reinterpret_cast<const float4*>(kb + (size_t)lr * DMn + lc + i * 4);
            float* d = &Ks[lr * FST + lc + i * 4];
            d[0] = rtf(f.x); d[1] = rtf(f.y); d[2] = rtf(f.z); d[3] = rtf(f.w);
            float4 f2 = *reinterpret_cast<const float4*>(vb + (size_t)lr * DMn + lc + i * 4);
            float* d2 = &Vs[lr * FST + lc + i * 4];
            d2[0] = rtf(f2.x); d2[1] = rtf(f2.y); d2[2] = rtf(f2.z); d2[3] = rtf(f2.w);
        }
        __syncthreads();

        // S = Q @ K^T
        float s[4][4];
#pragma unroll
        for (int ni = 0; ni < 4; ni++)
#pragma unroll
            for (int j = 0; j < 4; j++) s[ni][j] = 0.f;

#pragma unroll
        for (int ks = 0; ks < 8; ks++) {
            const int k0 = ks * 8;
            uint32_t a[4], bf[4][2];
            const float* ap = &Qs[(wm + g) * FST + k0 + t4];
            a[0] = __float_as_uint(ap[0]);
            a[1] = __float_as_uint(ap[8 * FST]);
            a[2] = __float_as_uint(ap[4]);
            a[3] = __float_as_uint(ap[8 * FST + 4]);
#pragma unroll
            for (int ni = 0; ni < 4; ni++) {
                const float* bp = &Ks[(wn + ni * 8 + g) * FST + k0 + t4];
                bf[ni][0] = __float_as_uint(bp[0]);
                bf[ni][1] = __float_as_uint(bp[4]);
            }
#pragma unroll
            for (int ni = 0; ni < 4; ni++) {
                float* c = s[ni];
                asm volatile(
                    "mma.sync.aligned.m16n8k8.row.col.f32.tf32.tf32.f32 "
                    "{%0,%1,%2,%3}, {%4,%5,%6,%7}, {%8,%9}, {%0,%1,%2,%3};"
                    : "+f"(c[0]), "+f"(c[1]), "+f"(c[2]), "+f"(c[3])
                    : "r"(a[0]), "r"(a[1]), "r"(a[2]), "r"(a[3]),
                      "r"(bf[ni][0]), "r"(bf[ni][1]));
            }
        }
        // scaled store to Ss
#pragma unroll
        for (int ni = 0; ni < 4; ni++) {
            *reinterpret_cast<float2*>(&Ss[(wm + g) * FST + wn + ni * 8 + 2 * t4]) =
                make_float2(s[ni][0] * 0.125f, s[ni][1] * 0.125f);
            *reinterpret_cast<float2*>(&Ss[(wm + g + 8) * FST + wn + ni * 8 + 2 * t4]) =
                make_float2(s[ni][2] * 0.125f, s[ni][3] * 0.125f);
        }
        __syncthreads();

        // online softmax (warp w handles rows 8w..8w+7; 4 lanes per row)
        {
            const int r = warp * 8 + (lane >> 2);
            float* srow = &Ss[r * FST + (lane & 3) * 16];
            float mx = -3e38f;
#pragma unroll
            for (int i = 0; i < 16; i++) mx = fmaxf(mx, srow[i]);
            mx = fmaxf(mx, __shfl_xor_sync(0xffffffffu, mx, 1));
            mx = fmaxf(mx, __shfl_xor_sync(0xffffffffu, mx, 2));
            const float mprev = mrow[r];
            const float mnew = fmaxf(mprev, mx);
            float sum = 0.f;
#pragma unroll
            for (int i = 0; i < 16; i++) {
                float p = rtf(__expf(srow[i] - mnew));
                srow[i] = p;
                sum += p;
            }
            sum += __shfl_xor_sync(0xffffffffu, sum, 1);
            sum += __shfl_xor_sync(0xffffffffu, sum, 2);
            if ((lane & 3) == 0) {
                const float al = __expf(mprev - mnew);
                arow[r] = al;
                lrow[r] = lrow[r] * al + sum;
                mrow[r] = mnew;
            }
        }
        __syncthreads();

        // O = O*alpha + P @ V
        const float al0 = arow[wm + g], al1 = arow[wm + g + 8];
#pragma unroll
        for (int ni = 0; ni < 4; ni++) {
            o[ni][0] *= al0; o[ni][1] *= al0;
            o[ni][2] *= al1; o[ni][3] *= al1;
        }
#pragma unroll
        for (int ks = 0; ks < 8; ks++) {
            const int k0 = ks * 8;
            uint32_t a[4], bf[4][2];
            const float* ap = &Ss[(wm + g) * FST + k0 + t4];
            a[0] = __float_as_uint(ap[0]);
            a[1] = __float_as_uint(ap[8 * FST]);
            a[2] = __float_as_uint(ap[4]);
            a[3] = __float_as_uint(ap[8 * FST + 4]);
#pragma unroll
            for (int ni = 0; ni < 4; ni++) {
                const float* bp = &Vs[(k0 + t4) * FST + wn + ni * 8 + g];
                bf[ni][0] = __float_as_uint(bp[0]);
                bf[ni][1] = __float_as_uint(bp[4 * FST]);
            }
#pragma unroll
            for (int ni = 0; ni < 4; ni++) {
                float* c = o[ni];
                asm volatile(
                    "mma.sync.aligned.m16n8k8.row.col.f32.tf32.tf32.f32 "
                    "{%0,%1,%2,%3}, {%4,%5,%6,%7}, {%8,%9}, {%0,%1,%2,%3};"
                    : "+f"(c[0]), "+f"(c[1]), "+f"(c[2]), "+f"(c[3])
                    : "r"(a[0]), "r"(a[1]), "r"(a[2]), "r"(a[3]),
                      "r"(bf[ni][0]), "r"(bf[ni][1]));
            }
        }
        __syncthreads();
    }

    // normalize and write (tf32-rounded; feeds O-proj A operand)
    const float il0 = 1.0f / lrow[wm + g];
    const float il1 = 1.0f / lrow[wm + g + 8];
    float* ob = out + (size_t)(b * Sn + t0) * DMn + h * Dn;
#pragma unroll
    for (int ni = 0; ni < 4; ni++) {
        const int col = wn + ni * 8 + 2 * t4;
        *reinterpret_cast<float2*>(&ob[(size_t)(wm + g) * DMn + col]) =
            make_float2(rtf(o[ni][0] * il0), rtf(o[ni][1] * il0));
        *reinterpret_cast<float2*>(&ob[(size_t)(wm + g + 8) * DMn + col]) =
            make_float2(rtf(o[ni][2] * il1), rtf(o[ni][3] * il1));
    }
}

#define FLASH_SMEM ((4 * 64 * FST + 3 * 64) * 4)

// ---------------- launch ------------------------------------------------------
extern "C" void kernel_launch(void* const* d_in, const int* in_sizes, int n_in,
                              void* d_out, int out_size)
{
    const float* x        = (const float*)d_in[0];
    const float* ln1_s    = (const float*)d_in[1];
    const float* ln1_o    = (const float*)d_in[2];
    const float* wq       = (const float*)d_in[3];
    const float* bq       = (const float*)d_in[4];
    const float* wk       = (const float*)d_in[5];
    const float* bk       = (const float*)d_in[6];
    const float* wv       = (const float*)d_in[7];
    const float* bv       = (const float*)d_in[8];
    const float* wo       = (const float*)d_in[9];
    const float* bo       = (const float*)d_in[10];
    const float* ln2_s    = (const float*)d_in[11];
    const float* ln2_o    = (const float*)d_in[12];
    const float* fc1_w    = (const float*)d_in[13];
    const float* fc1_b    = (const float*)d_in[14];
    const float* fc2_w    = (const float*)d_in[15];
    const float* fc2_b    = (const float*)d_in[16];
    float* out            = (float*)d_out;

    float *ph, *pq, *pk, *pv, *pattn, *px1, *pf1, *pwr;
    cudaGetSymbolAddress((void**)&ph,    g_h);
    cudaGetSymbolAddress((void**)&pq,    g_q);
    cudaGetSymbolAddress((void**)&pk,    g_k);
    cudaGetSymbolAddress((void**)&pv,    g_v);
    cudaGetSymbolAddress((void**)&pattn, g_attn);
    cudaGetSymbolAddress((void**)&px1,   g_x1);
    cudaGetSymbolAddress((void**)&pf1,   g_f1);
    cudaGetSymbolAddress((void**)&pwr,   g_wr);

    float* rwq  = pwr;
    float* rwk  = pwr + (size_t)WSZ_DM;
    float* rwv  = pwr + (size_t)2 * WSZ_DM;
    float* rwo  = pwr + (size_t)3 * WSZ_DM;
    float* rfc1 = pwr + (size_t)4 * WSZ_DM;
    float* rfc2 = pwr + (size_t)4 * WSZ_DM + WSZ_FC;

    static bool attr_done = false;
    if (!attr_done) {
        cudaFuncSetAttribute(flash_attn, cudaFuncAttributeMaxDynamicSharedMemorySize, FLASH_SMEM);
        attr_done = true;
    }

    // 0) pre-round weights to tf32
    round4_kernel<<<WSZ_DM / 4 / 256, 256>>>((const float4*)wq,    (float4*)rwq,  WSZ_DM / 4);
    round4_kernel<<<WSZ_DM / 4 / 256, 256>>>((const float4*)wk,    (float4*)rwk,  WSZ_DM / 4);
    round4_kernel<<<WSZ_DM / 4 / 256, 256>>>((const float4*)wv,    (float4*)rwv,  WSZ_DM / 4);
    round4_kernel<<<WSZ_DM / 4 / 256, 256>>>((const float4*)wo,    (float4*)rwo,  WSZ_DM / 4);
    round4_kernel<<<WSZ_FC / 4 / 256, 256>>>((const float4*)fc1_w, (float4*)rfc1, WSZ_FC / 4);
    round4_kernel<<<WSZ_FC / 4 / 256, 256>>>((const float4*)fc2_w, (float4*)rfc2, WSZ_FC / 4);

    // 1) LN1 (tf32-rounded output)
    ln_kernel<<<NTOK, 256>>>(x, ln1_s, ln1_o, ph);

    // 2) Q, K, V projections
    {
        dim3 grid(DMn / 128, NTOK / 128);
        gemm_tf32<0><<<grid, 256>>>(ph, rwq, bq, nullptr, pq, NTOK, DMn, DMn);
        gemm_tf32<0><<<grid, 256>>>(ph, rwk, bk, nullptr, pk, NTOK, DMn, DMn);
        gemm_tf32<0><<<grid, 256>>>(ph, rwv, bv, nullptr, pv, NTOK, DMn, DMn);
    }

    // 3) fused flash attention
    {
        dim3 grid(Sn / 64, NBH);
        flash_attn<<<grid, 256, FLASH_SMEM>>>(pq, pk, pv, pattn);
    }

    // 4) output projection + residual(x) -> x1
    {
        dim3 grid(DMn / 128, NTOK / 128);
        gemm_tf32<1><<<grid, 256>>>(pattn, rwo, bo, x, px1, NTOK, DMn, DMn);
    }

    // 5) LN2
    ln_kernel<<<NTOK, 256>>>(px1, ln2_s, ln2_o, ph);

    // 6) FC1 + exact GELU (tf32-rounded output)
    {
        dim3 grid(DFn / 128, NTOK / 128);
        gemm_tf32<2><<<grid, 256>>>(ph, rfc1, fc1_b, nullptr, pf1, NTOK, DFn, DMn);
    }

    // 7) FC2 + residual(x1) -> out
    {
        dim3 grid(DMn / 128, NTOK / 128);
        gemm_tf32<1><<<grid, 256>>>(pf1, rfc2, fc2_b, px1, out, NTOK, DMn, DFn);
    }
}

// round 4
// speedup vs baseline: 3.3330x; 1.0947x over previous
#include <cuda_runtime.h>
#include <math.h>
#include <stdint.h>

// Problem constants
#define Bn   4
#define Sn   1024
#define Hn   20
#define Dn   64
#define DMn  1280
#define DFn  5120
#define NTOK 4096           // Bn*Sn
#define NBH  80             // Bn*Hn
#define EPSLN 1e-5f

// ---------------- scratch (static device globals; no allocation) -------------
__device__ float g_h   [(size_t)NTOK * DMn];           // LN / plain activations
__device__ float g_hT  [(size_t)NTOK * DMn];           // fragment-major A (reused)
__device__ float g_q   [(size_t)NTOK * DMn];
__device__ float g_k   [(size_t)NTOK * DMn];
__device__ float g_v   [(size_t)NTOK * DMn];
__device__ float g_attn[(size_t)NTOK * DMn];
__device__ float g_x1  [(size_t)NTOK * DMn];           // residual 1
__device__ float g_f1  [(size_t)NTOK * DFn];           // FC1/GELU output (plain)
__device__ float g_f1T [(size_t)NTOK * DFn];           // fragment-major FC1 out
__device__ float g_wr  [19660800];                     // fragment-major weights

#define WSZ_DM (DMn * DMn)          // 1,638,400
#define WSZ_FC (DMn * DFn)          // 6,553,600

// ---------------- tf32 helpers ------------------------------------------------
__device__ __forceinline__ uint32_t f2tf(float f) {
    uint32_t u;
    asm("cvt.rna.tf32.f32 %0, %1;" : "=r"(u) : "f"(f));
    return u;
}
__device__ __forceinline__ float rtf(float f) { return __uint_as_float(f2tf(f)); }

// ---------------- operand transforms into fragment-major blocks ---------------
// A block (128m x 16k, 2048 floats):
//   element (m,k): mt=m>>4, h=(m>>3)&1, g=m&7, ks=k>>3, i2=(k>>2)&1, t4=k&3
//   idx = ((mt*2+ks)*32 + g*4 + t4)*4 + h + 2*i2
// Block order: At[(mb*(K/16) + kb)*2048 + idx]
__global__ void __launch_bounds__(256) atrans_kernel(const float* __restrict__ A,
                                                     float* __restrict__ At,
                                                     int M, int K)
{
    __shared__ float s[2048];
    const int kb = blockIdx.x, mb = blockIdx.y;
    const int KB = K >> 4;
    const int tid = threadIdx.x;
    const float* ab = A + (size_t)(mb * 128) * K + kb * 16;

#pragma unroll
    for (int e4 = tid; e4 < 512; e4 += 256) {
        const int m = e4 >> 2, kq = (e4 & 3) * 4;
        const float4 f = *reinterpret_cast<const float4*>(ab + (size_t)m * K + kq);
        const int mt = m >> 4, h = (m >> 3) & 1, g = m & 7;
        const float vv[4] = {f.x, f.y, f.z, f.w};
#pragma unroll
        for (int j = 0; j < 4; j++) {
            const int k = kq + j;
            const int ks = k >> 3, i2 = (k >> 2) & 1, t4 = k & 3;
            s[((mt * 2 + ks) * 32 + g * 4 + t4) * 4 + h + 2 * i2] = rtf(vv[j]);
        }
    }
    __syncthreads();
    float* ob = At + ((size_t)mb * KB + kb) * 2048;
#pragma unroll
    for (int e = tid * 4; e < 2048; e += 1024)
        *reinterpret_cast<float4*>(ob + e) = *reinterpret_cast<const float4*>(s + e);
}

// B block (16k x 128n, 2048 floats):
//   element (k,col): ks=k>>3, khalf=(k>>2)&1, t4=k&3, ni_g=col>>3, g=col&7
//   idx = ((ks*16+ni_g)*32 + g*4 + t4)*2 + khalf
// Block order: Bt[(kb*(N/128) + nb)*2048 + idx]
__global__ void __launch_bounds__(256) btrans_kernel(const float* __restrict__ B,
                                                     float* __restrict__ Bt,
                                                     int K, int N)
{
    __shared__ float s[2048];
    const int nb = blockIdx.x, kb = blockIdx.y;
    const int NB = N >> 7;
    const int tid = threadIdx.x;
    const float* bb = B + (size_t)(kb * 16) * N + nb * 128;

#pragma unroll
    for (int e4 = tid; e4 < 512; e4 += 256) {
        const int k = e4 >> 5, colq = (e4 & 31) * 4;
        const float4 f = *reinterpret_cast<const float4*>(bb + (size_t)k * N + colq);
        const int ks = k >> 3, khalf = (k >> 2) & 1, t4 = k & 3;
        const float vv[4] = {f.x, f.y, f.z, f.w};
#pragma unroll
        for (int j = 0; j < 4; j++) {
            const int col = colq + j;
            const int ni_g = col >> 3, g = col & 7;
            s[((ks * 16 + ni_g) * 32 + g * 4 + t4) * 2 + khalf] = rtf(vv[j]);
        }
    }
    __syncthreads();
    float* ob = Bt + ((size_t)kb * NB + nb) * 2048;
#pragma unroll
    for (int e = tid * 4; e < 2048; e += 1024)
        *reinterpret_cast<float4*>(ob + e) = *reinterpret_cast<const float4*>(s + e);
}

// ---------------- LayerNorm: one block per row ---------------------------------
__global__ void __launch_bounds__(256) ln_kernel(const float* __restrict__ x,
                                                 const float* __restrict__ sc,
                                                 const float* __restrict__ off,
                                                 float* __restrict__ y)
{
    const int row = blockIdx.x;
    const float* xr = x + (size_t)row * DMn;
    float* yr = y + (size_t)row * DMn;
    const int t = threadIdx.x;
    const int lane = t & 31, wid = t >> 5;

    __shared__ float sh[32];
    __shared__ float s_mean, s_rstd;

    float vals[5];
    float s = 0.f;
#pragma unroll
    for (int i = 0; i < 5; i++) { vals[i] = xr[t + i * 256]; s += vals[i]; }
#pragma unroll
    for (int o = 16; o; o >>= 1) s += __shfl_xor_sync(0xffffffffu, s, o);
    if (lane == 0) sh[wid] = s;
    __syncthreads();
    if (wid == 0) {
        float v = (lane < 8) ? sh[lane] : 0.f;
#pragma unroll
        for (int o = 4; o; o >>= 1) v += __shfl_xor_sync(0xffffffffu, v, o);
        if (lane == 0) s_mean = v * (1.0f / DMn);
    }
    __syncthreads();
    const float mean = s_mean;
    __syncthreads();

    float vs = 0.f;
#pragma unroll
    for (int i = 0; i < 5; i++) { float d = vals[i] - mean; vs += d * d; }
#pragma unroll
    for (int o = 16; o; o >>= 1) vs += __shfl_xor_sync(0xffffffffu, vs, o);
    if (lane == 0) sh[wid] = vs;
    __syncthreads();
    if (wid == 0) {
        float v = (lane < 8) ? sh[lane] : 0.f;
#pragma unroll
        for (int o = 4; o; o >>= 1) v += __shfl_xor_sync(0xffffffffu, v, o);
        if (lane == 0) s_rstd = rsqrtf(v * (1.0f / DMn) + EPSLN);
    }
    __syncthreads();
    const float rstd = s_rstd;

#pragma unroll
    for (int i = 0; i < 5; i++) {
        int c = t + i * 256;
        yr[c] = (vals[i] - mean) * rstd * sc[c] + off[c];
    }
}

// ---------------- TF32 tensor-core GEMM, fragment-major operands -------------
// C[M,N] = A @ B + bias ; EPI: 0=bias, 1=bias+res, 2=bias+gelu(exact)
// At/Bt are fragment-major block layouts produced by atrans/btrans.
__device__ __forceinline__ float gelu_exact(float v) {
    return 0.5f * v * (1.0f + erff(v * 0.70710678118654752f));
}

__device__ __forceinline__ void cp16(void* smem_dst, const void* gsrc) {
    uint32_t s = (uint32_t)__cvta_generic_to_shared(smem_dst);
    asm volatile("cp.async.cg.shared.global [%0], [%1], 16;" :: "r"(s), "l"(gsrc));
}

template <int EPI>
__global__ void __launch_bounds__(256, 2) gemm_ft(const float* __restrict__ At,
                                                  const float* __restrict__ Bt,
                                                  const float* __restrict__ bias,
                                                  const float* __restrict__ res,
                                                  float* __restrict__ C,
                                                  int M, int N, int K)
{
    __shared__ float As[3][2048];
    __shared__ float Bs[3][2048];

    const int tid = threadIdx.x;
    const int nb = blockIdx.x, mb = blockIdx.y;
    const int KB = K >> 4, NB = N >> 7;
    const int lane = tid & 31, warp = tid >> 5;
    const int wmBase = (warp >> 2) * 4;   // m-tile base (16-row tiles)
    const int wnBase = (warp & 3) * 4;    // n-tile base (8-col tiles)
    const int g = lane >> 2, t4 = lane & 3;

    const float* aBase = At + (size_t)mb * KB * 2048;
    const float* bBase = Bt + (size_t)nb * 2048;

    float acc[16][4];
#pragma unroll
    for (int i = 0; i < 16; i++)
#pragma unroll
        for (int j = 0; j < 4; j++) acc[i][j] = 0.f;

    auto issue = [&](int s, int kb) {
        const float* ab = aBase + (size_t)kb * 2048;
        const float* bb = bBase + (size_t)kb * NB * 2048;
        cp16(&As[s][tid * 4],        ab + tid * 4);
        cp16(&As[s][1024 + tid * 4], ab + 1024 + tid * 4);
        cp16(&Bs[s][tid * 4],        bb + tid * 4);
        cp16(&Bs[s][1024 + tid * 4], bb + 1024 + tid * 4);
        asm volatile("cp.async.commit_group;" ::: "memory");
    };

    issue(0, 0);
    issue(1, 1);

    for (int kb = 0; kb < KB; kb++) {
        const int s = kb % 3;
        asm volatile("cp.async.wait_group 1;" ::: "memory");
        __syncthreads();
        if (kb + 2 < KB) issue((kb + 2) % 3, kb + 2);

#pragma unroll
        for (int ks = 0; ks < 2; ks++) {
            uint32_t a[4][4], b[4][2];
#pragma unroll
            for (int mi = 0; mi < 4; mi++) {
                const float4 fa = *reinterpret_cast<const float4*>(
                    &As[s][(((wmBase + mi) * 2 + ks) * 32 + lane) * 4]);
                a[mi][0] = __float_as_uint(fa.x);
                a[mi][1] = __float_as_uint(fa.y);
                a[mi][2] = __float_as_uint(fa.z);
                a[mi][3] = __float_as_uint(fa.w);
            }
#pragma unroll
            for (int ni = 0; ni < 4; ni++) {
                const float2 fb = *reinterpret_cast<const float2*>(
                    &Bs[s][((ks * 16 + wnBase + ni) * 32 + lane) * 2]);
                b[ni][0] = __float_as_uint(fb.x);
                b[ni][1] = __float_as_uint(fb.y);
            }
#pragma unroll
            for (int mi = 0; mi < 4; mi++)
#pragma unroll
                for (int ni = 0; ni < 4; ni++) {
                    float* c = acc[mi * 4 + ni];
                    asm volatile(
                        "mma.sync.aligned.m16n8k8.row.col.f32.tf32.tf32.f32 "
                        "{%0,%1,%2,%3}, {%4,%5,%6,%7}, {%8,%9}, {%0,%1,%2,%3};"
                        : "+f"(c[0]), "+f"(c[1]), "+f"(c[2]), "+f"(c[3])
                        : "r"(a[mi][0]), "r"(a[mi][1]), "r"(a[mi][2]), "r"(a[mi][3]),
                          "r"(b[ni][0]), "r"(b[ni][1]));
                }
        }
    }

    // epilogue
    const int rowBase = mb * 128;
    const int colBase = nb * 128;
    const int wm = (warp >> 2) * 64;
    const int wn = (warp & 3) * 32;
#pragma unroll
    for (int mi = 0; mi < 4; mi++) {
#pragma unroll
        for (int ni = 0; ni < 4; ni++) {
            float* c = acc[mi * 4 + ni];
            const int col = colBase + wn + ni * 8 + t4 * 2;
            const float2 bb = *reinterpret_cast<const float2*>(bias + col);
#pragma unroll
            for (int h = 0; h < 2; h++) {
                const int row = rowBase + wm + mi * 16 + g + h * 8;
                float o0 = c[h * 2 + 0] + bb.x;
                float o1 = c[h * 2 + 1] + bb.y;
                if (EPI == 1) {
                    const float2 r2 = *reinterpret_cast<const float2*>(res + (size_t)row * N + col);
                    o0 += r2.x; o1 += r2.y;
                }
                if (EPI == 2) {
                    o0 = gelu_exact(o0);
                    o1 = gelu_exact(o1);
                }
                *reinterpret_cast<float2*>(C + (size_t)row * N + col) = make_float2(o0, o1);
            }
        }
    }
}

// ---------------- fused flash attention (tf32 mma, online softmax) -----------
#define FST 68
__global__ void __launch_bounds__(256) flash_attn(const float* __restrict__ q,
                                                  const float* __restrict__ k,
                                                  const float* __restrict__ v,
                                                  float* __restrict__ out)
{
    extern __shared__ float sm[];
    float* Qs = sm;
    float* Ks = sm + 64 * FST;
    float* Vs = sm + 2 * 64 * FST;
    float* Ss = sm + 3 * 64 * FST;
    float* mrow = sm + 4 * 64 * FST;
    float* lrow = mrow + 64;
    float* arow = lrow + 64;

    const int tid = threadIdx.x;
    const int lane = tid & 31, warp = tid >> 5;
    const int g = lane >> 2, t4 = lane & 3;
    const int wm = (warp >> 1) * 16, wn = (warp & 1) * 32;
    const int bh = blockIdx.y;
    const int b = bh / Hn, h = bh % Hn;
    const int t0 = blockIdx.x * 64;

    const int lr = tid >> 2, lc = (tid & 3) * 16;

    const float* qb = q + (size_t)(b * Sn + t0) * DMn + h * Dn;
#pragma unroll
    for (int i = 0; i < 4; i++) {
        float4 f = *reinterpret_cast<const float4*>(qb + (size_t)lr * DMn + lc + i * 4);
        float* d = &Qs[lr * FST + lc + i * 4];
        d[0] = rtf(f.x); d[1] = rtf(f.y); d[2] = rtf(f.z); d[3] = rtf(f.w);
    }
    if (tid < 64) { mrow[tid] = -3e38f; lrow[tid] = 0.f; }

    float o[4][4];
#pragma unroll
    for (int ni = 0; ni < 4; ni++)
#pragma unroll
        for (int j = 0; j < 4; j++) o[ni][j] = 0.f;

    __syncthreads();

    for (int j0 = 0; j0 < Sn; j0 += 64) {
        const float* kb = k + (size_t)(b * Sn + j0) * DMn + h * Dn;
        const float* vb = v + (size_t)(b * Sn + j0) * DMn + h * Dn;
#pragma unroll
        for (int i = 0; i < 4; i++) {
            float4 f = *reinterpret_cast<const float4*>(kb + (size_t)lr * DMn + lc + i * 4);
            float* d = &Ks[lr * FST + lc + i * 4];
            d[0] = rtf(f.x); d[1] = rtf(f.y); d[2] = rtf(f.z); d[3] = rtf(f.w);
            float4 f2 = *reinterpret_cast<const float4*>(vb + (size_t)lr * DMn + lc + i * 4);
            float* d2 = &Vs[lr * FST + lc + i * 4];
            d2[0] = rtf(f2.x); d2[1] = rtf(f2.y); d2[2] = rtf(f2.z); d2[3] = rtf(f2.w);
        }
        __syncthreads();

        float s[4][4];
#pragma unroll
        for (int ni = 0; ni < 4; ni++)
#pragma unroll
            for (int j = 0; j < 4; j++) s[ni][j] = 0.f;

#pragma unroll
        for (int ks = 0; ks < 8; ks++) {
            const int k0 = ks * 8;
            uint32_t a[4], bf[4][2];
            const float* ap = &Qs[(wm + g) * FST + k0 + t4];
            a[0] = __float_as_uint(ap[0]);
            a[1] = __float_as_uint(ap[8 * FST]);
            a[2] = __float_as_uint(ap[4]);
            a[3] = __float_as_uint(ap[8 * FST + 4]);
#pragma unroll
            for (int ni = 0; ni < 4; ni++) {
                const float* bp = &Ks[(wn + ni * 8 + g) * FST + k0 + t4];
                bf[ni][0] = __float_as_uint(bp[0]);
                bf[ni][1] = __float_as_uint(bp[4]);
            }
#pragma unroll
            for (int ni = 0; ni < 4; ni++) {
                float* c = s[ni];
                asm volatile(
                    "mma.sync.aligned.m16n8k8.row.col.f32.tf32.tf32.f32 "
                    "{%0,%1,%2,%3}, {%4,%5,%6,%7}, {%8,%9}, {%0,%1,%2,%3};"
                    : "+f"(c[0]), "+f"(c[1]), "+f"(c[2]), "+f"(c[3])
                    : "r"(a[0]), "r"(a[1]), "r"(a[2]), "r"(a[3]),
                      "r"(bf[ni][0]), "r"(bf[ni][1]));
            }
        }
#pragma unroll
        for (int ni = 0; ni < 4; ni++) {
            *reinterpret_cast<float2*>(&Ss[(wm + g) * FST + wn + ni * 8 + 2 * t4]) =
                make_float2(s[ni][0] * 0.125f, s[ni][1] * 0.125f);
            *reinterpret_cast<float2*>(&Ss[(wm + g + 8) * FST + wn + ni * 8 + 2 * t4]) =
                make_float2(s[ni][2] * 0.125f, s[ni][3] * 0.125f);
        }
        __syncthreads();

        {
            const int r = warp * 8 + (lane >> 2);
            float* srow = &Ss[r * FST + (lane & 3) * 16];
            float mx = -3e38f;
#pragma unroll
            for (int i = 0; i < 16; i++) mx = fmaxf(mx, srow[i]);
            mx = fmaxf(mx, __shfl_xor_sync(0xffffffffu, mx, 1));
            mx = fmaxf(mx, __shfl_xor_sync(0xffffffffu, mx, 2));
            const float mprev = mrow[r];
            const float mnew = fmaxf(mprev, mx);
            float sum = 0.f;
#pragma unroll
            for (int i = 0; i < 16; i++) {
                float p = rtf(__expf(srow[i] - mnew));
                srow[i] = p;
                sum += p;
            }
            sum += __shfl_xor_sync(0xffffffffu, sum, 1);
            sum += __shfl_xor_sync(0xffffffffu, sum, 2);
            if ((lane & 3) == 0) {
                const float al = __expf(mprev - mnew);
                arow[r] = al;
                lrow[r] = lrow[r] * al + sum;
                mrow[r] = mnew;
            }
        }
        __syncthreads();

        const float al0 = arow[wm + g], al1 = arow[wm + g + 8];
#pragma unroll
        for (int ni = 0; ni < 4; ni++) {
            o[ni][0] *= al0; o[ni][1] *= al0;
            o[ni][2] *= al1; o[ni][3] *= al1;
        }
#pragma unroll
        for (int ks = 0; ks < 8; ks++) {
            const int k0 = ks * 8;
            uint32_t a[4], bf[4][2];
            const float* ap = &Ss[(wm + g) * FST + k0 + t4];
            a[0] = __float_as_uint(ap[0]);
            a[1] = __float_as_uint(ap[8 * FST]);
            a[2] = __float_as_uint(ap[4]);
            a[3] = __float_as_uint(ap[8 * FST + 4]);
#pragma unroll
            for (int ni = 0; ni < 4; ni++) {
                const float* bp = &Vs[(k0 + t4) * FST + wn + ni * 8 + g];
                bf[ni][0] = __float_as_uint(bp[0]);
                bf[ni][1] = __float_as_uint(bp[4 * FST]);
            }
#pragma unroll
            for (int ni = 0; ni < 4; ni++) {
                float* c = o[ni];
                asm volatile(
                    "mma.sync.aligned.m16n8k8.row.col.f32.tf32.tf32.f32 "
                    "{%0,%1,%2,%3}, {%4,%5,%6,%7}, {%8,%9}, {%0,%1,%2,%3};"
                    : "+f"(c[0]), "+f"(c[1]), "+f"(c[2]), "+f"(c[3])
                    : "r"(a[0]), "r"(a[1]), "r"(a[2]), "r"(a[3]),
                      "r"(bf[ni][0]), "r"(bf[ni][1]));
            }
        }
        __syncthreads();
    }

    const float il0 = 1.0f / lrow[wm + g];
    const float il1 = 1.0f / lrow[wm + g + 8];
    float* ob = out + (size_t)(b * Sn + t0) * DMn + h * Dn;
#pragma unroll
    for (int ni = 0; ni < 4; ni++) {
        const int col = wn + ni * 8 + 2 * t4;
        *reinterpret_cast<float2*>(&ob[(size_t)(wm + g) * DMn + col]) =
            make_float2(o[ni][0] * il0, o[ni][1] * il0);
        *reinterpret_cast<float2*>(&ob[(size_t)(wm + g + 8) * DMn + col]) =
            make_float2(o[ni][2] * il1, o[ni][3] * il1);
    }
}

#define FLASH_SMEM ((4 * 64 * FST + 3 * 64) * 4)

// ---------------- launch ------------------------------------------------------
extern "C" void kernel_launch(void* const* d_in, const int* in_sizes, int n_in,
                              void* d_out, int out_size)
{
    const float* x        = (const float*)d_in[0];
    const float* ln1_s    = (const float*)d_in[1];
    const float* ln1_o    = (const float*)d_in[2];
    const float* wq       = (const float*)d_in[3];
    const float* bq       = (const float*)d_in[4];
    const float* wk       = (const float*)d_in[5];
    const float* bk       = (const float*)d_in[6];
    const float* wv       = (const float*)d_in[7];
    const float* bv       = (const float*)d_in[8];
    const float* wo       = (const float*)d_in[9];
    const float* bo       = (const float*)d_in[10];
    const float* ln2_s    = (const float*)d_in[11];
    const float* ln2_o    = (const float*)d_in[12];
    const float* fc1_w    = (const float*)d_in[13];
    const float* fc1_b    = (const float*)d_in[14];
    const float* fc2_w    = (const float*)d_in[15];
    const float* fc2_b    = (const float*)d_in[16];
    float* out            = (float*)d_out;

    float *ph, *phT, *pq, *pk, *pv, *pattn, *px1, *pf1, *pf1T, *pwr;
    cudaGetSymbolAddress((void**)&ph,    g_h);
    cudaGetSymbolAddress((void**)&phT,   g_hT);
    cudaGetSymbolAddress((void**)&pq,    g_q);
    cudaGetSymbolAddress((void**)&pk,    g_k);
    cudaGetSymbolAddress((void**)&pv,    g_v);
    cudaGetSymbolAddress((void**)&pattn, g_attn);
    cudaGetSymbolAddress((void**)&px1,   g_x1);
    cudaGetSymbolAddress((void**)&pf1,   g_f1);
    cudaGetSymbolAddress((void**)&pf1T,  g_f1T);
    cudaGetSymbolAddress((void**)&pwr,   g_wr);

    float* rwq  = pwr;
    float* rwk  = pwr + (size_t)WSZ_DM;
    float* rwv  = pwr + (size_t)2 * WSZ_DM;
    float* rwo  = pwr + (size_t)3 * WSZ_DM;
    float* rfc1 = pwr + (size_t)4 * WSZ_DM;
    float* rfc2 = pwr + (size_t)4 * WSZ_DM + WSZ_FC;

    static bool attr_done = false;
    if (!attr_done) {
        cudaFuncSetAttribute(flash_attn, cudaFuncAttributeMaxDynamicSharedMemorySize, FLASH_SMEM);
        attr_done = true;
    }

    // 0) weight transforms (tf32 round + fragment-major)
    {
        dim3 gdm(DMn / 128, DMn / 16);       // (10, 80)
        btrans_kernel<<<gdm, 256>>>(wq, rwq, DMn, DMn);
        btrans_kernel<<<gdm, 256>>>(wk, rwk, DMn, DMn);
        btrans_kernel<<<gdm, 256>>>(wv, rwv, DMn, DMn);
        btrans_kernel<<<gdm, 256>>>(wo, rwo, DMn, DMn);
        dim3 gf1(DFn / 128, DMn / 16);       // (40, 80)
        btrans_kernel<<<gf1, 256>>>(fc1_w, rfc1, DMn, DFn);
        dim3 gf2(DMn / 128, DFn / 16);       // (10, 320)
        btrans_kernel<<<gf2, 256>>>(fc2_w, rfc2, DFn, DMn);
    }

    // 1) LN1 -> h, transform -> hT
    ln_kernel<<<NTOK, 256>>>(x, ln1_s, ln1_o, ph);
    {
        dim3 ga(DMn / 16, NTOK / 128);       // (80, 32)
        atrans_kernel<<<ga, 256>>>(ph, phT, NTOK, DMn);
    }

    // 2) Q, K, V projections
    {
        dim3 grid(DMn / 128, NTOK / 128);
        gemm_ft<0><<<grid, 256>>>(phT, rwq, bq, nullptr, pq, NTOK, DMn, DMn);
        gemm_ft<0><<<grid, 256>>>(phT, rwk, bk, nullptr, pk, NTOK, DMn, DMn);
        gemm_ft<0><<<grid, 256>>>(phT, rwv, bv, nullptr, pv, NTOK, DMn, DMn);
    }

    // 3) fused flash attention
    {
        dim3 grid(Sn / 64, NBH);
        flash_attn<<<grid, 256, FLASH_SMEM>>>(pq, pk, pv, pattn);
    }

    // 4) transform attn, O-proj + residual(x) -> x1
    {
        dim3 ga(DMn / 16, NTOK / 128);
        atrans_kernel<<<ga, 256>>>(pattn, phT, NTOK, DMn);
        dim3 grid(DMn / 128, NTOK / 128);
        gemm_ft<1><<<grid, 256>>>(phT, rwo, bo, x, px1, NTOK, DMn, DMn);
    }

    // 5) LN2 -> h, transform -> hT
    ln_kernel<<<NTOK, 256>>>(px1, ln2_s, ln2_o, ph);
    {
        dim3 ga(DMn / 16, NTOK / 128);
        atrans_kernel<<<ga, 256>>>(ph, phT, NTOK, DMn);
    }

    // 6) FC1 + exact GELU
    {
        dim3 grid(DFn / 128, NTOK / 128);
        gemm_ft<2><<<grid, 256>>>(phT, rfc1, fc1_b, nullptr, pf1, NTOK, DFn, DMn);
    }

    // 7) transform f1, FC2 + residual(x1) -> out
    {
        dim3 ga(DFn / 16, NTOK / 128);       // (320, 32)
        atrans_kernel<<<ga, 256>>>(pf1, pf1T, NTOK, DFn);
        dim3 grid(DMn / 128, NTOK / 128);
        gemm_ft<1><<<grid, 256>>>(pf1T, rfc2, fc2_b, px1, out, NTOK, DMn, DFn);
    }
}

// round 5
// speedup vs baseline: 5.2923x; 1.5879x over previous
#include <cuda_runtime.h>
#include <cuda_fp16.h>
#include <math.h>
#include <stdint.h>

// Problem constants
#define Bn   4
#define Sn   1024
#define Hn   20
#define Dn   64
#define DMn  1280
#define DFn  5120
#define NTOK 4096           // Bn*Sn
#define NBH  80             // Bn*Hn
#define EPSLN 1e-5f
#define QKVLD 3840          // row stride of fused qkv output

// ---------------- scratch (static device globals; no allocation) -------------
__device__ float  g_h   [(size_t)NTOK * DMn];          // LN / plain activations
__device__ __half g_hT  [(size_t)NTOK * DMn];          // fragment-major A (fp16)
__device__ float  g_qkv [(size_t)NTOK * QKVLD];        // fused q|k|v
__device__ float  g_attn[(size_t)NTOK * DMn];
__device__ float  g_x1  [(size_t)NTOK * DMn];          // residual 1
__device__ float  g_f1  [(size_t)NTOK * DFn];          // FC1/GELU output (plain)
__device__ __half g_f1T [(size_t)NTOK * DFn];          // fragment-major FC1 out
__device__ __half g_wr  [19660800];                    // fragment-major weights (fp16)
__device__ float  g_bqkv[QKVLD];                       // concat bias

#define WSZ_DM (DMn * DMn)          // 1,638,400
#define WSZ_FC (DMn * DFn)          // 6,553,600

// ---------------- operand transforms into fp16 fragment-major blocks ----------
// A block (128m x 16k): for m-tile mt(0..7), lane(g,t4): 8 halves at (mt*32+lane)*8
//   [ (g,2t4),(g,2t4+1), (g+8,2t4),(g+8,2t4+1), (g,2t4+8),(g,2t4+9), (g+8,2t4+8),(g+8,2t4+9) ]
__global__ void __launch_bounds__(256) atrans_h(const float* __restrict__ A,
                                                __half* __restrict__ At,
                                                int M, int K)
{
    __shared__ __half s[2048];
    const int kb = blockIdx.x, mb = blockIdx.y;
    const int KB = K >> 4;
    const int tid = threadIdx.x;
    const float* ab = A + (size_t)(mb * 128) * K + kb * 16;

#pragma unroll
    for (int e4 = tid; e4 < 512; e4 += 256) {
        const int m = e4 >> 2, kq = (e4 & 3) * 4;
        const float4 f = *reinterpret_cast<const float4*>(ab + (size_t)m * K + kq);
        const int mt = m >> 4, hh = (m >> 3) & 1, gg = m & 7;
        const float vv[4] = {f.x, f.y, f.z, f.w};
#pragma unroll
        for (int j = 0; j < 4; j++) {
            const int k = kq + j;
            const int t4 = (k >> 1) & 3, khi = k >> 3, klo = k & 1;
            s[(mt * 32 + gg * 4 + t4) * 8 + khi * 4 + hh * 2 + klo] = __float2half_rn(vv[j]);
        }
    }
    __syncthreads();
    __half* ob = At + ((size_t)mb * KB + kb) * 2048;
    *reinterpret_cast<uint4*>(ob + tid * 8) = *reinterpret_cast<const uint4*>(s + tid * 8);
}

// B block (16k x 128n): for n-tile ni(0..15), lane(g,t4): 4 halves at (ni*32+lane)*4
//   [ (2t4,g),(2t4+1,g), (2t4+8,g),(2t4+9,g) ]   (col = ni*8+g)
__global__ void __launch_bounds__(256) btrans_h(const float* __restrict__ B,
                                                __half* __restrict__ Bt,
                                                int K, int N, int NBtot, int nbOff)
{
    __shared__ __half s[2048];
    const int nb = blockIdx.x, kb = blockIdx.y;
    const int tid = threadIdx.x;
    const float* bb = B + (size_t)(kb * 16) * N + nb * 128;

#pragma unroll
    for (int e4 = tid; e4 < 512; e4 += 256) {
        const int k = e4 >> 5, colq = (e4 & 31) * 4;
        const float4 f = *reinterpret_cast<const float4*>(bb + (size_t)k * N + colq);
        const int t4 = (k >> 1) & 3, khi = (k >> 3) & 1, klo = k & 1;
        const float vv[4] = {f.x, f.y, f.z, f.w};
#pragma unroll
        for (int j = 0; j < 4; j++) {
            const int col = colq + j;
            const int ni = col >> 3, gg = col & 7;
            s[(ni * 32 + gg * 4 + t4) * 4 + khi * 2 + klo] = __float2half_rn(vv[j]);
        }
    }
    __syncthreads();
    __half* ob = Bt + ((size_t)kb * NBtot + nbOff + nb) * 2048;
    *reinterpret_cast<uint4*>(ob + tid * 8) = *reinterpret_cast<const uint4*>(s + tid * 8);
}

// ---------------- bias concat for fused QKV -----------------------------------
__global__ void __launch_bounds__(256) bias_concat(const float* __restrict__ bq,
                                                   const float* __restrict__ bk,
                                                   const float* __restrict__ bv,
                                                   float* __restrict__ o)
{
    const int i = blockIdx.x * 256 + threadIdx.x;
    if (i < DMn) o[i] = bq[i];
    else if (i < 2 * DMn) o[i] = bk[i - DMn];
    else if (i < 3 * DMn) o[i] = bv[i - 2 * DMn];
}

// ---------------- LayerNorm: one block per row ---------------------------------
__global__ void __launch_bounds__(256) ln_kernel(const float* __restrict__ x,
                                                 const float* __restrict__ sc,
                                                 const float* __restrict__ off,
                                                 float* __restrict__ y)
{
    const int row = blockIdx.x;
    const float* xr = x + (size_t)row * DMn;
    float* yr = y + (size_t)row * DMn;
    const int t = threadIdx.x;
    const int lane = t & 31, wid = t >> 5;

    __shared__ float sh[32];
    __shared__ float s_mean, s_rstd;

    float vals[5];
    float s = 0.f;
#pragma unroll
    for (int i = 0; i < 5; i++) { vals[i] = xr[t + i * 256]; s += vals[i]; }
#pragma unroll
    for (int o = 16; o; o >>= 1) s += __shfl_xor_sync(0xffffffffu, s, o);
    if (lane == 0) sh[wid] = s;
    __syncthreads();
    if (wid == 0) {
        float v = (lane < 8) ? sh[lane] : 0.f;
#pragma unroll
        for (int o = 4; o; o >>= 1) v += __shfl_xor_sync(0xffffffffu, v, o);
        if (lane == 0) s_mean = v * (1.0f / DMn);
    }
    __syncthreads();
    const float mean = s_mean;
    __syncthreads();

    float vs = 0.f;
#pragma unroll
    for (int i = 0; i < 5; i++) { float d = vals[i] - mean; vs += d * d; }
#pragma unroll
    for (int o = 16; o; o >>= 1) vs += __shfl_xor_sync(0xffffffffu, vs, o);
    if (lane == 0) sh[wid] = vs;
    __syncthreads();
    if (wid == 0) {
        float v = (lane < 8) ? sh[lane] : 0.f;
#pragma unroll
        for (int o = 4; o; o >>= 1) v += __shfl_xor_sync(0xffffffffu, v, o);
        if (lane == 0) s_rstd = rsqrtf(v * (1.0f / DMn) + EPSLN);
    }
    __syncthreads();
    const float rstd = s_rstd;

#pragma unroll
    for (int i = 0; i < 5; i++) {
        int c = t + i * 256;
        yr[c] = (vals[i] - mean) * rstd * sc[c] + off[c];
    }
}

// ---------------- FP16 tensor-core GEMM, fragment-major operands -------------
// C[M,N] = A @ B + bias ; EPI: 0=bias, 1=bias+res, 2=bias+gelu(exact)
__device__ __forceinline__ float gelu_exact(float v) {
    return 0.5f * v * (1.0f + erff(v * 0.70710678118654752f));
}

__device__ __forceinline__ void cp16(void* smem_dst, const void* gsrc) {
    uint32_t s = (uint32_t)__cvta_generic_to_shared(smem_dst);
    asm volatile("cp.async.cg.shared.global [%0], [%1], 16;" :: "r"(s), "l"(gsrc));
}

template <int EPI>
__global__ void __launch_bounds__(256, 2) gemm_h(const __half* __restrict__ At,
                                                 const __half* __restrict__ Bt,
                                                 const float* __restrict__ bias,
                                                 const float* __restrict__ res,
                                                 float* __restrict__ C,
                                                 int M, int N, int K)
{
    __shared__ __align__(16) __half As[3][4096];   // 2 sub-blocks of 16k each
    __shared__ __align__(16) __half Bs[3][4096];

    const int tid = threadIdx.x;
    const int nb = blockIdx.x, mb = blockIdx.y;
    const int KB = K >> 5;       // 32-k iterations
    const int KB16 = K >> 4;
    const int NB = N >> 7;
    const int lane = tid & 31, warp = tid >> 5;
    const int wmBase = (warp >> 2) * 4;   // m-tile base (16-row tiles)
    const int wnBase = (warp & 3) * 4;    // n-tile base (8-col tiles)
    const int g = lane >> 2, t4 = lane & 3;

    const __half* aBase = At + (size_t)mb * KB16 * 2048;
    const __half* bBase = Bt + (size_t)nb * 2048;

    float acc[16][4];
#pragma unroll
    for (int i = 0; i < 16; i++)
#pragma unroll
        for (int j = 0; j < 4; j++) acc[i][j] = 0.f;

    auto issue = [&](int s, int kb) {
        const __half* ab  = aBase + (size_t)kb * 4096;                 // contiguous in kb16
        const __half* bb0 = bBase + (size_t)(kb * 2) * NB * 2048;
        const __half* bb1 = bBase + (size_t)(kb * 2 + 1) * NB * 2048;
        cp16(&As[s][tid * 8],        ab + tid * 8);
        cp16(&As[s][2048 + tid * 8], ab + 2048 + tid * 8);
        cp16(&Bs[s][tid * 8],        bb0 + tid * 8);
        cp16(&Bs[s][2048 + tid * 8], bb1 + tid * 8);
        asm volatile("cp.async.commit_group;" ::: "memory");
    };

    issue(0, 0);
    issue(1, 1);

    for (int kb = 0; kb < KB; kb++) {
        const int s = kb % 3;
        asm volatile("cp.async.wait_group 1;" ::: "memory");
        __syncthreads();
        if (kb + 2 < KB) issue((kb + 2) % 3, kb + 2);

#pragma unroll
        for (int kk = 0; kk < 2; kk++) {
            uint32_t a[4][4], b[4][2];
#pragma unroll
            for (int mi = 0; mi < 4; mi++) {
                const uint4 fa = *reinterpret_cast<const uint4*>(
                    &As[s][kk * 2048 + ((wmBase + mi) * 32 + lane) * 8]);
                a[mi][0] = fa.x; a[mi][1] = fa.y; a[mi][2] = fa.z; a[mi][3] = fa.w;
            }
#pragma unroll
            for (int ni = 0; ni < 4; ni++) {
                const uint2 fb = *reinterpret_cast<const uint2*>(
                    &Bs[s][kk * 2048 + ((wnBase + ni) * 32 + lane) * 4]);
                b[ni][0] = fb.x; b[ni][1] = fb.y;
            }
#pragma unroll
            for (int mi = 0; mi < 4; mi++)
#pragma unroll
                for (int ni = 0; ni < 4; ni++) {
                    float* c = acc[mi * 4 + ni];
                    asm volatile(
                        "mma.sync.aligned.m16n8k16.row.col.f32.f16.f16.f32 "
                        "{%0,%1,%2,%3}, {%4,%5,%6,%7}, {%8,%9}, {%0,%1,%2,%3};"
                        : "+f"(c[0]), "+f"(c[1]), "+f"(c[2]), "+f"(c[3])
                        : "r"(a[mi][0]), "r"(a[mi][1]), "r"(a[mi][2]), "r"(a[mi][3]),
                          "r"(b[ni][0]), "r"(b[ni][1]));
                }
        }
    }

    // epilogue
    const int rowBase = mb * 128;
    const int colBase = nb * 128;
    const int wm = (warp >> 2) * 64;
    const int wn = (warp & 3) * 32;
#pragma unroll
    for (int mi = 0; mi < 4; mi++) {
#pragma unroll
        for (int ni = 0; ni < 4; ni++) {
            float* c = acc[mi * 4 + ni];
            const int col = colBase + wn + ni * 8 + t4 * 2;
            const float2 bb = *reinterpret_cast<const float2*>(bias + col);
#pragma unroll
            for (int h = 0; h < 2; h++) {
                const int row = rowBase + wm + mi * 16 + g + h * 8;
                float o0 = c[h * 2 + 0] + bb.x;
                float o1 = c[h * 2 + 1] + bb.y;
                if (EPI == 1) {
                    const float2 r2 = *reinterpret_cast<const float2*>(res + (size_t)row * N + col);
                    o0 += r2.x; o1 += r2.y;
                }
                if (EPI == 2) {
                    o0 = gelu_exact(o0);
                    o1 = gelu_exact(o1);
                }
                *reinterpret_cast<float2*>(C + (size_t)row * N + col) = make_float2(o0, o1);
            }
        }
    }
}

// ---------------- fused flash attention (fp16 mma m16n8k16) ------------------
// grid (S/64, B*H), 256 threads (8 warps as 4m x 2n, warp tile 16x32).
#define FST 68   // Ss fp32 stride
#define HST 72   // fp16 tile stride (halves)
__global__ void __launch_bounds__(256) flash_h(const float* __restrict__ qkv,
                                               float* __restrict__ out)
{
    extern __shared__ char smb[];
    __half* Qs = (__half*)smb;
    __half* Ks = Qs + 64 * HST;
    __half* Vt = Ks + 64 * HST;          // transposed: Vt[dim][seq]
    __half* Ps = Vt + 64 * HST;
    float* Ss   = (float*)(Ps + 64 * HST);
    float* mrow = Ss + 64 * FST;
    float* lrow = mrow + 64;
    float* arow = lrow + 64;

    const int tid = threadIdx.x;
    const int lane = tid & 31, warp = tid >> 5;
    const int g = lane >> 2, t4 = lane & 3;
    const int wm = (warp >> 1) * 16, wn = (warp & 1) * 32;
    const int bh = blockIdx.y;
    const int b = bh / Hn, h = bh % Hn;
    const int t0 = blockIdx.x * 64;
    const int lr = tid >> 2, lc = (tid & 3) * 16;

    // load Q tile -> fp16
    const float* qb = qkv + (size_t)(b * Sn + t0) * QKVLD + h * Dn;
#pragma unroll
    for (int i = 0; i < 4; i++) {
        float4 f = *reinterpret_cast<const float4*>(qb + (size_t)lr * QKVLD + lc + i * 4);
        __half2* d = reinterpret_cast<__half2*>(&Qs[lr * HST + lc + i * 4]);
        d[0] = __floats2half2_rn(f.x, f.y);
        d[1] = __floats2half2_rn(f.z, f.w);
    }
    if (tid < 64) { mrow[tid] = -3e38f; lrow[tid] = 0.f; }

    float o[4][4];
#pragma unroll
    for (int ni = 0; ni < 4; ni++)
#pragma unroll
        for (int j = 0; j < 4; j++) o[ni][j] = 0.f;

    __syncthreads();

    for (int j0 = 0; j0 < Sn; j0 += 64) {
        const float* kb_ = qkv + (size_t)(b * Sn + j0) * QKVLD + DMn + h * Dn;
        const float* vb  = qkv + (size_t)(b * Sn + j0) * QKVLD + 2 * DMn + h * Dn;
#pragma unroll
        for (int i = 0; i < 4; i++) {
            float4 f = *reinterpret_cast<const float4*>(kb_ + (size_t)lr * QKVLD + lc + i * 4);
            __half2* d = reinterpret_cast<__half2*>(&Ks[lr * HST + lc + i * 4]);
            d[0] = __floats2half2_rn(f.x, f.y);
            d[1] = __floats2half2_rn(f.z, f.w);
            float4 f2 = *reinterpret_cast<const float4*>(vb + (size_t)lr * QKVLD + lc + i * 4);
            // transposed store: Vt[dim][seq]
            Vt[(lc + i * 4 + 0) * HST + lr] = __float2half_rn(f2.x);
            Vt[(lc + i * 4 + 1) * HST + lr] = __float2half_rn(f2.y);
            Vt[(lc + i * 4 + 2) * HST + lr] = __float2half_rn(f2.z);
            Vt[(lc + i * 4 + 3) * HST + lr] = __float2half_rn(f2.w);
        }
        __syncthreads();

        // S = Q @ K^T  (4 k16 steps over D=64)
        float s[4][4];
#pragma unroll
        for (int ni = 0; ni < 4; ni++)
#pragma unroll
            for (int j = 0; j < 4; j++) s[ni][j] = 0.f;

#pragma unroll
        for (int ks = 0; ks < 4; ks++) {
            const int k0 = ks * 16;
            uint32_t a[4], bf[4][2];
            const __half* ap = &Qs[(wm + g) * HST + k0 + 2 * t4];
            a[0] = *reinterpret_cast<const uint32_t*>(ap);
            a[1] = *reinterpret_cast<const uint32_t*>(ap + 8 * HST);
            a[2] = *reinterpret_cast<const uint32_t*>(ap + 8);
            a[3] = *reinterpret_cast<const uint32_t*>(ap + 8 * HST + 8);
#pragma unroll
            for (int ni = 0; ni < 4; ni++) {
                const __half* bp = &Ks[(wn + ni * 8 + g) * HST + k0 + 2 * t4];
                bf[ni][0] = *reinterpret_cast<const uint32_t*>(bp);
                bf[ni][1] = *reinterpret_cast<const uint32_t*>(bp + 8);
            }
#pragma unroll
            for (int ni = 0; ni < 4; ni++) {
                float* c = s[ni];
                asm volatile(
                    "mma.sync.aligned.m16n8k16.row.col.f32.f16.f16.f32 "
                    "{%0,%1,%2,%3}, {%4,%5,%6,%7}, {%8,%9}, {%0,%1,%2,%3};"
                    : "+f"(c[0]), "+f"(c[1]), "+f"(c[2]), "+f"(c[3])
                    : "r"(a[0]), "r"(a[1]), "r"(a[2]), "r"(a[3]),
                      "r"(bf[ni][0]), "r"(bf[ni][1]));
            }
        }
#pragma unroll
        for (int ni = 0; ni < 4; ni++) {
            *reinterpret_cast<float2*>(&Ss[(wm + g) * FST + wn + ni * 8 + 2 * t4]) =
                make_float2(s[ni][0] * 0.125f, s[ni][1] * 0.125f);
            *reinterpret_cast<float2*>(&Ss[(wm + g + 8) * FST + wn + ni * 8 + 2 * t4]) =
                make_float2(s[ni][2] * 0.125f, s[ni][3] * 0.125f);
        }
        __syncthreads();

        // online softmax; write P as fp16
        {
            const int r = warp * 8 + (lane >> 2);
            float* srow = &Ss[r * FST + (lane & 3) * 16];
            __half* prow = &Ps[r * HST + (lane & 3) * 16];
            float mx = -3e38f;
#pragma unroll
            for (int i = 0; i < 16; i++) mx = fmaxf(mx, srow[i]);
            mx = fmaxf(mx, __shfl_xor_sync(0xffffffffu, mx, 1));
            mx = fmaxf(mx, __shfl_xor_sync(0xffffffffu, mx, 2));
            const float mprev = mrow[r];
            const float mnew = fmaxf(mprev, mx);
            float sum = 0.f;
#pragma unroll
            for (int i = 0; i < 16; i++) {
                const __half ph = __float2half_rn(__expf(srow[i] - mnew));
                prow[i] = ph;
                sum += __half2float(ph);
            }
            sum += __shfl_xor_sync(0xffffffffu, sum, 1);
            sum += __shfl_xor_sync(0xffffffffu, sum, 2);
            if ((lane & 3) == 0) {
                const float al = __expf(mprev - mnew);
                arow[r] = al;
                lrow[r] = lrow[r] * al + sum;
                mrow[r] = mnew;
            }
        }
        __syncthreads();

        // O = O*alpha + P @ V   (4 k16 steps over 64 seq)
        const float al0 = arow[wm + g], al1 = arow[wm + g + 8];
#pragma unroll
        for (int ni = 0; ni < 4; ni++) {
            o[ni][0] *= al0; o[ni][1] *= al0;
            o[ni][2] *= al1; o[ni][3] *= al1;
        }
#pragma unroll
        for (int ks = 0; ks < 4; ks++) {
            const int k0 = ks * 16;
            uint32_t a[4], bf[4][2];
            const __half* ap = &Ps[(wm + g) * HST + k0 + 2 * t4];
            a[0] = *reinterpret_cast<const uint32_t*>(ap);
            a[1] = *reinterpret_cast<const uint32_t*>(ap + 8 * HST);
            a[2] = *reinterpret_cast<const uint32_t*>(ap + 8);
            a[3] = *reinterpret_cast<const uint32_t*>(ap + 8 * HST + 8);
#pragma unroll
            for (int ni = 0; ni < 4; ni++) {
                const __half* bp = &Vt[(wn + ni * 8 + g) * HST + k0 + 2 * t4];
                bf[ni][0] = *reinterpret_cast<const uint32_t*>(bp);
                bf[ni][1] = *reinterpret_cast<const uint32_t*>(bp + 8);
            }
#pragma unroll
            for (int ni = 0; ni < 4; ni++) {
                float* c = o[ni];
                asm volatile(
                    "mma.sync.aligned.m16n8k16.row.col.f32.f16.f16.f32 "
                    "{%0,%1,%2,%3}, {%4,%5,%6,%7}, {%8,%9}, {%0,%1,%2,%3};"
                    : "+f"(c[0]), "+f"(c[1]), "+f"(c[2]), "+f"(c[3])
                    : "r"(a[0]), "r"(a[1]), "r"(a[2]), "r"(a[3]),
                      "r"(bf[ni][0]), "r"(bf[ni][1]));
            }
        }
        __syncthreads();
    }

    const float il0 = 1.0f / lrow[wm + g];
    const float il1 = 1.0f / lrow[wm + g + 8];
    float* ob = out + (size_t)(b * Sn + t0) * DMn + h * Dn;
#pragma unroll
    for (int ni = 0; ni < 4; ni++) {
        const int col = wn + ni * 8 + 2 * t4;
        *reinterpret_cast<float2*>(&ob[(size_t)(wm + g) * DMn + col]) =
            make_float2(o[ni][0] * il0, o[ni][1] * il0);
        *reinterpret_cast<float2*>(&ob[(size_t)(wm + g + 8) * DMn + col]) =
            make_float2(o[ni][2] * il1, o[ni][3] * il1);
    }
}

#define FLASH_SMEM (4 * 64 * HST * 2 + (64 * FST + 3 * 64) * 4)

// ---------------- launch ------------------------------------------------------
extern "C" void kernel_launch(void* const* d_in, const int* in_sizes, int n_in,
                              void* d_out, int out_size)
{
    const float* x        = (const float*)d_in[0];
    const float* ln1_s    = (const float*)d_in[1];
    const float* ln1_o    = (const float*)d_in[2];
    const float* wq       = (const float*)d_in[3];
    const float* bq       = (const float*)d_in[4];
    const float* wk       = (const float*)d_in[5];
    const float* bk       = (const float*)d_in[6];
    const float* wv       = (const float*)d_in[7];
    const float* bv       = (const float*)d_in[8];
    const float* wo       = (const float*)d_in[9];
    const float* bo       = (const float*)d_in[10];
    const float* ln2_s    = (const float*)d_in[11];
    const float* ln2_o    = (const float*)d_in[12];
    const float* fc1_w    = (const float*)d_in[13];
    const float* fc1_b    = (const float*)d_in[14];
    const float* fc2_w    = (const float*)d_in[15];
    const float* fc2_b    = (const float*)d_in[16];
    float* out            = (float*)d_out;

    float *ph, *pqkv, *pattn, *px1, *pf1, *pbqkv;
    __half *phT, *pf1T, *pwr;
    cudaGetSymbolAddress((void**)&ph,    g_h);
    cudaGetSymbolAddress((void**)&phT,   g_hT);
    cudaGetSymbolAddress((void**)&pqkv,  g_qkv);
    cudaGetSymbolAddress((void**)&pattn, g_attn);
    cudaGetSymbolAddress((void**)&px1,   g_x1);
    cudaGetSymbolAddress((void**)&pf1,   g_f1);
    cudaGetSymbolAddress((void**)&pf1T,  g_f1T);
    cudaGetSymbolAddress((void**)&pwr,   g_wr);
    cudaGetSymbolAddress((void**)&pbqkv, g_bqkv);

    __half* rwqkv = pwr;                                     // fused, NBtot=30
    __half* rwo   = pwr + (size_t)3 * WSZ_DM;
    __half* rfc1  = pwr + (size_t)4 * WSZ_DM;
    __half* rfc2  = pwr + (size_t)4 * WSZ_DM + WSZ_FC;

    static bool attr_done = false;
    if (!attr_done) {
        cudaFuncSetAttribute(flash_h, cudaFuncAttributeMaxDynamicSharedMemorySize, FLASH_SMEM);
        attr_done = true;
    }

    // 0) weight transforms (fp16 fragment-major)
    {
        dim3 gdm(DMn / 128, DMn / 16);       // (10, 80)
        btrans_h<<<gdm, 256>>>(wq, rwqkv, DMn, DMn, 30, 0);
        btrans_h<<<gdm, 256>>>(wk, rwqkv, DMn, DMn, 30, 10);
        btrans_h<<<gdm, 256>>>(wv, rwqkv, DMn, DMn, 30, 20);
        btrans_h<<<gdm, 256>>>(wo, rwo, DMn, DMn, 10, 0);
        dim3 gf1(DFn / 128, DMn / 16);       // (40, 80)
        btrans_h<<<gf1, 256>>>(fc1_w, rfc1, DMn, DFn, 40, 0);
        dim3 gf2(DMn / 128, DFn / 16);       // (10, 320)
        btrans_h<<<gf2, 256>>>(fc2_w, rfc2, DFn, DMn, 10, 0);
        bias_concat<<<QKVLD / 256, 256>>>(bq, bk, bv, pbqkv);
    }

    // 1) LN1 -> h, transform -> hT
    ln_kernel<<<NTOK, 256>>>(x, ln1_s, ln1_o, ph);
    {
        dim3 ga(DMn / 16, NTOK / 128);       // (80, 32)
        atrans_h<<<ga, 256>>>(ph, phT, NTOK, DMn);
    }

    // 2) fused QKV projection -> qkv [4096 x 3840]
    {
        dim3 grid(QKVLD / 128, NTOK / 128);  // (30, 32)
        gemm_h<0><<<grid, 256>>>(phT, rwqkv, pbqkv, nullptr, pqkv, NTOK, QKVLD, DMn);
    }

    // 3) fused flash attention
    {
        dim3 grid(Sn / 64, NBH);
        flash_h<<<grid, 256, FLASH_SMEM>>>(pqkv, pattn);
    }

    // 4) transform attn, O-proj + residual(x) -> x1
    {
        dim3 ga(DMn / 16, NTOK / 128);
        atrans_h<<<ga, 256>>>(pattn, phT, NTOK, DMn);
        dim3 grid(DMn / 128, NTOK / 128);
        gemm_h<1><<<grid, 256>>>(phT, rwo, bo, x, px1, NTOK, DMn, DMn);
    }

    // 5) LN2 -> h, transform -> hT
    ln_kernel<<<NTOK, 256>>>(px1, ln2_s, ln2_o, ph);
    {
        dim3 ga(DMn / 16, NTOK / 128);
        atrans_h<<<ga, 256>>>(ph, phT, NTOK, DMn);
    }

    // 6) FC1 + exact GELU
    {
        dim3 grid(DFn / 128, NTOK / 128);
        gemm_h<2><<<grid, 256>>>(phT, rfc1, fc1_b, nullptr, pf1, NTOK, DFn, DMn);
    }

    // 7) transform f1, FC2 + residual(x1) -> out
    {
        dim3 ga(DFn / 16, NTOK / 128);       // (320, 32)
        atrans_h<<<ga, 256>>>(pf1, pf1T, NTOK, DFn);
        dim3 grid(DMn / 128, NTOK / 128);
        gemm_h<1><<<grid, 256>>>(pf1T, rfc2, fc2_b, px1, out, NTOK, DMn, DFn);
    }
}

// round 6
// speedup vs baseline: 6.0753x; 1.1480x over previous
#include <cuda_runtime.h>
#include <cuda_fp16.h>
#include <math.h>
#include <stdint.h>

// Problem constants
#define Bn   4
#define Sn   1024
#define Hn   20
#define Dn   64
#define DMn  1280
#define DFn  5120
#define NTOK 4096           // Bn*Sn
#define NBH  80             // Bn*Hn
#define EPSLN 1e-5f
#define QKVLD 3840          // row stride of fused qkv output

// ---------------- scratch (static device globals; no allocation) -------------
__device__ __half g_hT  [(size_t)NTOK * DMn];          // fragment-major A (reused 3x)
__device__ __half g_qkv [(size_t)NTOK * QKVLD];        // fused q|k|v (plain fp16)
__device__ float  g_x1  [(size_t)NTOK * DMn];          // residual 1
__device__ __half g_f1T [(size_t)NTOK * DFn];          // fragment-major FC1 out
__device__ __half g_wr  [19660800];                    // fragment-major weights (fp16)
__device__ float  g_bqkv[QKVLD];                       // concat bias

#define WSZ_DM (DMn * DMn)          // 1,638,400
#define WSZ_FC (DMn * DFn)          // 6,553,600

// ---------------- fragment-major index helper ---------------------------------
// A block (128m x 16k): idx = ((mt*32 + g*4 + t4)*8 + khi*4 + hh*2 + klo)
__device__ __forceinline__ size_t fmIdx(int m, int k, int KB) {
    const int mb = m >> 7, mr = m & 127;
    const int kb = k >> 4, kr = k & 15;
    const int mt = mr >> 4, hh = (mr >> 3) & 1, gg = mr & 7;
    const int t4k = (kr >> 1) & 3, khi = kr >> 3, klo = kr & 1;
    return ((size_t)mb * KB + kb) * 2048 +
           (size_t)((mt * 32 + gg * 4 + t4k) * 8 + khi * 4 + hh * 2 + klo);
}

// ---------------- weight transform into fp16 fragment-major blocks ------------
// B block (16k x 128n): for n-tile ni(0..15), lane(g,t4): 4 halves at (ni*32+lane)*4
__global__ void __launch_bounds__(256) btrans_h(const float* __restrict__ B,
                                                __half* __restrict__ Bt,
                                                int K, int N, int NBtot, int nbOff)
{
    __shared__ __half s[2048];
    const int nb = blockIdx.x, kb = blockIdx.y;
    const int tid = threadIdx.x;
    const float* bb = B + (size_t)(kb * 16) * N + nb * 128;

#pragma unroll
    for (int e4 = tid; e4 < 512; e4 += 256) {
        const int k = e4 >> 5, colq = (e4 & 31) * 4;
        const float4 f = *reinterpret_cast<const float4*>(bb + (size_t)k * N + colq);
        const int t4 = (k >> 1) & 3, khi = (k >> 3) & 1, klo = k & 1;
        const float vv[4] = {f.x, f.y, f.z, f.w};
#pragma unroll
        for (int j = 0; j < 4; j++) {
            const int col = colq + j;
            const int ni = col >> 3, gg = col & 7;
            s[(ni * 32 + gg * 4 + t4) * 4 + khi * 2 + klo] = __float2half_rn(vv[j]);
        }
    }
    __syncthreads();
    __half* ob = Bt + ((size_t)kb * NBtot + nbOff + nb) * 2048;
    *reinterpret_cast<uint4*>(ob + tid * 8) = *reinterpret_cast<const uint4*>(s + tid * 8);
}

// ---------------- bias concat for fused QKV -----------------------------------
__global__ void __launch_bounds__(256) bias_concat(const float* __restrict__ bq,
                                                   const float* __restrict__ bk,
                                                   const float* __restrict__ bv,
                                                   float* __restrict__ o)
{
    const int i = blockIdx.x * 256 + threadIdx.x;
    if (i < DMn) o[i] = bq[i];
    else if (i < 2 * DMn) o[i] = bk[i - DMn];
    else if (i < 3 * DMn) o[i] = bv[i - 2 * DMn];
}

// ---------------- LayerNorm fused with fragment-major fp16 output -------------
// one block per row; writes directly into A-operand layout (KB = DMn/16 = 80)
__global__ void __launch_bounds__(256) ln_ft(const float* __restrict__ x,
                                             const float* __restrict__ sc,
                                             const float* __restrict__ off,
                                             __half* __restrict__ yT)
{
    const int row = blockIdx.x;
    const float* xr = x + (size_t)row * DMn;
    const int t = threadIdx.x;
    const int lane = t & 31, wid = t >> 5;

    __shared__ float sh[32];
    __shared__ float s_mean, s_rstd;

    // pairs: p0=t (cols 2t..), p1=t+256, p2=t+512 (t<128 only)
    float2 p0 = *reinterpret_cast<const float2*>(xr + 2 * t);
    float2 p1 = *reinterpret_cast<const float2*>(xr + 512 + 2 * t);
    float2 p2 = make_float2(0.f, 0.f);
    if (t < 128) p2 = *reinterpret_cast<const float2*>(xr + 1024 + 2 * t);

    float s = p0.x + p0.y + p1.x + p1.y + p2.x + p2.y;
#pragma unroll
    for (int o = 16; o; o >>= 1) s += __shfl_xor_sync(0xffffffffu, s, o);
    if (lane == 0) sh[wid] = s;
    __syncthreads();
    if (wid == 0) {
        float v = (lane < 8) ? sh[lane] : 0.f;
#pragma unroll
        for (int o = 4; o; o >>= 1) v += __shfl_xor_sync(0xffffffffu, v, o);
        if (lane == 0) s_mean = v * (1.0f / DMn);
    }
    __syncthreads();
    const float mean = s_mean;
    __syncthreads();

    float vs = 0.f;
    {
        float d;
        d = p0.x - mean; vs += d * d;
        d = p0.y - mean; vs += d * d;
        d = p1.x - mean; vs += d * d;
        d = p1.y - mean; vs += d * d;
        if (t < 128) {
            d = p2.x - mean; vs += d * d;
            d = p2.y - mean; vs += d * d;
        }
    }
#pragma unroll
    for (int o = 16; o; o >>= 1) vs += __shfl_xor_sync(0xffffffffu, vs, o);
    if (lane == 0) sh[wid] = vs;
    __syncthreads();
    if (wid == 0) {
        float v = (lane < 8) ? sh[lane] : 0.f;
#pragma unroll
        for (int o = 4; o; o >>= 1) v += __shfl_xor_sync(0xffffffffu, v, o);
        if (lane == 0) s_rstd = rsqrtf(v * (1.0f / DMn) + EPSLN);
    }
    __syncthreads();
    const float rstd = s_rstd;

    __half* yb = yT;
    const int KB = DMn >> 4;
    {
        const int c = 2 * t;
        const float2 g2 = *reinterpret_cast<const float2*>(sc + c);
        const float2 b2 = *reinterpret_cast<const float2*>(off + c);
        *reinterpret_cast<__half2*>(yb + fmIdx(row, c, KB)) =
            __floats2half2_rn((p0.x - mean) * rstd * g2.x + b2.x,
                              (p0.y - mean) * rstd * g2.y + b2.y);
    }
    {
        const int c = 512 + 2 * t;
        const float2 g2 = *reinterpret_cast<const float2*>(sc + c);
        const float2 b2 = *reinterpret_cast<const float2*>(off + c);
        *reinterpret_cast<__half2*>(yb + fmIdx(row, c, KB)) =
            __floats2half2_rn((p1.x - mean) * rstd * g2.x + b2.x,
                              (p1.y - mean) * rstd * g2.y + b2.y);
    }
    if (t < 128) {
        const int c = 1024 + 2 * t;
        const float2 g2 = *reinterpret_cast<const float2*>(sc + c);
        const float2 b2 = *reinterpret_cast<const float2*>(off + c);
        *reinterpret_cast<__half2*>(yb + fmIdx(row, c, KB)) =
            __floats2half2_rn((p2.x - mean) * rstd * g2.x + b2.x,
                              (p2.y - mean) * rstd * g2.y + b2.y);
    }
}

// ---------------- FP16 tensor-core GEMM, fragment-major operands -------------
// EPI: 0 = bias -> plain fp16 out ; 1 = bias+res -> fp32 out ;
//      2 = bias+gelu -> fragment-major fp16 out (KB = N/16)
__device__ __forceinline__ float gelu_exact(float v) {
    return 0.5f * v * (1.0f + erff(v * 0.70710678118654752f));
}

__device__ __forceinline__ void cp16(void* smem_dst, const void* gsrc) {
    uint32_t s = (uint32_t)__cvta_generic_to_shared(smem_dst);
    asm volatile("cp.async.cg.shared.global [%0], [%1], 16;" :: "r"(s), "l"(gsrc));
}

template <int EPI>
__global__ void __launch_bounds__(256, 2) gemm_h(const __half* __restrict__ At,
                                                 const __half* __restrict__ Bt,
                                                 const float* __restrict__ bias,
                                                 const float* __restrict__ res,
                                                 void* __restrict__ Cv,
                                                 int M, int N, int K)
{
    __shared__ __align__(16) __half As[3][4096];   // 2 sub-blocks of 16k each
    __shared__ __align__(16) __half Bs[3][4096];

    const int tid = threadIdx.x;
    const int nb = blockIdx.x, mb = blockIdx.y;
    const int KB = K >> 5;       // 32-k iterations
    const int KB16 = K >> 4;
    const int NB = N >> 7;
    const int lane = tid & 31, warp = tid >> 5;
    const int wmBase = (warp >> 2) * 4;   // m-tile base (16-row tiles)
    const int wnBase = (warp & 3) * 4;    // n-tile base (8-col tiles)
    const int g = lane >> 2, t4 = lane & 3;

    const __half* aBase = At + (size_t)mb * KB16 * 2048;
    const __half* bBase = Bt + (size_t)nb * 2048;

    float acc[16][4];
#pragma unroll
    for (int i = 0; i < 16; i++)
#pragma unroll
        for (int j = 0; j < 4; j++) acc[i][j] = 0.f;

    auto issue = [&](int s, int kb) {
        const __half* ab  = aBase + (size_t)kb * 4096;
        const __half* bb0 = bBase + (size_t)(kb * 2) * NB * 2048;
        const __half* bb1 = bBase + (size_t)(kb * 2 + 1) * NB * 2048;
        cp16(&As[s][tid * 8],        ab + tid * 8);
        cp16(&As[s][2048 + tid * 8], ab + 2048 + tid * 8);
        cp16(&Bs[s][tid * 8],        bb0 + tid * 8);
        cp16(&Bs[s][2048 + tid * 8], bb1 + tid * 8);
        asm volatile("cp.async.commit_group;" ::: "memory");
    };

    issue(0, 0);
    issue(1, 1);

    for (int kb = 0; kb < KB; kb++) {
        const int s = kb % 3;
        asm volatile("cp.async.wait_group 1;" ::: "memory");
        __syncthreads();
        if (kb + 2 < KB) issue((kb + 2) % 3, kb + 2);

#pragma unroll
        for (int kk = 0; kk < 2; kk++) {
            uint32_t a[4][4], b[4][2];
#pragma unroll
            for (int mi = 0; mi < 4; mi++) {
                const uint4 fa = *reinterpret_cast<const uint4*>(
                    &As[s][kk * 2048 + ((wmBase + mi) * 32 + lane) * 8]);
                a[mi][0] = fa.x; a[mi][1] = fa.y; a[mi][2] = fa.z; a[mi][3] = fa.w;
            }
#pragma unroll
            for (int ni = 0; ni < 4; ni++) {
                const uint2 fb = *reinterpret_cast<const uint2*>(
                    &Bs[s][kk * 2048 + ((wnBase + ni) * 32 + lane) * 4]);
                b[ni][0] = fb.x; b[ni][1] = fb.y;
            }
#pragma unroll
            for (int mi = 0; mi < 4; mi++)
#pragma unroll
                for (int ni = 0; ni < 4; ni++) {
                    float* c = acc[mi * 4 + ni];
                    asm volatile(
                        "mma.sync.aligned.m16n8k16.row.col.f32.f16.f16.f32 "
                        "{%0,%1,%2,%3}, {%4,%5,%6,%7}, {%8,%9}, {%0,%1,%2,%3};"
                        : "+f"(c[0]), "+f"(c[1]), "+f"(c[2]), "+f"(c[3])
                        : "r"(a[mi][0]), "r"(a[mi][1]), "r"(a[mi][2]), "r"(a[mi][3]),
                          "r"(b[ni][0]), "r"(b[ni][1]));
                }
        }
    }

    // epilogue
    const int rowBase = mb * 128;
    const int colBase = nb * 128;
    const int wm = (warp >> 2) * 64;
    const int wn = (warp & 3) * 32;
    const int KBo = N >> 4;          // for EPI==2 fragment-major store
#pragma unroll
    for (int mi = 0; mi < 4; mi++) {
#pragma unroll
        for (int ni = 0; ni < 4; ni++) {
            float* c = acc[mi * 4 + ni];
            const int col = colBase + wn + ni * 8 + t4 * 2;
            const float2 bb = *reinterpret_cast<const float2*>(bias + col);
#pragma unroll
            for (int h = 0; h < 2; h++) {
                const int row = rowBase + wm + mi * 16 + g + h * 8;
                float o0 = c[h * 2 + 0] + bb.x;
                float o1 = c[h * 2 + 1] + bb.y;
                if (EPI == 0) {
                    __half* Ch = (__half*)Cv;
                    *reinterpret_cast<__half2*>(Ch + (size_t)row * N + col) =
                        __floats2half2_rn(o0, o1);
                } else if (EPI == 1) {
                    const float2 r2 = *reinterpret_cast<const float2*>(res + (size_t)row * N + col);
                    float* Cf = (float*)Cv;
                    *reinterpret_cast<float2*>(Cf + (size_t)row * N + col) =
                        make_float2(o0 + r2.x, o1 + r2.y);
                } else {
                    __half* Ch = (__half*)Cv;
                    *reinterpret_cast<__half2*>(Ch + fmIdx(row, col, KBo)) =
                        __floats2half2_rn(gelu_exact(o0), gelu_exact(o1));
                }
            }
        }
    }
}

// ---------------- fused flash attention (fp16 in, fragment-major fp16 out) ----
// grid (S/64, B*H), 256 threads (8 warps as 4m x 2n, warp tile 16x32).
#define FST 68   // Ss fp32 stride
#define HST 72   // fp16 tile stride (halves)
__global__ void __launch_bounds__(256) flash_h(const __half* __restrict__ qkv,
                                               __half* __restrict__ outT)
{
    extern __shared__ char smb[];
    __half* Qs = (__half*)smb;
    __half* Ks = Qs + 64 * HST;
    __half* Vt = Ks + 64 * HST;          // transposed: Vt[dim][seq]
    __half* Ps = Vt + 64 * HST;
    float* Ss   = (float*)(Ps + 64 * HST);
    float* mrow = Ss + 64 * FST;
    float* lrow = mrow + 64;
    float* arow = lrow + 64;

    const int tid = threadIdx.x;
    const int lane = tid & 31, warp = tid >> 5;
    const int g = lane >> 2, t4 = lane & 3;
    const int wm = (warp >> 1) * 16, wn = (warp & 1) * 32;
    const int bh = blockIdx.y;
    const int b = bh / Hn, h = bh % Hn;
    const int t0 = blockIdx.x * 64;
    const int lr = tid >> 2, lc = (tid & 3) * 16;

    // load Q tile: raw fp16 copy
    const __half* qb = qkv + (size_t)(b * Sn + t0) * QKVLD + h * Dn;
    {
        const __half* qr = qb + (size_t)lr * QKVLD + lc;
        *reinterpret_cast<uint4*>(&Qs[lr * HST + lc])     = *reinterpret_cast<const uint4*>(qr);
        *reinterpret_cast<uint4*>(&Qs[lr * HST + lc + 8]) = *reinterpret_cast<const uint4*>(qr + 8);
    }
    if (tid < 64) { mrow[tid] = -3e38f; lrow[tid] = 0.f; }

    float o[4][4];
#pragma unroll
    for (int ni = 0; ni < 4; ni++)
#pragma unroll
        for (int j = 0; j < 4; j++) o[ni][j] = 0.f;

    __syncthreads();

    for (int j0 = 0; j0 < Sn; j0 += 64) {
        const __half* kr = qkv + (size_t)(b * Sn + j0) * QKVLD + DMn + h * Dn + (size_t)lr * QKVLD + lc;
        const __half* vr = qkv + (size_t)(b * Sn + j0) * QKVLD + 2 * DMn + h * Dn + (size_t)lr * QKVLD + lc;
        *reinterpret_cast<uint4*>(&Ks[lr * HST + lc])     = *reinterpret_cast<const uint4*>(kr);
        *reinterpret_cast<uint4*>(&Ks[lr * HST + lc + 8]) = *reinterpret_cast<const uint4*>(kr + 8);
        {
            uint4 u0 = *reinterpret_cast<const uint4*>(vr);
            uint4 u1 = *reinterpret_cast<const uint4*>(vr + 8);
            const __half* hv = reinterpret_cast<const __half*>(&u0);
#pragma unroll
            for (int j = 0; j < 8; j++) Vt[(lc + j) * HST + lr] = hv[j];
            hv = reinterpret_cast<const __half*>(&u1);
#pragma unroll
            for (int j = 0; j < 8; j++) Vt[(lc + 8 + j) * HST + lr] = hv[j];
        }
        __syncthreads();

        // S = Q @ K^T  (4 k16 steps over D=64)
        float s[4][4];
#pragma unroll
        for (int ni = 0; ni < 4; ni++)
#pragma unroll
            for (int j = 0; j < 4; j++) s[ni][j] = 0.f;

#pragma unroll
        for (int ks = 0; ks < 4; ks++) {
            const int k0 = ks * 16;
            uint32_t a[4], bf[4][2];
            const __half* ap = &Qs[(wm + g) * HST + k0 + 2 * t4];
            a[0] = *reinterpret_cast<const uint32_t*>(ap);
            a[1] = *reinterpret_cast<const uint32_t*>(ap + 8 * HST);
            a[2] = *reinterpret_cast<const uint32_t*>(ap + 8);
            a[3] = *reinterpret_cast<const uint32_t*>(ap + 8 * HST + 8);
#pragma unroll
            for (int ni = 0; ni < 4; ni++) {
                const __half* bp = &Ks[(wn + ni * 8 + g) * HST + k0 + 2 * t4];
                bf[ni][0] = *reinterpret_cast<const uint32_t*>(bp);
                bf[ni][1] = *reinterpret_cast<const uint32_t*>(bp + 8);
            }
#pragma unroll
            for (int ni = 0; ni < 4; ni++) {
                float* c = s[ni];
                asm volatile(
                    "mma.sync.aligned.m16n8k16.row.col.f32.f16.f16.f32 "
                    "{%0,%1,%2,%3}, {%4,%5,%6,%7}, {%8,%9}, {%0,%1,%2,%3};"
                    : "+f"(c[0]), "+f"(c[1]), "+f"(c[2]), "+f"(c[3])
                    : "r"(a[0]), "r"(a[1]), "r"(a[2]), "r"(a[3]),
                      "r"(bf[ni][0]), "r"(bf[ni][1]));
            }
        }
#pragma unroll
        for (int ni = 0; ni < 4; ni++) {
            *reinterpret_cast<float2*>(&Ss[(wm + g) * FST + wn + ni * 8 + 2 * t4]) =
                make_float2(s[ni][0] * 0.125f, s[ni][1] * 0.125f);
            *reinterpret_cast<float2*>(&Ss[(wm + g + 8) * FST + wn + ni * 8 + 2 * t4]) =
                make_float2(s[ni][2] * 0.125f, s[ni][3] * 0.125f);
        }
        __syncthreads();

        // online softmax; write P as fp16
        {
            const int r = warp * 8 + (lane >> 2);
            float* srow = &Ss[r * FST + (lane & 3) * 16];
            __half* prow = &Ps[r * HST + (lane & 3) * 16];
            float mx = -3e38f;
#pragma unroll
            for (int i = 0; i < 16; i++) mx = fmaxf(mx, srow[i]);
            mx = fmaxf(mx, __shfl_xor_sync(0xffffffffu, mx, 1));
            mx = fmaxf(mx, __shfl_xor_sync(0xffffffffu, mx, 2));
            const float mprev = mrow[r];
            const float mnew = fmaxf(mprev, mx);
            float sum = 0.f;
#pragma unroll
            for (int i = 0; i < 16; i++) {
                const __half ph = __float2half_rn(__expf(srow[i] - mnew));
                prow[i] = ph;
                sum += __half2float(ph);
            }
            sum += __shfl_xor_sync(0xffffffffu, sum, 1);
            sum += __shfl_xor_sync(0xffffffffu, sum, 2);
            if ((lane & 3) == 0) {
                const float al = __expf(mprev - mnew);
                arow[r] = al;
                lrow[r] = lrow[r] * al + sum;
                mrow[r] = mnew;
            }
        }
        __syncthreads();

        // O = O*alpha + P @ V   (4 k16 steps over 64 seq)
        const float al0 = arow[wm + g], al1 = arow[wm + g + 8];
#pragma unroll
        for (int ni = 0; ni < 4; ni++) {
            o[ni][0] *= al0; o[ni][1] *= al0;
            o[ni][2] *= al1; o[ni][3] *= al1;
        }
#pragma unroll
        for (int ks = 0; ks < 4; ks++) {
            const int k0 = ks * 16;
            uint32_t a[4], bf[4][2];
            const __half* ap = &Ps[(wm + g) * HST + k0 + 2 * t4];
            a[0] = *reinterpret_cast<const uint32_t*>(ap);
            a[1] = *reinterpret_cast<const uint32_t*>(ap + 8 * HST);
            a[2] = *reinterpret_cast<const uint32_t*>(ap + 8);
            a[3] = *reinterpret_cast<const uint32_t*>(ap + 8 * HST + 8);
#pragma unroll
            for (int ni = 0; ni < 4; ni++) {
                const __half* bp = &Vt[(wn + ni * 8 + g) * HST + k0 + 2 * t4];
                bf[ni][0] = *reinterpret_cast<const uint32_t*>(bp);
                bf[ni][1] = *reinterpret_cast<const uint32_t*>(bp + 8);
            }
#pragma unroll
            for (int ni = 0; ni < 4; ni++) {
                float* c = o[ni];
                asm volatile(
                    "mma.sync.aligned.m16n8k16.row.col.f32.f16.f16.f32 "
                    "{%0,%1,%2,%3}, {%4,%5,%6,%7}, {%8,%9}, {%0,%1,%2,%3};"
                    : "+f"(c[0]), "+f"(c[1]), "+f"(c[2]), "+f"(c[3])
                    : "r"(a[0]), "r"(a[1]), "r"(a[2]), "r"(a[3]),
                      "r"(bf[ni][0]), "r"(bf[ni][1]));
            }
        }
        __syncthreads();
    }

    // normalize and write fragment-major fp16 (feeds O-proj A operand)
    const float il0 = 1.0f / lrow[wm + g];
    const float il1 = 1.0f / lrow[wm + g + 8];
    const int KBo = DMn >> 4;
#pragma unroll
    for (int ni = 0; ni < 4; ni++) {
        const int k = h * Dn + wn + ni * 8 + 2 * t4;
        const int m0 = b * Sn + t0 + wm + g;
        *reinterpret_cast<__half2*>(outT + fmIdx(m0, k, KBo)) =
            __floats2half2_rn(o[ni][0] * il0, o[ni][1] * il0);
        *reinterpret_cast<__half2*>(outT + fmIdx(m0 + 8, k, KBo)) =
            __floats2half2_rn(o[ni][2] * il1, o[ni][3] * il1);
    }
}

#define FLASH_SMEM (4 * 64 * HST * 2 + (64 * FST + 3 * 64) * 4)

// ---------------- launch ------------------------------------------------------
extern "C" void kernel_launch(void* const* d_in, const int* in_sizes, int n_in,
                              void* d_out, int out_size)
{
    const float* x        = (const float*)d_in[0];
    const float* ln1_s    = (const float*)d_in[1];
    const float* ln1_o    = (const float*)d_in[2];
    const float* wq       = (const float*)d_in[3];
    const float* bq       = (const float*)d_in[4];
    const float* wk       = (const float*)d_in[5];
    const float* bk       = (const float*)d_in[6];
    const float* wv       = (const float*)d_in[7];
    const float* bv       = (const float*)d_in[8];
    const float* wo       = (const float*)d_in[9];
    const float* bo       = (const float*)d_in[10];
    const float* ln2_s    = (const float*)d_in[11];
    const float* ln2_o    = (const float*)d_in[12];
    const float* fc1_w    = (const float*)d_in[13];
    const float* fc1_b    = (const float*)d_in[14];
    const float* fc2_w    = (const float*)d_in[15];
    const float* fc2_b    = (const float*)d_in[16];
    float* out            = (float*)d_out;

    float *px1, *pbqkv;
    __half *phT, *pqkv, *pf1T, *pwr;
    cudaGetSymbolAddress((void**)&phT,   g_hT);
    cudaGetSymbolAddress((void**)&pqkv,  g_qkv);
    cudaGetSymbolAddress((void**)&px1,   g_x1);
    cudaGetSymbolAddress((void**)&pf1T,  g_f1T);
    cudaGetSymbolAddress((void**)&pwr,   g_wr);
    cudaGetSymbolAddress((void**)&pbqkv, g_bqkv);

    __half* rwqkv = pwr;                                     // fused, NBtot=30
    __half* rwo   = pwr + (size_t)3 * WSZ_DM;
    __half* rfc1  = pwr + (size_t)4 * WSZ_DM;
    __half* rfc2  = pwr + (size_t)4 * WSZ_DM + WSZ_FC;

    static bool attr_done = false;
    if (!attr_done) {
        cudaFuncSetAttribute(flash_h, cudaFuncAttributeMaxDynamicSharedMemorySize, FLASH_SMEM);
        attr_done = true;
    }

    // 0) weight transforms (fp16 fragment-major)
    {
        dim3 gdm(DMn / 128, DMn / 16);       // (10, 80)
        btrans_h<<<gdm, 256>>>(wq, rwqkv, DMn, DMn, 30, 0);
        btrans_h<<<gdm, 256>>>(wk, rwqkv, DMn, DMn, 30, 10);
        btrans_h<<<gdm, 256>>>(wv, rwqkv, DMn, DMn, 30, 20);
        btrans_h<<<gdm, 256>>>(wo, rwo, DMn, DMn, 10, 0);
        dim3 gf1(DFn / 128, DMn / 16);       // (40, 80)
        btrans_h<<<gf1, 256>>>(fc1_w, rfc1, DMn, DFn, 40, 0);
        dim3 gf2(DMn / 128, DFn / 16);       // (10, 320)
        btrans_h<<<gf2, 256>>>(fc2_w, rfc2, DFn, DMn, 10, 0);
        bias_concat<<<QKVLD / 256, 256>>>(bq, bk, bv, pbqkv);
    }

    // 1) LN1 -> fragment-major hT
    ln_ft<<<NTOK, 256>>>(x, ln1_s, ln1_o, phT);

    // 2) fused QKV projection -> qkv (plain fp16)
    {
        dim3 grid(QKVLD / 128, NTOK / 128);  // (30, 32)
        gemm_h<0><<<grid, 256>>>(phT, rwqkv, pbqkv, nullptr, pqkv, NTOK, QKVLD, DMn);
    }

    // 3) fused flash attention -> fragment-major hT (reuse)
    {
        dim3 grid(Sn / 64, NBH);
        flash_h<<<grid, 256, FLASH_SMEM>>>(pqkv, phT);
    }

    // 4) O-proj + residual(x) -> x1 (fp32)
    {
        dim3 grid(DMn / 128, NTOK / 128);
        gemm_h<1><<<grid, 256>>>(phT, rwo, bo, x, px1, NTOK, DMn, DMn);
    }

    // 5) LN2 -> fragment-major hT (reuse)
    ln_ft<<<NTOK, 256>>>(px1, ln2_s, ln2_o, phT);

    // 6) FC1 + GELU -> fragment-major f1T
    {
        dim3 grid(DFn / 128, NTOK / 128);
        gemm_h<2><<<grid, 256>>>(phT, rfc1, fc1_b, nullptr, pf1T, NTOK, DFn, DMn);
    }

    // 7) FC2 + residual(x1) -> out
    {
        dim3 grid(DMn / 128, NTOK / 128);
        gemm_h<1><<<grid, 256>>>(pf1T, rfc2, fc2_b, px1, out, NTOK, DMn, DFn);
    }
}

// round 9
// speedup vs baseline: 6.2051x; 1.0214x over previous
#include <cuda_runtime.h>
#include <cuda_fp16.h>
#include <math.h>
#include <stdint.h>

// Problem constants
#define Bn   4
#define Sn   1024
#define Hn   20
#define Dn   64
#define DMn  1280
#define DFn  5120
#define NTOK 4096           // Bn*Sn
#define NBH  80             // Bn*Hn
#define EPSLN 1e-5f
#define QKVLD 3840          // row stride of fused qkv output

// ---------------- scratch (static device globals; no allocation) -------------
__device__ __half g_hT  [(size_t)NTOK * DMn];          // fragment-major A (reused 3x)
__device__ __half g_qkv [(size_t)NTOK * QKVLD];        // fused q|k|v (plain fp16)
__device__ float  g_x1  [(size_t)NTOK * DMn];          // residual 1
__device__ __half g_f1T [(size_t)NTOK * DFn];          // fragment-major FC1 out
__device__ __half g_wr  [19660800];                    // fragment-major weights (fp16)
__device__ float  g_bqkv[QKVLD];                       // concat bias

#define WSZ_DM (DMn * DMn)          // 1,638,400
#define WSZ_FC (DMn * DFn)          // 6,553,600

// ---------------- fragment-major index helper ---------------------------------
__device__ __forceinline__ size_t fmIdx(int m, int k, int KB) {
    const int mb = m >> 7, mr = m & 127;
    const int kb = k >> 4, kr = k & 15;
    const int mt = mr >> 4, hh = (mr >> 3) & 1, gg = mr & 7;
    const int t4k = (kr >> 1) & 3, khi = kr >> 3, klo = kr & 1;
    return ((size_t)mb * KB + kb) * 2048 +
           (size_t)((mt * 32 + gg * 4 + t4k) * 8 + khi * 4 + hh * 2 + klo);
}

// ---------------- weight transform into fp16 fragment-major blocks ------------
__global__ void __launch_bounds__(256) btrans_h(const float* __restrict__ B,
                                                __half* __restrict__ Bt,
                                                int K, int N, int NBtot, int nbOff)
{
    __shared__ __half s[2048];
    const int nb = blockIdx.x, kb = blockIdx.y;
    const int tid = threadIdx.x;
    const float* bb = B + (size_t)(kb * 16) * N + nb * 128;

#pragma unroll
    for (int e4 = tid; e4 < 512; e4 += 256) {
        const int k = e4 >> 5, colq = (e4 & 31) * 4;
        const float4 f = *reinterpret_cast<const float4*>(bb + (size_t)k * N + colq);
        const int t4 = (k >> 1) & 3, khi = (k >> 3) & 1, klo = k & 1;
        const float vv[4] = {f.x, f.y, f.z, f.w};
#pragma unroll
        for (int j = 0; j < 4; j++) {
            const int col = colq + j;
            const int ni = col >> 3, gg = col & 7;
            s[(ni * 32 + gg * 4 + t4) * 4 + khi * 2 + klo] = __float2half_rn(vv[j]);
        }
    }
    __syncthreads();
    __half* ob = Bt + ((size_t)kb * NBtot + nbOff + nb) * 2048;
    *reinterpret_cast<uint4*>(ob + tid * 8) = *reinterpret_cast<const uint4*>(s + tid * 8);
}

// ---------------- bias concat for fused QKV -----------------------------------
__global__ void __launch_bounds__(256) bias_concat(const float* __restrict__ bq,
                                                   const float* __restrict__ bk,
                                                   const float* __restrict__ bv,
                                                   float* __restrict__ o)
{
    const int i = blockIdx.x * 256 + threadIdx.x;
    if (i < DMn) o[i] = bq[i];
    else if (i < 2 * DMn) o[i] = bk[i - DMn];
    else if (i < 3 * DMn) o[i] = bv[i - 2 * DMn];
}

// ---------------- LayerNorm fused with fragment-major fp16 output -------------
__global__ void __launch_bounds__(256) ln_ft(const float* __restrict__ x,
                                             const float* __restrict__ sc,
                                             const float* __restrict__ off,
                                             __half* __restrict__ yT)
{
    const int row = blockIdx.x;
    const float* xr = x + (size_t)row * DMn;
    const int t = threadIdx.x;
    const int lane = t & 31, wid = t >> 5;

    __shared__ float sh[32];
    __shared__ float s_mean, s_rstd;

    float2 p0 = *reinterpret_cast<const float2*>(xr + 2 * t);
    float2 p1 = *reinterpret_cast<const float2*>(xr + 512 + 2 * t);
    float2 p2 = make_float2(0.f, 0.f);
    if (t < 128) p2 = *reinterpret_cast<const float2*>(xr + 1024 + 2 * t);

    float s = p0.x + p0.y + p1.x + p1.y + p2.x + p2.y;
#pragma unroll
    for (int o = 16; o; o >>= 1) s += __shfl_xor_sync(0xffffffffu, s, o);
    if (lane == 0) sh[wid] = s;
    __syncthreads();
    if (wid == 0) {
        float v = (lane < 8) ? sh[lane] : 0.f;
#pragma unroll
        for (int o = 4; o; o >>= 1) v += __shfl_xor_sync(0xffffffffu, v, o);
        if (lane == 0) s_mean = v * (1.0f / DMn);
    }
    __syncthreads();
    const float mean = s_mean;
    __syncthreads();

    float vs = 0.f;
    {
        float d;
        d = p0.x - mean; vs += d * d;
        d = p0.y - mean; vs += d * d;
        d = p1.x - mean; vs += d * d;
        d = p1.y - mean; vs += d * d;
        if (t < 128) {
            d = p2.x - mean; vs += d * d;
            d = p2.y - mean; vs += d * d;
        }
    }
#pragma unroll
    for (int o = 16; o; o >>= 1) vs += __shfl_xor_sync(0xffffffffu, vs, o);
    if (lane == 0) sh[wid] = vs;
    __syncthreads();
    if (wid == 0) {
        float v = (lane < 8) ? sh[lane] : 0.f;
#pragma unroll
        for (int o = 4; o; o >>= 1) v += __shfl_xor_sync(0xffffffffu, v, o);
        if (lane == 0) s_rstd = rsqrtf(v * (1.0f / DMn) + EPSLN);
    }
    __syncthreads();
    const float rstd = s_rstd;

    const int KB = DMn >> 4;
    {
        const int c = 2 * t;
        const float2 g2 = *reinterpret_cast<const float2*>(sc + c);
        const float2 b2 = *reinterpret_cast<const float2*>(off + c);
        *reinterpret_cast<__half2*>(yT + fmIdx(row, c, KB)) =
            __floats2half2_rn((p0.x - mean) * rstd * g2.x + b2.x,
                              (p0.y - mean) * rstd * g2.y + b2.y);
    }
    {
        const int c = 512 + 2 * t;
        const float2 g2 = *reinterpret_cast<const float2*>(sc + c);
        const float2 b2 = *reinterpret_cast<const float2*>(off + c);
        *reinterpret_cast<__half2*>(yT + fmIdx(row, c, KB)) =
            __floats2half2_rn((p1.x - mean) * rstd * g2.x + b2.x,
                              (p1.y - mean) * rstd * g2.y + b2.y);
    }
    if (t < 128) {
        const int c = 1024 + 2 * t;
        const float2 g2 = *reinterpret_cast<const float2*>(sc + c);
        const float2 b2 = *reinterpret_cast<const float2*>(off + c);
        *reinterpret_cast<__half2*>(yT + fmIdx(row, c, KB)) =
            __floats2half2_rn((p2.x - mean) * rstd * g2.x + b2.x,
                              (p2.y - mean) * rstd * g2.y + b2.y);
    }
}

// ---------------- GEMM helpers -------------------------------------------------
__device__ __forceinline__ float gelu_exact(float v) {
    return 0.5f * v * (1.0f + erff(v * 0.70710678118654752f));
}

__device__ __forceinline__ void cp16(void* smem_dst, const void* gsrc) {
    uint32_t s = (uint32_t)__cvta_generic_to_shared(smem_dst);
    asm volatile("cp.async.cg.shared.global [%0], [%1], 16;" :: "r"(s), "l"(gsrc));
}

// Drain discipline: buffer for iteration kb was filled by group G_kb. Before
// computing on it we must ensure G_kb is complete. Outstanding groups at the
// wait point are {G_kb, G_{kb+1}} except on the FINAL iteration where only
// {G_kb} remains — there wait_group 1 is a NO-OP and races the copy. Use
// wait_group 0 on the final iteration.
#define PIPE_WAIT(kb, KB) \
    do { if ((kb) + 1 < (KB)) asm volatile("cp.async.wait_group 1;" ::: "memory"); \
         else                 asm volatile("cp.async.wait_group 0;" ::: "memory"); } while (0)

#define MMA_H(c, a0,a1,a2,a3, b0,b1) \
    asm volatile("mma.sync.aligned.m16n8k16.row.col.f32.f16.f16.f32 " \
                 "{%0,%1,%2,%3}, {%4,%5,%6,%7}, {%8,%9}, {%0,%1,%2,%3};" \
                 : "+f"((c)[0]), "+f"((c)[1]), "+f"((c)[2]), "+f"((c)[3]) \
                 : "r"(a0), "r"(a1), "r"(a2), "r"(a3), "r"(b0), "r"(b1))

// ---------------- FP16 GEMM, 128x128 tile (EPI: 0 fp16 out, 2 gelu->frag) -----
template <int EPI>
__global__ void __launch_bounds__(256, 2) gemm_h(const __half* __restrict__ At,
                                                 const __half* __restrict__ Bt,
                                                 const float* __restrict__ bias,
                                                 const float* __restrict__ res,
                                                 void* __restrict__ Cv,
                                                 int M, int N, int K)
{
    __shared__ __align__(16) __half As[3][4096];
    __shared__ __align__(16) __half Bs[3][4096];

    const int tid = threadIdx.x;
    const int nb = blockIdx.x, mb = blockIdx.y;
    const int KB = K >> 5;
    const int KB16 = K >> 4;
    const int NB = N >> 7;
    const int lane = tid & 31, warp = tid >> 5;
    const int wmBase = (warp >> 2) * 4;
    const int wnBase = (warp & 3) * 4;
    const int g = lane >> 2, t4 = lane & 3;

    const __half* aBase = At + (size_t)mb * KB16 * 2048;
    const __half* bBase = Bt + (size_t)nb * 2048;

    float acc[16][4];
#pragma unroll
    for (int i = 0; i < 16; i++)
#pragma unroll
        for (int j = 0; j < 4; j++) acc[i][j] = 0.f;

    auto issue = [&](int s, int kb) {
        const __half* ab  = aBase + (size_t)kb * 4096;
        const __half* bb0 = bBase + (size_t)(kb * 2) * NB * 2048;
        const __half* bb1 = bBase + (size_t)(kb * 2 + 1) * NB * 2048;
        cp16(&As[s][tid * 8],        ab + tid * 8);
        cp16(&As[s][2048 + tid * 8], ab + 2048 + tid * 8);
        cp16(&Bs[s][tid * 8],        bb0 + tid * 8);
        cp16(&Bs[s][2048 + tid * 8], bb1 + tid * 8);
        asm volatile("cp.async.commit_group;" ::: "memory");
    };

    issue(0, 0);
    issue(1, 1);

    for (int kb = 0; kb < KB; kb++) {
        const int s = kb % 3;
        PIPE_WAIT(kb, KB);
        __syncthreads();
        if (kb + 2 < KB) issue((kb + 2) % 3, kb + 2);

#pragma unroll
        for (int kk = 0; kk < 2; kk++) {
            uint32_t a[4][4], b[4][2];
#pragma unroll
            for (int mi = 0; mi < 4; mi++) {
                const uint4 fa = *reinterpret_cast<const uint4*>(
                    &As[s][kk * 2048 + ((wmBase + mi) * 32 + lane) * 8]);
                a[mi][0] = fa.x; a[mi][1] = fa.y; a[mi][2] = fa.z; a[mi][3] = fa.w;
            }
#pragma unroll
            for (int ni = 0; ni < 4; ni++) {
                const uint2 fb = *reinterpret_cast<const uint2*>(
                    &Bs[s][kk * 2048 + ((wnBase + ni) * 32 + lane) * 4]);
                b[ni][0] = fb.x; b[ni][1] = fb.y;
            }
#pragma unroll
            for (int mi = 0; mi < 4; mi++)
#pragma unroll
                for (int ni = 0; ni < 4; ni++)
                    MMA_H(acc[mi * 4 + ni], a[mi][0], a[mi][1], a[mi][2], a[mi][3],
                          b[ni][0], b[ni][1]);
        }
    }

    const int rowBase = mb * 128;
    const int colBase = nb * 128;
    const int wm = (warp >> 2) * 64;
    const int wn = (warp & 3) * 32;
    const int KBo = N >> 4;
#pragma unroll
    for (int mi = 0; mi < 4; mi++) {
#pragma unroll
        for (int ni = 0; ni < 4; ni++) {
            float* c = acc[mi * 4 + ni];
            const int col = colBase + wn + ni * 8 + t4 * 2;
            const float2 bb = *reinterpret_cast<const float2*>(bias + col);
#pragma unroll
            for (int h = 0; h < 2; h++) {
                const int row = rowBase + wm + mi * 16 + g + h * 8;
                float o0 = c[h * 2 + 0] + bb.x;
                float o1 = c[h * 2 + 1] + bb.y;
                if (EPI == 0) {
                    __half* Ch = (__half*)Cv;
                    *reinterpret_cast<__half2*>(Ch + (size_t)row * N + col) =
                        __floats2half2_rn(o0, o1);
                } else {
                    __half* Ch = (__half*)Cv;
                    *reinterpret_cast<__half2*>(Ch + fmIdx(row, col, KBo)) =
                        __floats2half2_rn(gelu_exact(o0), gelu_exact(o1));
                }
            }
        }
    }
}

// ---------------- FP16 GEMM, 64x128 tile, EPI = bias+res -> fp32 --------------
__global__ void __launch_bounds__(256, 3) gemm_h64(const __half* __restrict__ At,
                                                   const __half* __restrict__ Bt,
                                                   const float* __restrict__ bias,
                                                   const float* __restrict__ res,
                                                   float* __restrict__ C,
                                                   int M, int N, int K)
{
    __shared__ __align__(16) __half As[3][2048];   // 2 kk x 1024 (4 m-tiles)
    __shared__ __align__(16) __half Bs[3][4096];

    const int tid = threadIdx.x;
    const int nb = blockIdx.x, mb = blockIdx.y;
    const int KB = K >> 5;
    const int KB16 = K >> 4;
    const int NB = N >> 7;
    const int lane = tid & 31, warp = tid >> 5;
    const int wmBase = (warp >> 2) * 2;   // m-tile base (0 or 2)
    const int wnBase = (warp & 3) * 4;
    const int g = lane >> 2, t4 = lane & 3;
    const int mhalf = mb & 1, mblk = mb >> 1;

    const __half* aBase = At + (size_t)mblk * KB16 * 2048 + mhalf * 1024;
    const __half* bBase = Bt + (size_t)nb * 2048;

    float acc[8][4];
#pragma unroll
    for (int i = 0; i < 8; i++)
#pragma unroll
        for (int j = 0; j < 4; j++) acc[i][j] = 0.f;

    auto issue = [&](int s, int kb) {
        const __half* ab0 = aBase + (size_t)(kb * 2) * 2048;
        const __half* ab1 = aBase + (size_t)(kb * 2 + 1) * 2048;
        if (tid < 128) cp16(&As[s][tid * 8], ab0 + tid * 8);
        else           cp16(&As[s][1024 + (tid - 128) * 8], ab1 + (tid - 128) * 8);
        const __half* bb0 = bBase + (size_t)(kb * 2) * NB * 2048;
        const __half* bb1 = bBase + (size_t)(kb * 2 + 1) * NB * 2048;
        cp16(&Bs[s][tid * 8],        bb0 + tid * 8);
        cp16(&Bs[s][2048 + tid * 8], bb1 + tid * 8);
        asm volatile("cp.async.commit_group;" ::: "memory");
    };

    issue(0, 0);
    issue(1, 1);

    for (int kb = 0; kb < KB; kb++) {
        const int s = kb % 3;
        PIPE_WAIT(kb, KB);
        __syncthreads();
        if (kb + 2 < KB) issue((kb + 2) % 3, kb + 2);

#pragma unroll
        for (int kk = 0; kk < 2; kk++) {
            uint32_t a[2][4], b[4][2];
#pragma unroll
            for (int mi = 0; mi < 2; mi++) {
                const uint4 fa = *reinterpret_cast<const uint4*>(
                    &As[s][kk * 1024 + (wmBase + mi) * 256 + lane * 8]);
                a[mi][0] = fa.x; a[mi][1] = fa.y; a[mi][2] = fa.z; a[mi][3] = fa.w;
            }
#pragma unroll
            for (int ni = 0; ni < 4; ni++) {
                const uint2 fb = *reinterpret_cast<const uint2*>(
                    &Bs[s][kk * 2048 + ((wnBase + ni) * 32 + lane) * 4]);
                b[ni][0] = fb.x; b[ni][1] = fb.y;
            }
#pragma unroll
            for (int mi = 0; mi < 2; mi++)
#pragma unroll
                for (int ni = 0; ni < 4; ni++)
                    MMA_H(acc[mi * 4 + ni], a[mi][0], a[mi][1], a[mi][2], a[mi][3],
                          b[ni][0], b[ni][1]);
        }
    }

    const int rowBase = mb * 64;
    const int colBase = nb * 128;
    const int wm = (warp >> 2) * 32;
    const int wn = (warp & 3) * 32;
#pragma unroll
    for (int mi = 0; mi < 2; mi++) {
#pragma unroll
        for (int ni = 0; ni < 4; ni++) {
            float* c = acc[mi * 4 + ni];
            const int col = colBase + wn + ni * 8 + t4 * 2;
            const float2 bb = *reinterpret_cast<const float2*>(bias + col);
#pragma unroll
            for (int h = 0; h < 2; h++) {
                const int row = rowBase + wm + mi * 16 + g + h * 8;
                const float2 r2 = *reinterpret_cast<const float2*>(res + (size_t)row * N + col);
                *reinterpret_cast<float2*>(C + (size_t)row * N + col) =
                    make_float2(c[h * 2 + 0] + bb.x + r2.x, c[h * 2 + 1] + bb.y + r2.y);
            }
        }
    }
}

// ---------------- fused flash attention (round-6 proven version) --------------
// grid (S/64, B*H), 256 threads (8 warps as 4m x 2n, warp tile 16x32).
#define FST 68   // Ss fp32 stride
#define HST 72   // fp16 tile stride (halves)
__global__ void __launch_bounds__(256) flash_h(const __half* __restrict__ qkv,
                                               __half* __restrict__ outT)
{
    extern __shared__ char smb[];
    __half* Qs = (__half*)smb;
    __half* Ks = Qs + 64 * HST;
    __half* Vt = Ks + 64 * HST;          // transposed: Vt[dim][seq]
    __half* Ps = Vt + 64 * HST;
    float* Ss   = (float*)(Ps + 64 * HST);
    float* mrow = Ss + 64 * FST;
    float* lrow = mrow + 64;
    float* arow = lrow + 64;

    const int tid = threadIdx.x;
    const int lane = tid & 31, warp = tid >> 5;
    const int g = lane >> 2, t4 = lane & 3;
    const int wm = (warp >> 1) * 16, wn = (warp & 1) * 32;
    const int bh = blockIdx.y;
    const int b = bh / Hn, h = bh % Hn;
    const int t0 = blockIdx.x * 64;
    const int lr = tid >> 2, lc = (tid & 3) * 16;

    // load Q tile: raw fp16 copy
    const __half* qb = qkv + (size_t)(b * Sn + t0) * QKVLD + h * Dn;
    {
        const __half* qr = qb + (size_t)lr * QKVLD + lc;
        *reinterpret_cast<uint4*>(&Qs[lr * HST + lc])     = *reinterpret_cast<const uint4*>(qr);
        *reinterpret_cast<uint4*>(&Qs[lr * HST + lc + 8]) = *reinterpret_cast<const uint4*>(qr + 8);
    }
    if (tid < 64) { mrow[tid] = -3e38f; lrow[tid] = 0.f; }

    float o[4][4];
#pragma unroll
    for (int ni = 0; ni < 4; ni++)
#pragma unroll
        for (int j = 0; j < 4; j++) o[ni][j] = 0.f;

    __syncthreads();

    for (int j0 = 0; j0 < Sn; j0 += 64) {
        const __half* kr = qkv + (size_t)(b * Sn + j0) * QKVLD + DMn + h * Dn + (size_t)lr * QKVLD + lc;
        const __half* vr = qkv + (size_t)(b * Sn + j0) * QKVLD + 2 * DMn + h * Dn + (size_t)lr * QKVLD + lc;
        *reinterpret_cast<uint4*>(&Ks[lr * HST + lc])     = *reinterpret_cast<const uint4*>(kr);
        *reinterpret_cast<uint4*>(&Ks[lr * HST + lc + 8]) = *reinterpret_cast<const uint4*>(kr + 8);
        {
            uint4 u0 = *reinterpret_cast<const uint4*>(vr);
            uint4 u1 = *reinterpret_cast<const uint4*>(vr + 8);
            const __half* hv = reinterpret_cast<const __half*>(&u0);
#pragma unroll
            for (int j = 0; j < 8; j++) Vt[(lc + j) * HST + lr] = hv[j];
            hv = reinterpret_cast<const __half*>(&u1);
#pragma unroll
            for (int j = 0; j < 8; j++) Vt[(lc + 8 + j) * HST + lr] = hv[j];
        }
        __syncthreads();

        // S = Q @ K^T  (4 k16 steps over D=64)
        float s[4][4];
#pragma unroll
        for (int ni = 0; ni < 4; ni++)
#pragma unroll
            for (int j = 0; j < 4; j++) s[ni][j] = 0.f;

#pragma unroll
        for (int ks = 0; ks < 4; ks++) {
            const int k0 = ks * 16;
            uint32_t a[4], bf[4][2];
            const __half* ap = &Qs[(wm + g) * HST + k0 + 2 * t4];
            a[0] = *reinterpret_cast<const uint32_t*>(ap);
            a[1] = *reinterpret_cast<const uint32_t*>(ap + 8 * HST);
            a[2] = *reinterpret_cast<const uint32_t*>(ap + 8);
            a[3] = *reinterpret_cast<const uint32_t*>(ap + 8 * HST + 8);
#pragma unroll
            for (int ni = 0; ni < 4; ni++) {
                const __half* bp = &Ks[(wn + ni * 8 + g) * HST + k0 + 2 * t4];
                bf[ni][0] = *reinterpret_cast<const uint32_t*>(bp);
                bf[ni][1] = *reinterpret_cast<const uint32_t*>(bp + 8);
            }
#pragma unroll
            for (int ni = 0; ni < 4; ni++)
                MMA_H(s[ni], a[0], a[1], a[2], a[3], bf[ni][0], bf[ni][1]);
        }
#pragma unroll
        for (int ni = 0; ni < 4; ni++) {
            *reinterpret_cast<float2*>(&Ss[(wm + g) * FST + wn + ni * 8 + 2 * t4]) =
                make_float2(s[ni][0] * 0.125f, s[ni][1] * 0.125f);
            *reinterpret_cast<float2*>(&Ss[(wm + g + 8) * FST + wn + ni * 8 + 2 * t4]) =
                make_float2(s[ni][2] * 0.125f, s[ni][3] * 0.125f);
        }
        __syncthreads();

        // online softmax; write P as fp16
        {
            const int r = warp * 8 + (lane >> 2);
            float* srow = &Ss[r * FST + (lane & 3) * 16];
            __half* prow = &Ps[r * HST + (lane & 3) * 16];
            float mx = -3e38f;
#pragma unroll
            for (int i = 0; i < 16; i++) mx = fmaxf(mx, srow[i]);
            mx = fmaxf(mx, __shfl_xor_sync(0xffffffffu, mx, 1));
            mx = fmaxf(mx, __shfl_xor_sync(0xffffffffu, mx, 2));
            const float mprev = mrow[r];
            const float mnew = fmaxf(mprev, mx);
            float sum = 0.f;
#pragma unroll
            for (int i = 0; i < 16; i++) {
                const __half ph = __float2half_rn(__expf(srow[i] - mnew));
                prow[i] = ph;
                sum += __half2float(ph);
            }
            sum += __shfl_xor_sync(0xffffffffu, sum, 1);
            sum += __shfl_xor_sync(0xffffffffu, sum, 2);
            if ((lane & 3) == 0) {
                const float al = __expf(mprev - mnew);
                arow[r] = al;
                lrow[r] = lrow[r] * al + sum;
                mrow[r] = mnew;
            }
        }
        __syncthreads();

        // O = O*alpha + P @ V   (4 k16 steps over 64 seq)
        const float al0 = arow[wm + g], al1 = arow[wm + g + 8];
#pragma unroll
        for (int ni = 0; ni < 4; ni++) {
            o[ni][0] *= al0; o[ni][1] *= al0;
            o[ni][2] *= al1; o[ni][3] *= al1;
        }
#pragma unroll
        for (int ks = 0; ks < 4; ks++) {
            const int k0 = ks * 16;
            uint32_t a[4], bf[4][2];
            const __half* ap = &Ps[(wm + g) * HST + k0 + 2 * t4];
            a[0] = *reinterpret_cast<const uint32_t*>(ap);
            a[1] = *reinterpret_cast<const uint32_t*>(ap + 8 * HST);
            a[2] = *reinterpret_cast<const uint32_t*>(ap + 8);
            a[3] = *reinterpret_cast<const uint32_t*>(ap + 8 * HST + 8);
#pragma unroll
            for (int ni = 0; ni < 4; ni++) {
                const __half* bp = &Vt[(wn + ni * 8 + g) * HST + k0 + 2 * t4];
                bf[ni][0] = *reinterpret_cast<const uint32_t*>(bp);
                bf[ni][1] = *reinterpret_cast<const uint32_t*>(bp + 8);
            }
#pragma unroll
            for (int ni = 0; ni < 4; ni++)
                MMA_H(o[ni], a[0], a[1], a[2], a[3], bf[ni][0], bf[ni][1]);
        }
        __syncthreads();
    }

    // normalize and write fragment-major fp16 (feeds O-proj A operand)
    const float il0 = 1.0f / lrow[wm + g];
    const float il1 = 1.0f / lrow[wm + g + 8];
    const int KBo = DMn >> 4;
#pragma unroll
    for (int ni = 0; ni < 4; ni++) {
        const int k = h * Dn + wn + ni * 8 + 2 * t4;
        const int m0 = b * Sn + t0 + wm + g;
        *reinterpret_cast<__half2*>(outT + fmIdx(m0, k, KBo)) =
            __floats2half2_rn(o[ni][0] * il0, o[ni][1] * il0);
        *reinterpret_cast<__half2*>(outT + fmIdx(m0 + 8, k, KBo)) =
            __floats2half2_rn(o[ni][2] * il1, o[ni][3] * il1);
    }
}

#define FLASH_SMEM (4 * 64 * HST * 2 + (64 * FST + 3 * 64) * 4)

// ---------------- launch ------------------------------------------------------
extern "C" void kernel_launch(void* const* d_in, const int* in_sizes, int n_in,
                              void* d_out, int out_size)
{
    const float* x        = (const float*)d_in[0];
    const float* ln1_s    = (const float*)d_in[1];
    const float* ln1_o    = (const float*)d_in[2];
    const float* wq       = (const float*)d_in[3];
    const float* bq       = (const float*)d_in[4];
    const float* wk       = (const float*)d_in[5];
    const float* bk       = (const float*)d_in[6];
    const float* wv       = (const float*)d_in[7];
    const float* bv       = (const float*)d_in[8];
    const float* wo       = (const float*)d_in[9];
    const float* bo       = (const float*)d_in[10];
    const float* ln2_s    = (const float*)d_in[11];
    const float* ln2_o    = (const float*)d_in[12];
    const float* fc1_w    = (const float*)d_in[13];
    const float* fc1_b    = (const float*)d_in[14];
    const float* fc2_w    = (const float*)d_in[15];
    const float* fc2_b    = (const float*)d_in[16];
    float* out            = (float*)d_out;

    float *px1, *pbqkv;
    __half *phT, *pqkv, *pf1T, *pwr;
    cudaGetSymbolAddress((void**)&phT,   g_hT);
    cudaGetSymbolAddress((void**)&pqkv,  g_qkv);
    cudaGetSymbolAddress((void**)&px1,   g_x1);
    cudaGetSymbolAddress((void**)&pf1T,  g_f1T);
    cudaGetSymbolAddress((void**)&pwr,   g_wr);
    cudaGetSymbolAddress((void**)&pbqkv, g_bqkv);

    __half* rwqkv = pwr;                                     // fused, NBtot=30
    __half* rwo   = pwr + (size_t)3 * WSZ_DM;
    __half* rfc1  = pwr + (size_t)4 * WSZ_DM;
    __half* rfc2  = pwr + (size_t)4 * WSZ_DM + WSZ_FC;

    static bool attr_done = false;
    if (!attr_done) {
        cudaFuncSetAttribute(flash_h, cudaFuncAttributeMaxDynamicSharedMemorySize, FLASH_SMEM);
        attr_done = true;
    }

    // 0) weight transforms (fp16 fragment-major)
    {
        dim3 gdm(DMn / 128, DMn / 16);       // (10, 80)
        btrans_h<<<gdm, 256>>>(wq, rwqkv, DMn, DMn, 30, 0);
        btrans_h<<<gdm, 256>>>(wk, rwqkv, DMn, DMn, 30, 10);
        btrans_h<<<gdm, 256>>>(wv, rwqkv, DMn, DMn, 30, 20);
        btrans_h<<<gdm, 256>>>(wo, rwo, DMn, DMn, 10, 0);
        dim3 gf1(DFn / 128, DMn / 16);       // (40, 80)
        btrans_h<<<gf1, 256>>>(fc1_w, rfc1, DMn, DFn, 40, 0);
        dim3 gf2(DMn / 128, DFn / 16);       // (10, 320)
        btrans_h<<<gf2, 256>>>(fc2_w, rfc2, DFn, DMn, 10, 0);
        bias_concat<<<QKVLD / 256, 256>>>(bq, bk, bv, pbqkv);
    }

    // 1) LN1 -> fragment-major hT
    ln_ft<<<NTOK, 256>>>(x, ln1_s, ln1_o, phT);

    // 2) fused QKV projection -> qkv (plain fp16)
    {
        dim3 grid(QKVLD / 128, NTOK / 128);  // (30, 32)
        gemm_h<0><<<grid, 256>>>(phT, rwqkv, pbqkv, nullptr, pqkv, NTOK, QKVLD, DMn);
    }

    // 3) flash attention (round-6 proven) -> fragment-major hT (reuse)
    {
        dim3 grid(Sn / 64, NBH);             // (16, 80)
        flash_h<<<grid, 256, FLASH_SMEM>>>(pqkv, phT);
    }

    // 4) O-proj + residual(x) -> x1 (fp32), 64-row tiles
    {
        dim3 grid(DMn / 128, NTOK / 64);     // (10, 64)
        gemm_h64<<<grid, 256>>>(phT, rwo, bo, x, px1, NTOK, DMn, DMn);
    }

    // 5) LN2 -> fragment-major hT (reuse)
    ln_ft<<<NTOK, 256>>>(px1, ln2_s, ln2_o, phT);

    // 6) FC1 + GELU -> fragment-major f1T
    {
        dim3 grid(DFn / 128, NTOK / 128);    // (40, 32)
        gemm_h<2><<<grid, 256>>>(phT, rfc1, fc1_b, nullptr, pf1T, NTOK, DFn, DMn);
    }

    // 7) FC2 + residual(x1) -> out, 64-row tiles
    {
        dim3 grid(DMn / 128, NTOK / 64);     // (10, 64)
        gemm_h64<<<grid, 256>>>(pf1T, rfc2, fc2_b, px1, out, NTOK, DMn, DFn);
    }
}

// round 10
// speedup vs baseline: 7.4909x; 1.2072x over previous
#include <cuda_runtime.h>
#include <cuda_fp16.h>
#include <math.h>
#include <stdint.h>

// Problem constants
#define Bn   4
#define Sn   1024
#define Hn   20
#define Dn   64
#define DMn  1280
#define DFn  5120
#define NTOK 4096           // Bn*Sn
#define NBH  80             // Bn*Hn
#define EPSLN 1e-5f
#define QKVLD 3840          // row stride of fused qkv output

// ---------------- scratch (static device globals; no allocation) -------------
__device__ __half g_hT  [(size_t)NTOK * DMn];          // fragment-major A (reused 3x)
__device__ __half g_qkv [(size_t)NTOK * QKVLD];        // fused q|k|v (plain fp16)
__device__ float  g_x1  [(size_t)NTOK * DMn];          // residual 1
__device__ __half g_f1T [(size_t)NTOK * DFn];          // fragment-major FC1 out
__device__ __half g_wr  [19660800];                    // fragment-major weights (fp16)
__device__ float  g_bqkv[QKVLD];                       // concat bias

#define WSZ_DM (DMn * DMn)          // 1,638,400
#define WSZ_FC (DMn * DFn)          // 6,553,600

// ---------------- fragment-major index helper ---------------------------------
__device__ __forceinline__ size_t fmIdx(int m, int k, int KB) {
    const int mb = m >> 7, mr = m & 127;
    const int kb = k >> 4, kr = k & 15;
    const int mt = mr >> 4, hh = (mr >> 3) & 1, gg = mr & 7;
    const int t4k = (kr >> 1) & 3, khi = kr >> 3, klo = kr & 1;
    return ((size_t)mb * KB + kb) * 2048 +
           (size_t)((mt * 32 + gg * 4 + t4k) * 8 + khi * 4 + hh * 2 + klo);
}

// ---------------- weight transform into fp16 fragment-major blocks ------------
__global__ void __launch_bounds__(256) btrans_h(const float* __restrict__ B,
                                                __half* __restrict__ Bt,
                                                int K, int N, int NBtot, int nbOff)
{
    __shared__ __half s[2048];
    const int nb = blockIdx.x, kb = blockIdx.y;
    const int tid = threadIdx.x;
    const float* bb = B + (size_t)(kb * 16) * N + nb * 128;

#pragma unroll
    for (int e4 = tid; e4 < 512; e4 += 256) {
        const int k = e4 >> 5, colq = (e4 & 31) * 4;
        const float4 f = *reinterpret_cast<const float4*>(bb + (size_t)k * N + colq);
        const int t4 = (k >> 1) & 3, khi = (k >> 3) & 1, klo = k & 1;
        const float vv[4] = {f.x, f.y, f.z, f.w};
#pragma unroll
        for (int j = 0; j < 4; j++) {
            const int col = colq + j;
            const int ni = col >> 3, gg = col & 7;
            s[(ni * 32 + gg * 4 + t4) * 4 + khi * 2 + klo] = __float2half_rn(vv[j]);
        }
    }
    __syncthreads();
    __half* ob = Bt + ((size_t)kb * NBtot + nbOff + nb) * 2048;
    *reinterpret_cast<uint4*>(ob + tid * 8) = *reinterpret_cast<const uint4*>(s + tid * 8);
}

// ---------------- bias concat for fused QKV -----------------------------------
__global__ void __launch_bounds__(256) bias_concat(const float* __restrict__ bq,
                                                   const float* __restrict__ bk,
                                                   const float* __restrict__ bv,
                                                   float* __restrict__ o)
{
    const int i = blockIdx.x * 256 + threadIdx.x;
    if (i < DMn) o[i] = bq[i];
    else if (i < 2 * DMn) o[i] = bk[i - DMn];
    else if (i < 3 * DMn) o[i] = bv[i - 2 * DMn];
}

// ---------------- LayerNorm fused with fragment-major fp16 output -------------
__global__ void __launch_bounds__(256) ln_ft(const float* __restrict__ x,
                                             const float* __restrict__ sc,
                                             const float* __restrict__ off,
                                             __half* __restrict__ yT)
{
    const int row = blockIdx.x;
    const float* xr = x + (size_t)row * DMn;
    const int t = threadIdx.x;
    const int lane = t & 31, wid = t >> 5;

    __shared__ float sh[32];
    __shared__ float s_mean, s_rstd;

    float2 p0 = *reinterpret_cast<const float2*>(xr + 2 * t);
    float2 p1 = *reinterpret_cast<const float2*>(xr + 512 + 2 * t);
    float2 p2 = make_float2(0.f, 0.f);
    if (t < 128) p2 = *reinterpret_cast<const float2*>(xr + 1024 + 2 * t);

    float s = p0.x + p0.y + p1.x + p1.y + p2.x + p2.y;
#pragma unroll
    for (int o = 16; o; o >>= 1) s += __shfl_xor_sync(0xffffffffu, s, o);
    if (lane == 0) sh[wid] = s;
    __syncthreads();
    if (wid == 0) {
        float v = (lane < 8) ? sh[lane] : 0.f;
#pragma unroll
        for (int o = 4; o; o >>= 1) v += __shfl_xor_sync(0xffffffffu, v, o);
        if (lane == 0) s_mean = v * (1.0f / DMn);
    }
    __syncthreads();
    const float mean = s_mean;
    __syncthreads();

    float vs = 0.f;
    {
        float d;
        d = p0.x - mean; vs += d * d;
        d = p0.y - mean; vs += d * d;
        d = p1.x - mean; vs += d * d;
        d = p1.y - mean; vs += d * d;
        if (t < 128) {
            d = p2.x - mean; vs += d * d;
            d = p2.y - mean; vs += d * d;
        }
    }
#pragma unroll
    for (int o = 16; o; o >>= 1) vs += __shfl_xor_sync(0xffffffffu, vs, o);
    if (lane == 0) sh[wid] = vs;
    __syncthreads();
    if (wid == 0) {
        float v = (lane < 8) ? sh[lane] : 0.f;
#pragma unroll
        for (int o = 4; o; o >>= 1) v += __shfl_xor_sync(0xffffffffu, v, o);
        if (lane == 0) s_rstd = rsqrtf(v * (1.0f / DMn) + EPSLN);
    }
    __syncthreads();
    const float rstd = s_rstd;

    const int KB = DMn >> 4;
    {
        const int c = 2 * t;
        const float2 g2 = *reinterpret_cast<const float2*>(sc + c);
        const float2 b2 = *reinterpret_cast<const float2*>(off + c);
        *reinterpret_cast<__half2*>(yT + fmIdx(row, c, KB)) =
            __floats2half2_rn((p0.x - mean) * rstd * g2.x + b2.x,
                              (p0.y - mean) * rstd * g2.y + b2.y);
    }
    {
        const int c = 512 + 2 * t;
        const float2 g2 = *reinterpret_cast<const float2*>(sc + c);
        const float2 b2 = *reinterpret_cast<const float2*>(off + c);
        *reinterpret_cast<__half2*>(yT + fmIdx(row, c, KB)) =
            __floats2half2_rn((p1.x - mean) * rstd * g2.x + b2.x,
                              (p1.y - mean) * rstd * g2.y + b2.y);
    }
    if (t < 128) {
        const int c = 1024 + 2 * t;
        const float2 g2 = *reinterpret_cast<const float2*>(sc + c);
        const float2 b2 = *reinterpret_cast<const float2*>(off + c);
        *reinterpret_cast<__half2*>(yT + fmIdx(row, c, KB)) =
            __floats2half2_rn((p2.x - mean) * rstd * g2.x + b2.x,
                              (p2.y - mean) * rstd * g2.y + b2.y);
    }
}

// ---------------- GEMM helpers -------------------------------------------------
__device__ __forceinline__ float gelu_exact(float v) {
    return 0.5f * v * (1.0f + erff(v * 0.70710678118654752f));
}

__device__ __forceinline__ void cp16(void* smem_dst, const void* gsrc) {
    uint32_t s = (uint32_t)__cvta_generic_to_shared(smem_dst);
    asm volatile("cp.async.cg.shared.global [%0], [%1], 16;" :: "r"(s), "l"(gsrc));
}

// Drain discipline: wait_group 1 only while another group is still in flight;
// on the FINAL iteration only the current group remains -> wait_group 0.
#define PIPE_WAIT(kb, KB) \
    do { if ((kb) + 1 < (KB)) asm volatile("cp.async.wait_group 1;" ::: "memory"); \
         else                 asm volatile("cp.async.wait_group 0;" ::: "memory"); } while (0)

#define MMA_H(c, a0,a1,a2,a3, b0,b1) \
    asm volatile("mma.sync.aligned.m16n8k16.row.col.f32.f16.f16.f32 " \
                 "{%0,%1,%2,%3}, {%4,%5,%6,%7}, {%8,%9}, {%0,%1,%2,%3};" \
                 : "+f"((c)[0]), "+f"((c)[1]), "+f"((c)[2]), "+f"((c)[3]) \
                 : "r"(a0), "r"(a1), "r"(a2), "r"(a3), "r"(b0), "r"(b1))

// ---------------- FP16 GEMM, 128x128 tile (EPI: 0 fp16 out, 2 gelu->frag) -----
template <int EPI>
__global__ void __launch_bounds__(256, 2) gemm_h(const __half* __restrict__ At,
                                                 const __half* __restrict__ Bt,
                                                 const float* __restrict__ bias,
                                                 const float* __restrict__ res,
                                                 void* __restrict__ Cv,
                                                 int M, int N, int K)
{
    __shared__ __align__(16) __half As[3][4096];
    __shared__ __align__(16) __half Bs[3][4096];

    const int tid = threadIdx.x;
    const int nb = blockIdx.x, mb = blockIdx.y;
    const int KB = K >> 5;
    const int KB16 = K >> 4;
    const int NB = N >> 7;
    const int lane = tid & 31, warp = tid >> 5;
    const int wmBase = (warp >> 2) * 4;
    const int wnBase = (warp & 3) * 4;
    const int g = lane >> 2, t4 = lane & 3;

    const __half* aBase = At + (size_t)mb * KB16 * 2048;
    const __half* bBase = Bt + (size_t)nb * 2048;

    float acc[16][4];
#pragma unroll
    for (int i = 0; i < 16; i++)
#pragma unroll
        for (int j = 0; j < 4; j++) acc[i][j] = 0.f;

    auto issue = [&](int s, int kb) {
        const __half* ab  = aBase + (size_t)kb * 4096;
        const __half* bb0 = bBase + (size_t)(kb * 2) * NB * 2048;
        const __half* bb1 = bBase + (size_t)(kb * 2 + 1) * NB * 2048;
        cp16(&As[s][tid * 8],        ab + tid * 8);
        cp16(&As[s][2048 + tid * 8], ab + 2048 + tid * 8);
        cp16(&Bs[s][tid * 8],        bb0 + tid * 8);
        cp16(&Bs[s][2048 + tid * 8], bb1 + tid * 8);
        asm volatile("cp.async.commit_group;" ::: "memory");
    };

    issue(0, 0);
    issue(1, 1);

    for (int kb = 0; kb < KB; kb++) {
        const int s = kb % 3;
        PIPE_WAIT(kb, KB);
        __syncthreads();
        if (kb + 2 < KB) issue((kb + 2) % 3, kb + 2);

#pragma unroll
        for (int kk = 0; kk < 2; kk++) {
            uint32_t a[4][4], b[4][2];
#pragma unroll
            for (int mi = 0; mi < 4; mi++) {
                const uint4 fa = *reinterpret_cast<const uint4*>(
                    &As[s][kk * 2048 + ((wmBase + mi) * 32 + lane) * 8]);
                a[mi][0] = fa.x; a[mi][1] = fa.y; a[mi][2] = fa.z; a[mi][3] = fa.w;
            }
#pragma unroll
            for (int ni = 0; ni < 4; ni++) {
                const uint2 fb = *reinterpret_cast<const uint2*>(
                    &Bs[s][kk * 2048 + ((wnBase + ni) * 32 + lane) * 4]);
                b[ni][0] = fb.x; b[ni][1] = fb.y;
            }
#pragma unroll
            for (int mi = 0; mi < 4; mi++)
#pragma unroll
                for (int ni = 0; ni < 4; ni++)
                    MMA_H(acc[mi * 4 + ni], a[mi][0], a[mi][1], a[mi][2], a[mi][3],
                          b[ni][0], b[ni][1]);
        }
    }

    const int rowBase = mb * 128;
    const int colBase = nb * 128;
    const int wm = (warp >> 2) * 64;
    const int wn = (warp & 3) * 32;
    const int KBo = N >> 4;
#pragma unroll
    for (int mi = 0; mi < 4; mi++) {
#pragma unroll
        for (int ni = 0; ni < 4; ni++) {
            float* c = acc[mi * 4 + ni];
            const int col = colBase + wn + ni * 8 + t4 * 2;
            const float2 bb = *reinterpret_cast<const float2*>(bias + col);
#pragma unroll
            for (int h = 0; h < 2; h++) {
                const int row = rowBase + wm + mi * 16 + g + h * 8;
                float o0 = c[h * 2 + 0] + bb.x;
                float o1 = c[h * 2 + 1] + bb.y;
                if (EPI == 0) {
                    __half* Ch = (__half*)Cv;
                    *reinterpret_cast<__half2*>(Ch + (size_t)row * N + col) =
                        __floats2half2_rn(o0, o1);
                } else {
                    __half* Ch = (__half*)Cv;
                    *reinterpret_cast<__half2*>(Ch + fmIdx(row, col, KBo)) =
                        __floats2half2_rn(gelu_exact(o0), gelu_exact(o1));
                }
            }
        }
    }
}

// ---------------- FP16 GEMM, 64x128 tile, EPI = bias+res -> fp32 --------------
__global__ void __launch_bounds__(256, 3) gemm_h64(const __half* __restrict__ At,
                                                   const __half* __restrict__ Bt,
                                                   const float* __restrict__ bias,
                                                   const float* __restrict__ res,
                                                   float* __restrict__ C,
                                                   int M, int N, int K)
{
    __shared__ __align__(16) __half As[3][2048];   // 2 kk x 1024 (4 m-tiles)
    __shared__ __align__(16) __half Bs[3][4096];

    const int tid = threadIdx.x;
    const int nb = blockIdx.x, mb = blockIdx.y;
    const int KB = K >> 5;
    const int KB16 = K >> 4;
    const int NB = N >> 7;
    const int lane = tid & 31, warp = tid >> 5;
    const int wmBase = (warp >> 2) * 2;   // m-tile base (0 or 2)
    const int wnBase = (warp & 3) * 4;
    const int g = lane >> 2, t4 = lane & 3;
    const int mhalf = mb & 1, mblk = mb >> 1;

    const __half* aBase = At + (size_t)mblk * KB16 * 2048 + mhalf * 1024;
    const __half* bBase = Bt + (size_t)nb * 2048;

    float acc[8][4];
#pragma unroll
    for (int i = 0; i < 8; i++)
#pragma unroll
        for (int j = 0; j < 4; j++) acc[i][j] = 0.f;

    auto issue = [&](int s, int kb) {
        const __half* ab0 = aBase + (size_t)(kb * 2) * 2048;
        const __half* ab1 = aBase + (size_t)(kb * 2 + 1) * 2048;
        if (tid < 128) cp16(&As[s][tid * 8], ab0 + tid * 8);
        else           cp16(&As[s][1024 + (tid - 128) * 8], ab1 + (tid - 128) * 8);
        const __half* bb0 = bBase + (size_t)(kb * 2) * NB * 2048;
        const __half* bb1 = bBase + (size_t)(kb * 2 + 1) * NB * 2048;
        cp16(&Bs[s][tid * 8],        bb0 + tid * 8);
        cp16(&Bs[s][2048 + tid * 8], bb1 + tid * 8);
        asm volatile("cp.async.commit_group;" ::: "memory");
    };

    issue(0, 0);
    issue(1, 1);

    for (int kb = 0; kb < KB; kb++) {
        const int s = kb % 3;
        PIPE_WAIT(kb, KB);
        __syncthreads();
        if (kb + 2 < KB) issue((kb + 2) % 3, kb + 2);

#pragma unroll
        for (int kk = 0; kk < 2; kk++) {
            uint32_t a[2][4], b[4][2];
#pragma unroll
            for (int mi = 0; mi < 2; mi++) {
                const uint4 fa = *reinterpret_cast<const uint4*>(
                    &As[s][kk * 1024 + (wmBase + mi) * 256 + lane * 8]);
                a[mi][0] = fa.x; a[mi][1] = fa.y; a[mi][2] = fa.z; a[mi][3] = fa.w;
            }
#pragma unroll
            for (int ni = 0; ni < 4; ni++) {
                const uint2 fb = *reinterpret_cast<const uint2*>(
                    &Bs[s][kk * 2048 + ((wnBase + ni) * 32 + lane) * 4]);
                b[ni][0] = fb.x; b[ni][1] = fb.y;
            }
#pragma unroll
            for (int mi = 0; mi < 2; mi++)
#pragma unroll
                for (int ni = 0; ni < 4; ni++)
                    MMA_H(acc[mi * 4 + ni], a[mi][0], a[mi][1], a[mi][2], a[mi][3],
                          b[ni][0], b[ni][1]);
        }
    }

    const int rowBase = mb * 64;
    const int colBase = nb * 128;
    const int wm = (warp >> 2) * 32;
    const int wn = (warp & 3) * 32;
#pragma unroll
    for (int mi = 0; mi < 2; mi++) {
#pragma unroll
        for (int ni = 0; ni < 4; ni++) {
            float* c = acc[mi * 4 + ni];
            const int col = colBase + wn + ni * 8 + t4 * 2;
            const float2 bb = *reinterpret_cast<const float2*>(bias + col);
#pragma unroll
            for (int h = 0; h < 2; h++) {
                const int row = rowBase + wm + mi * 16 + g + h * 8;
                const float2 r2 = *reinterpret_cast<const float2*>(res + (size_t)row * N + col);
                *reinterpret_cast<float2*>(C + (size_t)row * N + col) =
                    make_float2(c[h * 2 + 0] + bb.x + r2.x, c[h * 2 + 1] + bb.y + r2.y);
            }
        }
    }
}

// ---------------- flash attention: register softmax, 128-row Q tile -----------
// grid (S/128, B*H), 256 threads; warp w owns rows [w*16, w*16+16), all 64 dims.
#define KVST 72
#define FLASH_SMEM (3 * 2 * 64 * KVST * 2)   // 3-stage K+V ring, fp16
__global__ void __launch_bounds__(256, 2) flash_reg(const __half* __restrict__ qkv,
                                                    __half* __restrict__ outT)
{
    extern __shared__ __half kvs[];
    __half* Ks = kvs;                       // [3][64*KVST]
    __half* Vs = kvs + 3 * 64 * KVST;       // [3][64*KVST]

    const int tid = threadIdx.x;
    const int lane = tid & 31, warp = tid >> 5;
    const int g = lane >> 2, t4 = lane & 3;
    const int bh = blockIdx.y;
    const int b = bh / Hn, h = bh % Hn;
    const int t0 = blockIdx.x * 128;
    const int rw = t0 + warp * 16;
    const int lr = tid >> 2, lc = (tid & 3) * 16;

    // Q fragments straight from gmem (row-major fp16 qkv)
    uint32_t aq[4][4];
    {
        const __half* q0 = qkv + (size_t)(b * Sn + rw + g) * QKVLD + h * Dn + 2 * t4;
        const __half* q1 = q0 + (size_t)8 * QKVLD;
#pragma unroll
        for (int ks = 0; ks < 4; ks++) {
            const int k0 = ks * 16;
            aq[ks][0] = *reinterpret_cast<const uint32_t*>(q0 + k0);
            aq[ks][1] = *reinterpret_cast<const uint32_t*>(q1 + k0);
            aq[ks][2] = *reinterpret_cast<const uint32_t*>(q0 + k0 + 8);
            aq[ks][3] = *reinterpret_cast<const uint32_t*>(q1 + k0 + 8);
        }
    }

    float o[8][4];
#pragma unroll
    for (int ni = 0; ni < 8; ni++)
#pragma unroll
        for (int j = 0; j < 4; j++) o[ni][j] = 0.f;
    float m0 = -3e38f, m1 = -3e38f, l0 = 0.f, l1 = 0.f;

    auto loadKV = [&](int buf, int j0) {
        const __half* kr = qkv + (size_t)(b * Sn + j0 + lr) * QKVLD + DMn + h * Dn + lc;
        const __half* vr = kr + DMn;
        __half* kd = Ks + buf * (64 * KVST) + lr * KVST + lc;
        __half* vd = Vs + buf * (64 * KVST) + lr * KVST + lc;
        cp16(kd, kr); cp16(kd + 8, kr + 8);
        cp16(vd, vr); cp16(vd + 8, vr + 8);
        asm volatile("cp.async.commit_group;" ::: "memory");
    };

    loadKV(0, 0);
    loadKV(1, 64);

    for (int j = 0; j < 16; j++) {
        const int s = j % 3;
        PIPE_WAIT(j, 16);
        __syncthreads();
        if (j + 2 < 16) loadKV((j + 2) % 3, (j + 2) * 64);

        const __half* Kb = Ks + s * (64 * KVST);
        const __half* Vb = Vs + s * (64 * KVST);

        // S = Q K^T (scaled)
        float sc[8][4];
#pragma unroll
        for (int ni = 0; ni < 8; ni++)
#pragma unroll
            for (int jj = 0; jj < 4; jj++) sc[ni][jj] = 0.f;
#pragma unroll
        for (int ks = 0; ks < 4; ks++) {
            const int k0 = ks * 16;
#pragma unroll
            for (int ni = 0; ni < 8; ni++) {
                const __half* bp = Kb + (ni * 8 + g) * KVST + k0 + 2 * t4;
                const uint32_t b0 = *reinterpret_cast<const uint32_t*>(bp);
                const uint32_t b1 = *reinterpret_cast<const uint32_t*>(bp + 8);
                MMA_H(sc[ni], aq[ks][0], aq[ks][1], aq[ks][2], aq[ks][3], b0, b1);
            }
        }

        // row stats in registers (rows g and g+8)
        float mx0 = -3e38f, mx1 = -3e38f;
#pragma unroll
        for (int ni = 0; ni < 8; ni++) {
#pragma unroll
            for (int jj = 0; jj < 4; jj++) sc[ni][jj] *= 0.125f;
            mx0 = fmaxf(mx0, fmaxf(sc[ni][0], sc[ni][1]));
            mx1 = fmaxf(mx1, fmaxf(sc[ni][2], sc[ni][3]));
        }
        mx0 = fmaxf(mx0, __shfl_xor_sync(0xffffffffu, mx0, 1));
        mx0 = fmaxf(mx0, __shfl_xor_sync(0xffffffffu, mx0, 2));
        mx1 = fmaxf(mx1, __shfl_xor_sync(0xffffffffu, mx1, 1));
        mx1 = fmaxf(mx1, __shfl_xor_sync(0xffffffffu, mx1, 2));

        const float mn0 = fmaxf(m0, mx0), mn1 = fmaxf(m1, mx1);
        const float al0 = __expf(m0 - mn0), al1 = __expf(m1 - mn1);
        m0 = mn0; m1 = mn1;

        uint32_t p[8][2];
        float sum0 = 0.f, sum1 = 0.f;
#pragma unroll
        for (int ni = 0; ni < 8; ni++) {
            const __half2 h20 = __floats2half2_rn(__expf(sc[ni][0] - m0),
                                                  __expf(sc[ni][1] - m0));
            const __half2 h21 = __floats2half2_rn(__expf(sc[ni][2] - m1),
                                                  __expf(sc[ni][3] - m1));
            p[ni][0] = *reinterpret_cast<const uint32_t*>(&h20);
            p[ni][1] = *reinterpret_cast<const uint32_t*>(&h21);
            sum0 += __low2float(h20) + __high2float(h20);
            sum1 += __low2float(h21) + __high2float(h21);
        }
        sum0 += __shfl_xor_sync(0xffffffffu, sum0, 1);
        sum0 += __shfl_xor_sync(0xffffffffu, sum0, 2);
        sum1 += __shfl_xor_sync(0xffffffffu, sum1, 1);
        sum1 += __shfl_xor_sync(0xffffffffu, sum1, 2);
        l0 = l0 * al0 + sum0;
        l1 = l1 * al1 + sum1;

#pragma unroll
        for (int ni = 0; ni < 8; ni++) {
            o[ni][0] *= al0; o[ni][1] *= al0;
            o[ni][2] *= al1; o[ni][3] *= al1;
        }

        // O += P V  (A from p regs, B = 2-byte V loads)
#pragma unroll
        for (int ks = 0; ks < 4; ks++) {
            const int k0 = ks * 16;
#pragma unroll
            for (int ni = 0; ni < 8; ni++) {
                const __half* vp = Vb + (k0 + 2 * t4) * KVST + ni * 8 + g;
                const uint32_t v00 = *reinterpret_cast<const uint16_t*>(vp);
                const uint32_t v01 = *reinterpret_cast<const uint16_t*>(vp + KVST);
                const uint32_t v10 = *reinterpret_cast<const uint16_t*>(vp + 8 * KVST);
                const uint32_t v11 = *reinterpret_cast<const uint16_t*>(vp + 9 * KVST);
                const uint32_t b0 = v00 | (v01 << 16);
                const uint32_t b1 = v10 | (v11 << 16);
                MMA_H(o[ni], p[2 * ks][0], p[2 * ks][1], p[2 * ks + 1][0], p[2 * ks + 1][1],
                      b0, b1);
            }
        }
    }

    // normalize, write fragment-major fp16
    const float il0 = 1.0f / l0, il1 = 1.0f / l1;
    const int KBo = DMn >> 4;
    const int mr0 = b * Sn + rw + g;
#pragma unroll
    for (int ni = 0; ni < 8; ni++) {
        const int k = h * Dn + ni * 8 + 2 * t4;
        *reinterpret_cast<__half2*>(outT + fmIdx(mr0, k, KBo)) =
            __floats2half2_rn(o[ni][0] * il0, o[ni][1] * il0);
        *reinterpret_cast<__half2*>(outT + fmIdx(mr0 + 8, k, KBo)) =
            __floats2half2_rn(o[ni][2] * il1, o[ni][3] * il1);
    }
}

// ---------------- launch ------------------------------------------------------
extern "C" void kernel_launch(void* const* d_in, const int* in_sizes, int n_in,
                              void* d_out, int out_size)
{
    const float* x        = (const float*)d_in[0];
    const float* ln1_s    = (const float*)d_in[1];
    const float* ln1_o    = (const float*)d_in[2];
    const float* wq       = (const float*)d_in[3];
    const float* bq       = (const float*)d_in[4];
    const float* wk       = (const float*)d_in[5];
    const float* bk       = (const float*)d_in[6];
    const float* wv       = (const float*)d_in[7];
    const float* bv       = (const float*)d_in[8];
    const float* wo       = (const float*)d_in[9];
    const float* bo       = (const float*)d_in[10];
    const float* ln2_s    = (const float*)d_in[11];
    const float* ln2_o    = (const float*)d_in[12];
    const float* fc1_w    = (const float*)d_in[13];
    const float* fc1_b    = (const float*)d_in[14];
    const float* fc2_w    = (const float*)d_in[15];
    const float* fc2_b    = (const float*)d_in[16];
    float* out            = (float*)d_out;

    float *px1, *pbqkv;
    __half *phT, *pqkv, *pf1T, *pwr;
    cudaGetSymbolAddress((void**)&phT,   g_hT);
    cudaGetSymbolAddress((void**)&pqkv,  g_qkv);
    cudaGetSymbolAddress((void**)&px1,   g_x1);
    cudaGetSymbolAddress((void**)&pf1T,  g_f1T);
    cudaGetSymbolAddress((void**)&pwr,   g_wr);
    cudaGetSymbolAddress((void**)&pbqkv, g_bqkv);

    __half* rwqkv = pwr;                                     // fused, NBtot=30
    __half* rwo   = pwr + (size_t)3 * WSZ_DM;
    __half* rfc1  = pwr + (size_t)4 * WSZ_DM;
    __half* rfc2  = pwr + (size_t)4 * WSZ_DM + WSZ_FC;

    static bool attr_done = false;
    if (!attr_done) {
        cudaFuncSetAttribute(flash_reg, cudaFuncAttributeMaxDynamicSharedMemorySize, FLASH_SMEM);
        attr_done = true;
    }

    // 0) weight transforms (fp16 fragment-major)
    {
        dim3 gdm(DMn / 128, DMn / 16);       // (10, 80)
        btrans_h<<<gdm, 256>>>(wq, rwqkv, DMn, DMn, 30, 0);
        btrans_h<<<gdm, 256>>>(wk, rwqkv, DMn, DMn, 30, 10);
        btrans_h<<<gdm, 256>>>(wv, rwqkv, DMn, DMn, 30, 20);
        btrans_h<<<gdm, 256>>>(wo, rwo, DMn, DMn, 10, 0);
        dim3 gf1(DFn / 128, DMn / 16);       // (40, 80)
        btrans_h<<<gf1, 256>>>(fc1_w, rfc1, DMn, DFn, 40, 0);
        dim3 gf2(DMn / 128, DFn / 16);       // (10, 320)
        btrans_h<<<gf2, 256>>>(fc2_w, rfc2, DFn, DMn, 10, 0);
        bias_concat<<<QKVLD / 256, 256>>>(bq, bk, bv, pbqkv);
    }

    // 1) LN1 -> fragment-major hT
    ln_ft<<<NTOK, 256>>>(x, ln1_s, ln1_o, phT);

    // 2) fused QKV projection -> qkv (plain fp16)
    {
        dim3 grid(QKVLD / 128, NTOK / 128);  // (30, 32)
        gemm_h<0><<<grid, 256>>>(phT, rwqkv, pbqkv, nullptr, pqkv, NTOK, QKVLD, DMn);
    }

    // 3) flash attention (register softmax) -> fragment-major hT (reuse)
    {
        dim3 grid(Sn / 128, NBH);            // (8, 80)
        flash_reg<<<grid, 256, FLASH_SMEM>>>(pqkv, phT);
    }

    // 4) O-proj + residual(x) -> x1 (fp32), 64-row tiles
    {
        dim3 grid(DMn / 128, NTOK / 64);     // (10, 64)
        gemm_h64<<<grid, 256>>>(phT, rwo, bo, x, px1, NTOK, DMn, DMn);
    }

    // 5) LN2 -> fragment-major hT (reuse)
    ln_ft<<<NTOK, 256>>>(px1, ln2_s, ln2_o, phT);

    // 6) FC1 + GELU -> fragment-major f1T
    {
        dim3 grid(DFn / 128, NTOK / 128);    // (40, 32)
        gemm_h<2><<<grid, 256>>>(phT, rfc1, fc1_b, nullptr, pf1T, NTOK, DFn, DMn);
    }

    // 7) FC2 + residual(x1) -> out, 64-row tiles
    {
        dim3 grid(DMn / 128, NTOK / 64);     // (10, 64)
        gemm_h64<<<grid, 256>>>(pf1T, rfc2, fc2_b, px1, out, NTOK, DMn, DFn);
    }
}